// round 7
// baseline (speedup 1.0000x reference)
#include <cuda_runtime.h>
#include <cuda_bf16.h>
#include <cstdint>

#define NN 30000
#define EE 250000
#define IN_F 512
#define HID_F 256
#define OUT_F 128

typedef unsigned long long u64;
typedef __nv_bfloat16 bf16;

// ---------------- scratch (static device globals; no allocs) ----------------
__device__ float g_y[(size_t)12 * NN * HID_F];
__device__ float g_zd[(size_t)NN * 3 * OUT_F];
__device__ float g_zp[(size_t)NN * 3 * OUT_F];
__device__ float g_rout[12 * NN];
__device__ float g_rin[12 * NN];
__device__ float g_wsum[8];
__device__ float g_beta[8];
__device__ int   g_cnts[12 * NN];
__device__ int   g_cnt[12 * NN];
__device__ int   g_base[12 * NN];
__device__ int   g_cur[12 * NN];
__device__ int   g_csrs[(size_t)12 * EE];
__device__ float g_csrw[(size_t)12 * EE];
__device__ __align__(16) bf16 g_x1[(size_t)2 * NN * IN_F];
__device__ __align__(16) bf16 g_x2[(size_t)2 * NN * IN_F];
__device__ __align__(16) bf16 g_h1[(size_t)6 * NN * HID_F];
__device__ __align__(16) bf16 g_h2[(size_t)6 * NN * HID_F];
__device__ __align__(16) bf16 g_za1[(size_t)2 * NN * 3 * OUT_F];
__device__ __align__(16) bf16 g_za2[(size_t)2 * NN * 3 * OUT_F];
__device__ __align__(16) bf16 g_wt1a[(size_t)12 * HID_F * IN_F];
__device__ __align__(16) bf16 g_wt1b[(size_t)12 * HID_F * IN_F];
__device__ __align__(16) bf16 g_wt2a[(size_t)12 * OUT_F * HID_F];
__device__ __align__(16) bf16 g_wt2b[(size_t)12 * OUT_F * HID_F];
__device__ __align__(16) bf16 g_wpa[(size_t)OUT_F * OUT_F];
__device__ __align__(16) bf16 g_wpb[(size_t)OUT_F * OUT_F];

__device__ __forceinline__ void fma4(float4& a, float w, const float4 v) {
    a.x += w * v.x; a.y += w * v.y; a.z += w * v.z; a.w += w * v.w;
}
__device__ __forceinline__ int u2cr(int u) {
    int ci = u >> 2;
    int c = (ci == 0) ? 0 : (ci == 1 ? 2 : 3);
    return c * 4 + (u & 3);
}
__device__ __forceinline__ uint32_t smem_u32(const void* p) {
    uint32_t a;
    asm("{ .reg .u64 t; cvta.to.shared.u64 t, %1; cvt.u32.u64 %0, t; }" : "=r"(a) : "l"(p));
    return a;
}
__device__ __forceinline__ void cpa(uint32_t saddr, const void* g, int psize) {
    asm volatile("cp.async.cg.shared.global [%0], [%1], 16, %2;"
                 :: "r"(saddr), "l"(g), "r"(psize));
}

// ---------------- utility kernels ----------------
__global__ void k_zero(float* __restrict__ p, int n) {
    int i = blockIdx.x * blockDim.x + threadIdx.x;
    if (i < n) p[i] = 0.f;
}
__global__ void k_zeroi2(int* __restrict__ a, int* __restrict__ b, int n) {
    int i = blockIdx.x * blockDim.x + threadIdx.x;
    if (i < n) { a[i] = 0; b[i] = 0; }
}

__global__ void k_hist2(const int* __restrict__ src, const int* __restrict__ dst,
                        int* __restrict__ cnts, int* __restrict__ cntd) {
    int i = blockIdx.x * blockDim.x + threadIdx.x;
    if (i >= 12 * EE) return;
    int u = i / EE, e = i - u * EE;
    int cr = u2cr(u);
    atomicAdd(&cnts[u * NN + src[(size_t)cr * EE + e]], 1);
    atomicAdd(&cntd[u * NN + dst[(size_t)cr * EE + e]], 1);
}

__global__ void k_prep(const int* __restrict__ cnts, const int* __restrict__ cntd,
                       float* __restrict__ rout, float* __restrict__ rin) {
    int i = blockIdx.x * blockDim.x + threadIdx.x;
    if (i >= 12 * NN) return;
    rout[i] = rsqrtf((float)max(cnts[i], 1));
    rin[i]  = rsqrtf((float)max(cntd[i], 1));
}

// deterministic exclusive scan per u (12 blocks, 1024 threads)
__global__ void k_scan(const int* __restrict__ cnt, int* __restrict__ base,
                       int* __restrict__ cur) {
    __shared__ int ws[32];
    __shared__ int carry;
    int u = blockIdx.x;
    const int* c = cnt + u * NN;
    int* b = base + u * NN;
    int* q = cur + u * NN;
    int lane = threadIdx.x & 31, w = threadIdx.x >> 5;
    if (threadIdx.x == 0) carry = 0;
    __syncthreads();
    for (int off = 0; off < NN; off += 1024) {
        int i = off + threadIdx.x;
        int v = (i < NN) ? c[i] : 0;
        int s = v;
#pragma unroll
        for (int o = 1; o < 32; o <<= 1) {
            int t = __shfl_up_sync(0xffffffffu, s, o);
            if (lane >= o) s += t;
        }
        if (lane == 31) ws[w] = s;
        __syncthreads();
        if (w == 0) {
            int t2 = ws[lane];
#pragma unroll
            for (int o = 1; o < 32; o <<= 1) {
                int t = __shfl_up_sync(0xffffffffu, t2, o);
                if (lane >= o) t2 += t;
            }
            ws[lane] = t2;
        }
        __syncthreads();
        int excl = s - v + (w > 0 ? ws[w - 1] : 0) + carry;
        if (i < NN) { b[i] = excl; q[i] = excl; }
        __syncthreads();
        if (threadIdx.x == 1023) carry = excl + v;
        __syncthreads();
    }
}

__global__ void k_fill(const int* __restrict__ src, const int* __restrict__ dst,
                       const float* __restrict__ rout, int* __restrict__ cur,
                       int* __restrict__ csrs, float* __restrict__ csrw) {
    int i = blockIdx.x * blockDim.x + threadIdx.x;
    if (i >= 12 * EE) return;
    int u = i / EE, e = i - u * EE;
    int cr = u2cr(u);
    int s = src[(size_t)cr * EE + e];
    int d = dst[(size_t)cr * EE + e];
    int pos = atomicAdd(&cur[u * NN + d], 1);
    csrs[(size_t)u * EE + pos] = s;
    csrw[(size_t)u * EE + pos] = rout[u * NN + s];
}

// split fp32 -> bf16 hi/lo
__global__ void k_split(const float* __restrict__ x, bf16* __restrict__ hi,
                        bf16* __restrict__ lo, int n4) {
    int i = blockIdx.x * blockDim.x + threadIdx.x;
    if (i >= n4) return;
    float4 v = ((const float4*)x)[i];
    bf16 h0 = __float2bfloat16(v.x), h1 = __float2bfloat16(v.y);
    bf16 h2 = __float2bfloat16(v.z), h3 = __float2bfloat16(v.w);
    ((__nv_bfloat162*)hi)[2 * i]     = __halves2bfloat162(h0, h1);
    ((__nv_bfloat162*)hi)[2 * i + 1] = __halves2bfloat162(h2, h3);
    bf16 l0 = __float2bfloat16(v.x - __bfloat162float(h0));
    bf16 l1 = __float2bfloat16(v.y - __bfloat162float(h1));
    bf16 l2 = __float2bfloat16(v.z - __bfloat162float(h2));
    bf16 l3 = __float2bfloat16(v.w - __bfloat162float(h3));
    ((__nv_bfloat162*)lo)[2 * i]     = __halves2bfloat162(l0, l1);
    ((__nv_bfloat162*)lo)[2 * i + 1] = __halves2bfloat162(l2, l3);
}

// transpose+split weights
__global__ void k_wts(const float* __restrict__ W, bf16* __restrict__ t1,
                      bf16* __restrict__ t2, int K, int N) {
    __shared__ float tile[32][33];
    int z = blockIdx.z;
    int cz = z >> 2;
    int c = (cz == 0) ? 0 : (cz == 1 ? 2 : 3);
    const float* Wm = W + (size_t)(c * 4 + (z & 3)) * K * N;
    bf16* o1 = t1 + (size_t)z * K * N;
    bf16* o2 = t2 + (size_t)z * K * N;
    int k0 = blockIdx.y * 32, n0 = blockIdx.x * 32;
    for (int r = threadIdx.y; r < 32; r += 8)
        tile[r][threadIdx.x] = Wm[(size_t)(k0 + r) * N + n0 + threadIdx.x];
    __syncthreads();
    for (int r = threadIdx.y; r < 32; r += 8) {
        float v = tile[threadIdx.x][r];
        bf16 h = __float2bfloat16(v);
        size_t o = (size_t)(n0 + r) * K + k0 + threadIdx.x;
        o1[o] = h;
        o2[o] = __float2bfloat16(v - __bfloat162float(h));
    }
}

__global__ void k_wts1(const float* __restrict__ W, bf16* __restrict__ t1,
                       bf16* __restrict__ t2, int K, int N) {
    __shared__ float tile[32][33];
    int k0 = blockIdx.y * 32, n0 = blockIdx.x * 32;
    for (int r = threadIdx.y; r < 32; r += 8)
        tile[r][threadIdx.x] = W[(size_t)(k0 + r) * N + n0 + threadIdx.x];
    __syncthreads();
    for (int r = threadIdx.y; r < 32; r += 8) {
        float v = tile[threadIdx.x][r];
        bf16 h = __float2bfloat16(v);
        size_t o = (size_t)(n0 + r) * K + k0 + threadIdx.x;
        t1[o] = h;
        t2[o] = __float2bfloat16(v - __bfloat162float(h));
    }
}

// ---------------- fused 3-chain bf16 GEMM, 128x128 tile, cp.async ----------------
__device__ __forceinline__ void mma16816(float* c, const uint32_t* a, const uint32_t* b) {
    asm volatile("mma.sync.aligned.m16n8k16.row.col.f32.bf16.bf16.f32 "
                 "{%0,%1,%2,%3}, {%4,%5,%6,%7}, {%8,%9}, {%0,%1,%2,%3};"
                 : "+f"(c[0]), "+f"(c[1]), "+f"(c[2]), "+f"(c[3])
                 : "r"(a[0]), "r"(a[1]), "r"(a[2]), "r"(a[3]), "r"(b[0]), "r"(b[1]));
}

template <int KK, int NOUT, int CH>
__global__ void __launch_bounds__(256, 2) k_mma(
    const bf16* __restrict__ A1b, const bf16* __restrict__ A2b,
    const bf16* __restrict__ Bt1, const bf16* __restrict__ Bt2,
    float* __restrict__ Y, int M) {
    // dynamic smem: 2 buffers x (A1|A2|B1|B2), each tile 2048 words (128x32 bf16)
    extern __shared__ uint32_t S[];

    const int tid = threadIdx.x;
    const int lane = tid & 31;
    const int wid = tid >> 5;
    const int warpM = wid & 3;
    const int warpN = wid >> 2;
    constexpr int NT = NOUT / 128;
    const int u = blockIdx.x / NT;
    const int bn = (blockIdx.x % NT) * 128;
    const int bm = blockIdx.y * 128;

    const int aoff = (CH ? (u >> 2) * 2 : 0) + ((u & 3) >> 1);
    const bf16* A1 = A1b + (size_t)aoff * M * KK;
    const bf16* A2 = A2b + (size_t)aoff * M * KK;
    const bf16* B1 = Bt1 + (size_t)u * KK * NOUT;
    const bf16* B2 = Bt2 + (size_t)u * KK * NOUT;
    float* Yp = Y + (size_t)u * M * NOUT;

    const uint32_t sbase = smem_u32(S);

    // per-thread staging indices (slot i: row m0+64i, k-words seg*8..+7)
    const int m0 = tid >> 2, seg = tid & 3;
    const int kb0 = seg >> 1, h0 = seg & 1;
    const int r0 = ((m0 >> 3) & 1) + 2 * h0;          // same for m0 and m0+64
    const int Lb = (((m0 & 7) * 4) + seg * 8) & 31;
    const int Wa0 = ((kb0 * 8 + (m0 >> 4)) * 4 + r0) * 32 + Lb;
    const int Wb0 = ((kb0 * 16 + (m0 >> 3)) * 2 + h0) * 32 + Lb;

    float c[2][8][4];
#pragma unroll
    for (int i = 0; i < 2; ++i)
#pragma unroll
        for (int j = 0; j < 8; ++j)
#pragma unroll
            for (int l = 0; l < 4; ++l) c[i][j][l] = 0.f;

    auto issue_chunk = [&](int g) {
        const int koff = g * 32;
        const uint32_t sb = sbase + (g & 1) * 32768;
#pragma unroll
        for (int i = 0; i < 2; ++i) {
            int m = m0 + 64 * i;
            int gm = bm + m;
            int pa = (gm < M) ? 16 : 0;
            int gmc = (gm < M) ? gm : (M - 1);
            uint32_t wa = sb + (uint32_t)(Wa0 + 512 * i) * 4;
            uint32_t wb = sb + (uint32_t)(Wb0 + 512 * i) * 4;
            cpa(wa,          A1 + (size_t)gmc * KK + koff + seg * 8, pa);
            cpa(wa + 8192,   A2 + (size_t)gmc * KK + koff + seg * 8, pa);
            cpa(wb + 16384,  B1 + (size_t)(bn + m) * KK + koff + seg * 8, 16);
            cpa(wb + 24576,  B2 + (size_t)(bn + m) * KK + koff + seg * 8, 16);
        }
        asm volatile("cp.async.commit_group;" ::: "memory");
    };

    constexpr int NC = KK / 32;
    issue_chunk(0);

#pragma unroll 1
    for (int g = 0; g < NC; ++g) {
        asm volatile("cp.async.wait_group 0;" ::: "memory");
        __syncthreads();
        if (g + 1 < NC) issue_chunk(g + 1);

        const uint32_t* A1s = S + (g & 1) * 8192;
        const uint32_t* A2s = A1s + 2048;
        const uint32_t* B1s = A1s + 4096;
        const uint32_t* B2s = A1s + 6144;
#pragma unroll
        for (int kb = 0; kb < 2; ++kb) {
            uint32_t a1[2][4], a2[2][4];
#pragma unroll
            for (int mbl = 0; mbl < 2; ++mbl) {
                int mb = warpM * 2 + mbl;
#pragma unroll
                for (int r = 0; r < 4; ++r) {
                    int Lr = (lane + (kb * 2 + (r >> 1)) * 8) & 31;
                    int idx = ((kb * 8 + mb) * 4 + r) * 32 + Lr;
                    a1[mbl][r] = A1s[idx];
                    a2[mbl][r] = A2s[idx];
                }
            }
#pragma unroll
            for (int nbl = 0; nbl < 8; ++nbl) {
                int nb = warpN * 8 + nbl;
                uint32_t b1[2], b2[2];
#pragma unroll
                for (int h = 0; h < 2; ++h) {
                    int Lr = (lane + (kb * 2 + h) * 8) & 31;
                    int idx = ((kb * 16 + nb) * 2 + h) * 32 + Lr;
                    b1[h] = B1s[idx];
                    b2[h] = B2s[idx];
                }
#pragma unroll
                for (int mbl = 0; mbl < 2; ++mbl) {
                    mma16816(c[mbl][nbl], a1[mbl], b1);
                    mma16816(c[mbl][nbl], a1[mbl], b2);
                    mma16816(c[mbl][nbl], a2[mbl], b1);
                }
            }
        }
        __syncthreads();
    }

#pragma unroll
    for (int mbl = 0; mbl < 2; ++mbl) {
        int mrow = bm + warpM * 32 + mbl * 16 + (lane >> 2);
#pragma unroll
        for (int nbl = 0; nbl < 8; ++nbl) {
            int ncol = bn + warpN * 64 + nbl * 8 + (lane & 3) * 2;
            float* base = Yp + (size_t)mrow * NOUT + ncol;
            if (mrow < M)
                *(float2*)base = make_float2(c[mbl][nbl][0], c[mbl][nbl][1]);
            if (mrow + 8 < M)
                *(float2*)(base + (size_t)8 * NOUT) = make_float2(c[mbl][nbl][2], c[mbl][nbl][3]);
        }
    }
}

// --------- fused gather layer1 ---------
__global__ void __launch_bounds__(256) k_gag1(
    const float* __restrict__ y,
    const int* __restrict__ csrs, const float* __restrict__ csrw,
    const int* __restrict__ base, const int* __restrict__ cnt,
    const float* __restrict__ rin, const float* __restrict__ b1,
    bf16* __restrict__ h1, bf16* __restrict__ h2) {
    int gw = (blockIdx.x * blockDim.x + threadIdx.x) >> 5;
    if (gw >= NN) return;
    int lane = threadIdx.x & 31;
    int d = gw;
    int by = blockIdx.y;
    int ci = by >> 1, t = by & 1;
    int uLo = ci * 4 + t, uHi = uLo + 2;
    int c = (ci == 0) ? 0 : (ci == 1 ? 2 : 3);
    const float* yLo = y + (size_t)uLo * NN * HID_F;
    const float* yHi = y + (size_t)uHi * NN * HID_F;
    const float* bLo = b1 + (c * 4 + t) * HID_F;
    const float* bHi = b1 + (c * 4 + t + 2) * HID_F;

    float4 a0 = make_float4(0, 0, 0, 0), a1 = a0, c0 = a0, c1 = a0;
    {
        int b = base[uLo * NN + d], n = cnt[uLo * NN + d];
        const int* cs = csrs + (size_t)uLo * EE;
        const float* cw = csrw + (size_t)uLo * EE;
        for (int i = 0; i < n; ++i) {
            int s = cs[b + i];
            float w = cw[b + i];
            const float4* r = (const float4*)(yLo + (size_t)s * HID_F);
            fma4(a0, w, r[lane]);
            fma4(a1, w, r[32 + lane]);
        }
    }
    {
        int b = base[uHi * NN + d], n = cnt[uHi * NN + d];
        const int* cs = csrs + (size_t)uHi * EE;
        const float* cw = csrw + (size_t)uHi * EE;
        for (int i = 0; i < n; ++i) {
            int s = cs[b + i];
            float w = cw[b + i];
            const float4* r = (const float4*)(yHi + (size_t)s * HID_F);
            fma4(c0, w, r[lane]);
            fma4(c1, w, r[32 + lane]);
        }
    }
    float rl = rin[uLo * NN + d], rh = rin[uHi * NN + d];
    bf16* o1 = h1 + (size_t)by * NN * HID_F;
    bf16* o2 = h2 + (size_t)by * NN * HID_F;
#pragma unroll
    for (int ch = 0; ch < 2; ++ch) {
        float4 A = ch ? a1 : a0, C = ch ? c1 : c0;
        float4 x = ((const float4*)bLo)[ch * 32 + lane];
        float4 yb = ((const float4*)bHi)[ch * 32 + lane];
        float r0 = fmaxf(x.x + yb.x + rl * A.x + rh * C.x, 0.f);
        float r1 = fmaxf(x.y + yb.y + rl * A.y + rh * C.y, 0.f);
        float r2 = fmaxf(x.z + yb.z + rl * A.z + rh * C.z, 0.f);
        float r3 = fmaxf(x.w + yb.w + rl * A.w + rh * C.w, 0.f);
        bf16 h0 = __float2bfloat16(r0), hh1 = __float2bfloat16(r1);
        bf16 h2v = __float2bfloat16(r2), h3 = __float2bfloat16(r3);
        __nv_bfloat162 p0 = __halves2bfloat162(h0, hh1);
        __nv_bfloat162 p1 = __halves2bfloat162(h2v, h3);
        uint2 st;
        st.x = *(unsigned*)&p0; st.y = *(unsigned*)&p1;
        size_t off = (size_t)d * HID_F + ch * 128 + lane * 4;
        *(uint2*)(o1 + off) = st;
        bf16 l0 = __float2bfloat16(r0 - __bfloat162float(h0));
        bf16 l1 = __float2bfloat16(r1 - __bfloat162float(hh1));
        bf16 l2 = __float2bfloat16(r2 - __bfloat162float(h2v));
        bf16 l3 = __float2bfloat16(r3 - __bfloat162float(h3));
        p0 = __halves2bfloat162(l0, l1);
        p1 = __halves2bfloat162(l2, l3);
        st.x = *(unsigned*)&p0; st.y = *(unsigned*)&p1;
        *(uint2*)(o2 + off) = st;
    }
}

// --------- fused gather layer2 + z split ---------
__global__ void __launch_bounds__(256) k_gag2(
    const float* __restrict__ y,
    const int* __restrict__ csrs, const float* __restrict__ csrw,
    const int* __restrict__ base, const int* __restrict__ cnt,
    const float* __restrict__ rin, const float* __restrict__ b2,
    float* __restrict__ zd, float* __restrict__ zp,
    bf16* __restrict__ za1, bf16* __restrict__ za2) {
    int gw = (blockIdx.x * blockDim.x + threadIdx.x) >> 5;
    if (gw >= NN) return;
    int lane = threadIdx.x & 31;
    int d = gw;
    int by = blockIdx.y;
    int ci = by >> 1, t = by & 1;
    int uLo = ci * 4 + t, uHi = uLo + 2;
    int c = (ci == 0) ? 0 : (ci == 1 ? 2 : 3);
    const float* yLo = y + (size_t)uLo * NN * OUT_F;
    const float* yHi = y + (size_t)uHi * NN * OUT_F;
    const float* bLo = b2 + (c * 4 + t) * OUT_F;
    const float* bHi = b2 + (c * 4 + t + 2) * OUT_F;

    float4 a0 = make_float4(0, 0, 0, 0), c0 = a0;
    {
        int b = base[uLo * NN + d], n = cnt[uLo * NN + d];
        const int* cs = csrs + (size_t)uLo * EE;
        const float* cw = csrw + (size_t)uLo * EE;
        for (int i = 0; i < n; ++i)
            fma4(a0, cw[b + i], ((const float4*)(yLo + (size_t)cs[b + i] * OUT_F))[lane]);
    }
    {
        int b = base[uHi * NN + d], n = cnt[uHi * NN + d];
        const int* cs = csrs + (size_t)uHi * EE;
        const float* cw = csrw + (size_t)uHi * EE;
        for (int i = 0; i < n; ++i)
            fma4(c0, cw[b + i], ((const float4*)(yHi + (size_t)cs[b + i] * OUT_F))[lane]);
    }
    float rl = rin[uLo * NN + d], rh = rin[uHi * NN + d];
    float4 x = ((const float4*)bLo)[lane], yb = ((const float4*)bHi)[lane];
    float4 res;
    res.x = fmaxf(x.x + yb.x + rl * a0.x + rh * c0.x, 0.f);
    res.y = fmaxf(x.y + yb.y + rl * a0.y + rh * c0.y, 0.f);
    res.z = fmaxf(x.z + yb.z + rl * a0.z + rh * c0.z, 0.f);
    res.w = fmaxf(x.w + yb.w + rl * a0.w + rh * c0.w, 0.f);
    float* zt = t ? zp : zd;
    *(float4*)(zt + (size_t)d * (3 * OUT_F) + ci * OUT_F + lane * 4) = res;

    size_t row = (size_t)t * NN * 3 + (size_t)d * 3 + ci;
    bf16 h0 = __float2bfloat16(res.x), h1 = __float2bfloat16(res.y);
    bf16 h2 = __float2bfloat16(res.z), h3 = __float2bfloat16(res.w);
    __nv_bfloat162 p0 = __halves2bfloat162(h0, h1);
    __nv_bfloat162 p1 = __halves2bfloat162(h2, h3);
    uint2 st;
    st.x = *(unsigned*)&p0; st.y = *(unsigned*)&p1;
    *(uint2*)(za1 + row * OUT_F + lane * 4) = st;
    bf16 l0 = __float2bfloat16(res.x - __bfloat162float(h0));
    bf16 l1 = __float2bfloat16(res.y - __bfloat162float(h1));
    bf16 l2 = __float2bfloat16(res.z - __bfloat162float(h2));
    bf16 l3 = __float2bfloat16(res.w - __bfloat162float(h3));
    p0 = __halves2bfloat162(l0, l1);
    p1 = __halves2bfloat162(l2, l3);
    st.x = *(unsigned*)&p0; st.y = *(unsigned*)&p1;
    *(uint2*)(za2 + row * OUT_F + lane * 4) = st;
}

// ------------- attention tail -------------
__global__ void k_wred(const float* __restrict__ T, const float* __restrict__ bp,
                       const float* __restrict__ q, float* __restrict__ wsum) {
    __shared__ float sb[6];
    if (threadIdx.x < 6) sb[threadIdx.x] = 0.f;
    __syncthreads();
    int gw = (blockIdx.x * blockDim.x + threadIdx.x) >> 5;
    int lane = threadIdx.x & 31;
    bool valid = gw < 2 * NN * 3;
    float s = 0.f;
    int t = 0, k = 0;
    if (valid) {
        t = gw / (NN * 3);
        int r = gw - t * NN * 3;
        k = r % 3;
        const float* tp = T + (size_t)gw * OUT_F;
        int j0 = lane * 4;
        float4 tv = *(const float4*)(tp + j0);
        float4 bv = *(const float4*)(bp + j0);
        float4 qv = *(const float4*)(q + j0);
        s = tanhf(tv.x + bv.x) * qv.x + tanhf(tv.y + bv.y) * qv.y
          + tanhf(tv.z + bv.z) * qv.z + tanhf(tv.w + bv.w) * qv.w;
    }
#pragma unroll
    for (int o = 16; o; o >>= 1) s += __shfl_down_sync(0xffffffffu, s, o);
    if (valid && lane == 0) atomicAdd(&sb[t * 3 + k], s);
    __syncthreads();
    if (threadIdx.x < 6 && sb[threadIdx.x] != 0.f) atomicAdd(&wsum[threadIdx.x], sb[threadIdx.x]);
}

__global__ void k_beta(const float* __restrict__ wsum, float* __restrict__ beta,
                       float* __restrict__ outBeta) {
    if (threadIdx.x != 0 || blockIdx.x != 0) return;
    for (int t = 0; t < 2; ++t) {
        float w0 = wsum[t * 3 + 0] / (float)NN;
        float w1 = wsum[t * 3 + 1] / (float)NN;
        float w2 = wsum[t * 3 + 2] / (float)NN;
        float m = fmaxf(w0, fmaxf(w1, w2));
        float e0 = expf(w0 - m), e1 = expf(w1 - m), e2 = expf(w2 - m);
        float inv = 1.f / (e0 + e1 + e2);
        beta[t * 3 + 0] = e0 * inv; outBeta[t * 3 + 0] = e0 * inv;
        beta[t * 3 + 1] = e1 * inv; outBeta[t * 3 + 1] = e1 * inv;
        beta[t * 3 + 2] = e2 * inv; outBeta[t * 3 + 2] = e2 * inv;
    }
}

__global__ void k_combine(const float* __restrict__ zd, const float* __restrict__ zp,
                          const float* __restrict__ beta, float* __restrict__ out) {
    int i = blockIdx.x * blockDim.x + threadIdx.x;
    if (i >= 2 * NN * OUT_F) return;
    int t = i / (NN * OUT_F);
    int r = i - t * NN * OUT_F;
    int n = r / OUT_F, f = r - n * OUT_F;
    const float* z = (t ? zp : zd) + (size_t)n * (3 * OUT_F) + f;
    const float* b = beta + t * 3;
    out[i] = b[0] * z[0] + b[1] * z[OUT_F] + b[2] * z[2 * OUT_F];
}

// ---------------- host orchestration ----------------
extern "C" void kernel_launch(void* const* d_in, const int* in_sizes, int n_in,
                              void* d_out, int out_size) {
    const float* xd  = (const float*)d_in[0];
    const float* xp  = (const float*)d_in[1];
    const int*   src = (const int*)  d_in[2];
    const int*   dst = (const int*)  d_in[3];
    const float* W1  = (const float*)d_in[4];
    const float* b1  = (const float*)d_in[5];
    const float* W2  = (const float*)d_in[6];
    const float* b2  = (const float*)d_in[7];
    const float* Wpm = (const float*)d_in[8];
    const float* bp  = (const float*)d_in[9];
    const float* q   = (const float*)d_in[10];
    float* out = (float*)d_out;

    float *y, *zd, *zp, *rout, *rin, *wsum, *beta, *csrw;
    int *cnts, *cnt, *base, *cur, *csrs;
    bf16 *x1, *x2, *h1, *h2, *za1, *za2;
    bf16 *wt1a, *wt1b, *wt2a, *wt2b, *wpa, *wpb;
    cudaGetSymbolAddress((void**)&y,    g_y);
    cudaGetSymbolAddress((void**)&zd,   g_zd);
    cudaGetSymbolAddress((void**)&zp,   g_zp);
    cudaGetSymbolAddress((void**)&rout, g_rout);
    cudaGetSymbolAddress((void**)&rin,  g_rin);
    cudaGetSymbolAddress((void**)&wsum, g_wsum);
    cudaGetSymbolAddress((void**)&beta, g_beta);
    cudaGetSymbolAddress((void**)&cnts, g_cnts);
    cudaGetSymbolAddress((void**)&cnt,  g_cnt);
    cudaGetSymbolAddress((void**)&base, g_base);
    cudaGetSymbolAddress((void**)&cur,  g_cur);
    cudaGetSymbolAddress((void**)&csrs, g_csrs);
    cudaGetSymbolAddress((void**)&csrw, g_csrw);
    cudaGetSymbolAddress((void**)&x1,   g_x1);
    cudaGetSymbolAddress((void**)&x2,   g_x2);
    cudaGetSymbolAddress((void**)&h1,   g_h1);
    cudaGetSymbolAddress((void**)&h2,   g_h2);
    cudaGetSymbolAddress((void**)&za1,  g_za1);
    cudaGetSymbolAddress((void**)&za2,  g_za2);
    cudaGetSymbolAddress((void**)&wt1a, g_wt1a);
    cudaGetSymbolAddress((void**)&wt1b, g_wt1b);
    cudaGetSymbolAddress((void**)&wt2a, g_wt2a);
    cudaGetSymbolAddress((void**)&wt2b, g_wt2b);
    cudaGetSymbolAddress((void**)&wpa,  g_wpa);
    cudaGetSymbolAddress((void**)&wpb,  g_wpb);

    const int SMEM = 65536;
    cudaFuncSetAttribute(k_mma<IN_F, HID_F, 0>,
                         cudaFuncAttributeMaxDynamicSharedMemorySize, SMEM);
    cudaFuncSetAttribute(k_mma<HID_F, OUT_F, 1>,
                         cudaFuncAttributeMaxDynamicSharedMemorySize, SMEM);
    cudaFuncSetAttribute(k_mma<OUT_F, OUT_F, 0>,
                         cudaFuncAttributeMaxDynamicSharedMemorySize, SMEM);

    const int T = 256;
    const int mtiles = (NN + 127) / 128;            // 235
    const int gblocks = (NN * 32 + T - 1) / T;      // 3750

    // 1-3: splits + W1 transform (k_mma is launch #4 for ncu -s 5 -c 1)
    k_split<<<(NN * IN_F / 4 + T - 1) / T, T>>>(xd, x1, x2, NN * IN_F / 4);
    k_split<<<(NN * IN_F / 4 + T - 1) / T, T>>>(xp, x1 + (size_t)NN * IN_F,
                                                x2 + (size_t)NN * IN_F, NN * IN_F / 4);
    k_wts<<<dim3(HID_F / 32, IN_F / 32, 12), dim3(32, 8)>>>(W1, wt1a, wt1b, IN_F, HID_F);

    // 4: ALL 12 layer-1 GEMMs in one launch
    k_mma<IN_F, HID_F, 0><<<dim3(12 * (HID_F / 128), mtiles), 256, SMEM>>>(
        x1, x2, wt1a, wt1b, y, NN);

    // CSR + remaining weight transforms
    k_zeroi2<<<(12 * NN + T - 1) / T, T>>>(cnts, cnt, 12 * NN);
    k_hist2<<<(12 * EE + T - 1) / T, T>>>(src, dst, cnts, cnt);
    k_prep<<<(12 * NN + T - 1) / T, T>>>(cnts, cnt, rout, rin);
    k_scan<<<12, 1024>>>(cnt, base, cur);
    k_fill<<<(12 * EE + T - 1) / T, T>>>(src, dst, rout, cur, csrs, csrw);
    k_wts<<<dim3(OUT_F / 32, HID_F / 32, 12), dim3(32, 8)>>>(W2, wt2a, wt2b, HID_F, OUT_F);
    k_wts1<<<dim3(OUT_F / 32, OUT_F / 32), dim3(32, 8)>>>(Wpm, wpa, wpb, OUT_F, OUT_F);

    // gather layer 1
    k_gag1<<<dim3(gblocks, 6), T>>>(y, csrs, csrw, base, cnt, rin, b1, h1, h2);

    // ALL 12 layer-2 GEMMs
    k_mma<HID_F, OUT_F, 1><<<dim3(12, mtiles), 256, SMEM>>>(h1, h2, wt2a, wt2b, y, NN);

    // gather layer 2 (+ z bf16 split)
    k_gag2<<<dim3(gblocks, 6), T>>>(y, csrs, csrw, base, cnt, rin, b2, zd, zp, za1, za2);

    // attention GEMM
    const int rowsA = 2 * NN * 3;
    k_mma<OUT_F, OUT_F, 0><<<dim3(1, (rowsA + 127) / 128), 256, SMEM>>>(
        za1, za2, wpa, wpb, y, rowsA);

    k_zero<<<1, 32>>>(wsum, 8);
    k_wred<<<(rowsA * 32 + 255) / 256, 256>>>(y, bp, q, wsum);
    k_beta<<<1, 1>>>(wsum, beta, out + (size_t)2 * NN * OUT_F);
    k_combine<<<(2 * NN * OUT_F + T - 1) / T, T>>>(zd, zp, beta, out);
}

// round 8
// speedup vs baseline: 1.0069x; 1.0069x over previous
#include <cuda_runtime.h>
#include <cuda_bf16.h>
#include <cstdint>

#define NN 30000
#define EE 250000
#define IN_F 512
#define HID_F 256
#define OUT_F 128

typedef unsigned long long u64;
typedef __nv_bfloat16 bf16;

// ---------------- scratch (static device globals; no allocs) ----------------
__device__ float g_y[(size_t)12 * NN * HID_F];
__device__ float g_zd[(size_t)NN * 3 * OUT_F];
__device__ float g_zp[(size_t)NN * 3 * OUT_F];
__device__ float g_rout[12 * NN];
__device__ float g_rin[12 * NN];
__device__ float g_wsum[8];
__device__ float g_beta[8];
__device__ int   g_cnts[12 * NN];
__device__ int   g_cnt[12 * NN];
__device__ int   g_base[12 * NN];
__device__ int   g_cur[12 * NN];
__device__ int   g_csrs[(size_t)12 * EE];
__device__ float g_csrw[(size_t)12 * EE];
__device__ __align__(16) bf16 g_x1[(size_t)2 * NN * IN_F];
__device__ __align__(16) bf16 g_x2[(size_t)2 * NN * IN_F];
__device__ __align__(16) bf16 g_h1[(size_t)6 * NN * HID_F];
__device__ __align__(16) bf16 g_h2[(size_t)6 * NN * HID_F];
__device__ __align__(16) bf16 g_za1[(size_t)2 * NN * 3 * OUT_F];
__device__ __align__(16) bf16 g_za2[(size_t)2 * NN * 3 * OUT_F];
__device__ __align__(16) bf16 g_wt1a[(size_t)12 * HID_F * IN_F];
__device__ __align__(16) bf16 g_wt1b[(size_t)12 * HID_F * IN_F];
__device__ __align__(16) bf16 g_wt2a[(size_t)12 * OUT_F * HID_F];
__device__ __align__(16) bf16 g_wt2b[(size_t)12 * OUT_F * HID_F];
__device__ __align__(16) bf16 g_wpa[(size_t)OUT_F * OUT_F];
__device__ __align__(16) bf16 g_wpb[(size_t)OUT_F * OUT_F];

__device__ __forceinline__ void fma4(float4& a, float w, const float4 v) {
    a.x += w * v.x; a.y += w * v.y; a.z += w * v.z; a.w += w * v.w;
}
__device__ __forceinline__ int u2cr(int u) {
    int ci = u >> 2;
    int c = (ci == 0) ? 0 : (ci == 1 ? 2 : 3);
    return c * 4 + (u & 3);
}
__device__ __forceinline__ uint32_t smem_u32(const void* p) {
    uint32_t a;
    asm("{ .reg .u64 t; cvta.to.shared.u64 t, %1; cvt.u32.u64 %0, t; }" : "=r"(a) : "l"(p));
    return a;
}
__device__ __forceinline__ void cpa(uint32_t saddr, const void* g, int psize) {
    asm volatile("cp.async.cg.shared.global [%0], [%1], 16, %2;"
                 :: "r"(saddr), "l"(g), "r"(psize));
}

// ---------------- utility kernels ----------------
__global__ void k_zero(float* __restrict__ p, int n) {
    int i = blockIdx.x * blockDim.x + threadIdx.x;
    if (i < n) p[i] = 0.f;
}
__global__ void k_zeroi2(int* __restrict__ a, int* __restrict__ b, int n) {
    int i = blockIdx.x * blockDim.x + threadIdx.x;
    if (i < n) { a[i] = 0; b[i] = 0; }
}

__global__ void k_hist2(const int* __restrict__ src, const int* __restrict__ dst,
                        int* __restrict__ cnts, int* __restrict__ cntd) {
    int i = blockIdx.x * blockDim.x + threadIdx.x;
    if (i >= 12 * EE) return;
    int u = i / EE, e = i - u * EE;
    int cr = u2cr(u);
    atomicAdd(&cnts[u * NN + src[(size_t)cr * EE + e]], 1);
    atomicAdd(&cntd[u * NN + dst[(size_t)cr * EE + e]], 1);
}

__global__ void k_prep(const int* __restrict__ cnts, const int* __restrict__ cntd,
                       float* __restrict__ rout, float* __restrict__ rin) {
    int i = blockIdx.x * blockDim.x + threadIdx.x;
    if (i >= 12 * NN) return;
    rout[i] = rsqrtf((float)max(cnts[i], 1));
    rin[i]  = rsqrtf((float)max(cntd[i], 1));
}

// deterministic exclusive scan per u (12 blocks, 1024 threads)
__global__ void k_scan(const int* __restrict__ cnt, int* __restrict__ base,
                       int* __restrict__ cur) {
    __shared__ int ws[32];
    __shared__ int carry;
    int u = blockIdx.x;
    const int* c = cnt + u * NN;
    int* b = base + u * NN;
    int* q = cur + u * NN;
    int lane = threadIdx.x & 31, w = threadIdx.x >> 5;
    if (threadIdx.x == 0) carry = 0;
    __syncthreads();
    for (int off = 0; off < NN; off += 1024) {
        int i = off + threadIdx.x;
        int v = (i < NN) ? c[i] : 0;
        int s = v;
#pragma unroll
        for (int o = 1; o < 32; o <<= 1) {
            int t = __shfl_up_sync(0xffffffffu, s, o);
            if (lane >= o) s += t;
        }
        if (lane == 31) ws[w] = s;
        __syncthreads();
        if (w == 0) {
            int t2 = ws[lane];
#pragma unroll
            for (int o = 1; o < 32; o <<= 1) {
                int t = __shfl_up_sync(0xffffffffu, t2, o);
                if (lane >= o) t2 += t;
            }
            ws[lane] = t2;
        }
        __syncthreads();
        int excl = s - v + (w > 0 ? ws[w - 1] : 0) + carry;
        if (i < NN) { b[i] = excl; q[i] = excl; }
        __syncthreads();
        if (threadIdx.x == 1023) carry = excl + v;
        __syncthreads();
    }
}

__global__ void k_fill(const int* __restrict__ src, const int* __restrict__ dst,
                       const float* __restrict__ rout, int* __restrict__ cur,
                       int* __restrict__ csrs, float* __restrict__ csrw) {
    int i = blockIdx.x * blockDim.x + threadIdx.x;
    if (i >= 12 * EE) return;
    int u = i / EE, e = i - u * EE;
    int cr = u2cr(u);
    int s = src[(size_t)cr * EE + e];
    int d = dst[(size_t)cr * EE + e];
    int pos = atomicAdd(&cur[u * NN + d], 1);
    csrs[(size_t)u * EE + pos] = s;
    csrw[(size_t)u * EE + pos] = rout[u * NN + s];
}

// split fp32 -> bf16 hi/lo
__global__ void k_split(const float* __restrict__ x, bf16* __restrict__ hi,
                        bf16* __restrict__ lo, int n4) {
    int i = blockIdx.x * blockDim.x + threadIdx.x;
    if (i >= n4) return;
    float4 v = ((const float4*)x)[i];
    bf16 h0 = __float2bfloat16(v.x), h1 = __float2bfloat16(v.y);
    bf16 h2 = __float2bfloat16(v.z), h3 = __float2bfloat16(v.w);
    ((__nv_bfloat162*)hi)[2 * i]     = __halves2bfloat162(h0, h1);
    ((__nv_bfloat162*)hi)[2 * i + 1] = __halves2bfloat162(h2, h3);
    bf16 l0 = __float2bfloat16(v.x - __bfloat162float(h0));
    bf16 l1 = __float2bfloat16(v.y - __bfloat162float(h1));
    bf16 l2 = __float2bfloat16(v.z - __bfloat162float(h2));
    bf16 l3 = __float2bfloat16(v.w - __bfloat162float(h3));
    ((__nv_bfloat162*)lo)[2 * i]     = __halves2bfloat162(l0, l1);
    ((__nv_bfloat162*)lo)[2 * i + 1] = __halves2bfloat162(l2, l3);
}

// transpose+split weights
__global__ void k_wts(const float* __restrict__ W, bf16* __restrict__ t1,
                      bf16* __restrict__ t2, int K, int N) {
    __shared__ float tile[32][33];
    int z = blockIdx.z;
    int cz = z >> 2;
    int c = (cz == 0) ? 0 : (cz == 1 ? 2 : 3);
    const float* Wm = W + (size_t)(c * 4 + (z & 3)) * K * N;
    bf16* o1 = t1 + (size_t)z * K * N;
    bf16* o2 = t2 + (size_t)z * K * N;
    int k0 = blockIdx.y * 32, n0 = blockIdx.x * 32;
    for (int r = threadIdx.y; r < 32; r += 8)
        tile[r][threadIdx.x] = Wm[(size_t)(k0 + r) * N + n0 + threadIdx.x];
    __syncthreads();
    for (int r = threadIdx.y; r < 32; r += 8) {
        float v = tile[threadIdx.x][r];
        bf16 h = __float2bfloat16(v);
        size_t o = (size_t)(n0 + r) * K + k0 + threadIdx.x;
        o1[o] = h;
        o2[o] = __float2bfloat16(v - __bfloat162float(h));
    }
}

__global__ void k_wts1(const float* __restrict__ W, bf16* __restrict__ t1,
                       bf16* __restrict__ t2, int K, int N) {
    __shared__ float tile[32][33];
    int k0 = blockIdx.y * 32, n0 = blockIdx.x * 32;
    for (int r = threadIdx.y; r < 32; r += 8)
        tile[r][threadIdx.x] = W[(size_t)(k0 + r) * N + n0 + threadIdx.x];
    __syncthreads();
    for (int r = threadIdx.y; r < 32; r += 8) {
        float v = tile[threadIdx.x][r];
        bf16 h = __float2bfloat16(v);
        size_t o = (size_t)(n0 + r) * K + k0 + threadIdx.x;
        t1[o] = h;
        t2[o] = __float2bfloat16(v - __bfloat162float(h));
    }
}

// ---------------- fused 3-chain bf16 GEMM, 128x128 tile, 3-stage cp.async ----------------
__device__ __forceinline__ void mma16816(float* c, const uint32_t* a, const uint32_t* b) {
    asm volatile("mma.sync.aligned.m16n8k16.row.col.f32.bf16.bf16.f32 "
                 "{%0,%1,%2,%3}, {%4,%5,%6,%7}, {%8,%9}, {%0,%1,%2,%3};"
                 : "+f"(c[0]), "+f"(c[1]), "+f"(c[2]), "+f"(c[3])
                 : "r"(a[0]), "r"(a[1]), "r"(a[2]), "r"(a[3]), "r"(b[0]), "r"(b[1]));
}

template <int KK, int NOUT, int CH>
__global__ void __launch_bounds__(256, 2) k_mma(
    const bf16* __restrict__ A1b, const bf16* __restrict__ A2b,
    const bf16* __restrict__ Bt1, const bf16* __restrict__ Bt2,
    float* __restrict__ Y, int M) {
    // dynamic smem: 3 stages x (A1|A2|B1|B2), each tile 2048 words (128x32 bf16)
    extern __shared__ uint32_t S[];

    const int tid = threadIdx.x;
    const int lane = tid & 31;
    const int wid = tid >> 5;
    const int warpM = wid & 3;
    const int warpN = wid >> 2;
    constexpr int NT = NOUT / 128;
    const int u = blockIdx.x / NT;
    const int bn = (blockIdx.x % NT) * 128;
    const int bm = blockIdx.y * 128;

    const int aoff = (CH ? (u >> 2) * 2 : 0) + ((u & 3) >> 1);
    const bf16* A1 = A1b + (size_t)aoff * M * KK;
    const bf16* A2 = A2b + (size_t)aoff * M * KK;
    const bf16* B1 = Bt1 + (size_t)u * KK * NOUT;
    const bf16* B2 = Bt2 + (size_t)u * KK * NOUT;
    float* Yp = Y + (size_t)u * M * NOUT;

    const uint32_t sbase = smem_u32(S);

    // per-thread staging indices (slot i: row m0+64i, k-words seg*8..+7)
    const int m0 = tid >> 2, seg = tid & 3;
    const int kb0 = seg >> 1, h0 = seg & 1;
    const int r0 = ((m0 >> 3) & 1) + 2 * h0;
    const int Lb = (((m0 & 7) * 4) + seg * 8) & 31;
    const int Wa0 = ((kb0 * 8 + (m0 >> 4)) * 4 + r0) * 32 + Lb;
    const int Wb0 = ((kb0 * 16 + (m0 >> 3)) * 2 + h0) * 32 + Lb;

    float c[2][8][4];
#pragma unroll
    for (int i = 0; i < 2; ++i)
#pragma unroll
        for (int j = 0; j < 8; ++j)
#pragma unroll
            for (int l = 0; l < 4; ++l) c[i][j][l] = 0.f;

    auto issue_chunk = [&](int g) {
        const int koff = g * 32;
        const uint32_t sb = sbase + (uint32_t)(g % 3) * 32768;
#pragma unroll
        for (int i = 0; i < 2; ++i) {
            int m = m0 + 64 * i;
            int gm = bm + m;
            int pa = (gm < M) ? 16 : 0;
            int gmc = (gm < M) ? gm : (M - 1);
            uint32_t wa = sb + (uint32_t)(Wa0 + 512 * i) * 4;
            uint32_t wb = sb + (uint32_t)(Wb0 + 512 * i) * 4;
            cpa(wa,          A1 + (size_t)gmc * KK + koff + seg * 8, pa);
            cpa(wa + 8192,   A2 + (size_t)gmc * KK + koff + seg * 8, pa);
            cpa(wb + 16384,  B1 + (size_t)(bn + m) * KK + koff + seg * 8, 16);
            cpa(wb + 24576,  B2 + (size_t)(bn + m) * KK + koff + seg * 8, 16);
        }
        asm volatile("cp.async.commit_group;" ::: "memory");
    };

    constexpr int NC = KK / 32;
    issue_chunk(0);
    if (NC > 1) issue_chunk(1);

#pragma unroll 1
    for (int g = 0; g < NC; ++g) {
        if (g + 1 < NC)
            asm volatile("cp.async.wait_group 1;" ::: "memory");
        else
            asm volatile("cp.async.wait_group 0;" ::: "memory");
        __syncthreads();
        if (g + 2 < NC) issue_chunk(g + 2);

        const uint32_t* A1s = S + (g % 3) * 8192;
        const uint32_t* A2s = A1s + 2048;
        const uint32_t* B1s = A1s + 4096;
        const uint32_t* B2s = A1s + 6144;
#pragma unroll
        for (int kb = 0; kb < 2; ++kb) {
            uint32_t a1[2][4], a2[2][4];
#pragma unroll
            for (int mbl = 0; mbl < 2; ++mbl) {
                int mb = warpM * 2 + mbl;
#pragma unroll
                for (int r = 0; r < 4; ++r) {
                    int Lr = (lane + (kb * 2 + (r >> 1)) * 8) & 31;
                    int idx = ((kb * 8 + mb) * 4 + r) * 32 + Lr;
                    a1[mbl][r] = A1s[idx];
                    a2[mbl][r] = A2s[idx];
                }
            }
#pragma unroll
            for (int nbl = 0; nbl < 8; ++nbl) {
                int nb = warpN * 8 + nbl;
                uint32_t b1[2], b2[2];
#pragma unroll
                for (int h = 0; h < 2; ++h) {
                    int Lr = (lane + (kb * 2 + h) * 8) & 31;
                    int idx = ((kb * 16 + nb) * 2 + h) * 32 + Lr;
                    b1[h] = B1s[idx];
                    b2[h] = B2s[idx];
                }
#pragma unroll
                for (int mbl = 0; mbl < 2; ++mbl) {
                    mma16816(c[mbl][nbl], a1[mbl], b1);
                    mma16816(c[mbl][nbl], a1[mbl], b2);
                    mma16816(c[mbl][nbl], a2[mbl], b1);
                }
            }
        }
        // no trailing sync: 3-stage ring guarantees the buffer written by
        // issue_chunk(g+3) at the next iteration differs from both buffers
        // still being read, and the next wait+sync re-aligns all threads.
    }

#pragma unroll
    for (int mbl = 0; mbl < 2; ++mbl) {
        int mrow = bm + warpM * 32 + mbl * 16 + (lane >> 2);
#pragma unroll
        for (int nbl = 0; nbl < 8; ++nbl) {
            int ncol = bn + warpN * 64 + nbl * 8 + (lane & 3) * 2;
            float* base = Yp + (size_t)mrow * NOUT + ncol;
            if (mrow < M)
                *(float2*)base = make_float2(c[mbl][nbl][0], c[mbl][nbl][1]);
            if (mrow + 8 < M)
                *(float2*)(base + (size_t)8 * NOUT) = make_float2(c[mbl][nbl][2], c[mbl][nbl][3]);
        }
    }
}

// --------- fused gather layer1 ---------
__global__ void __launch_bounds__(256) k_gag1(
    const float* __restrict__ y,
    const int* __restrict__ csrs, const float* __restrict__ csrw,
    const int* __restrict__ base, const int* __restrict__ cnt,
    const float* __restrict__ rin, const float* __restrict__ b1,
    bf16* __restrict__ h1, bf16* __restrict__ h2) {
    int gw = (blockIdx.x * blockDim.x + threadIdx.x) >> 5;
    if (gw >= NN) return;
    int lane = threadIdx.x & 31;
    int d = gw;
    int by = blockIdx.y;
    int ci = by >> 1, t = by & 1;
    int uLo = ci * 4 + t, uHi = uLo + 2;
    int c = (ci == 0) ? 0 : (ci == 1 ? 2 : 3);
    const float* yLo = y + (size_t)uLo * NN * HID_F;
    const float* yHi = y + (size_t)uHi * NN * HID_F;
    const float* bLo = b1 + (c * 4 + t) * HID_F;
    const float* bHi = b1 + (c * 4 + t + 2) * HID_F;

    float4 a0 = make_float4(0, 0, 0, 0), a1 = a0, c0 = a0, c1 = a0;
    {
        int b = base[uLo * NN + d], n = cnt[uLo * NN + d];
        const int* cs = csrs + (size_t)uLo * EE;
        const float* cw = csrw + (size_t)uLo * EE;
        for (int i = 0; i < n; ++i) {
            int s = cs[b + i];
            float w = cw[b + i];
            const float4* r = (const float4*)(yLo + (size_t)s * HID_F);
            fma4(a0, w, r[lane]);
            fma4(a1, w, r[32 + lane]);
        }
    }
    {
        int b = base[uHi * NN + d], n = cnt[uHi * NN + d];
        const int* cs = csrs + (size_t)uHi * EE;
        const float* cw = csrw + (size_t)uHi * EE;
        for (int i = 0; i < n; ++i) {
            int s = cs[b + i];
            float w = cw[b + i];
            const float4* r = (const float4*)(yHi + (size_t)s * HID_F);
            fma4(c0, w, r[lane]);
            fma4(c1, w, r[32 + lane]);
        }
    }
    float rl = rin[uLo * NN + d], rh = rin[uHi * NN + d];
    bf16* o1 = h1 + (size_t)by * NN * HID_F;
    bf16* o2 = h2 + (size_t)by * NN * HID_F;
#pragma unroll
    for (int ch = 0; ch < 2; ++ch) {
        float4 A = ch ? a1 : a0, C = ch ? c1 : c0;
        float4 x = ((const float4*)bLo)[ch * 32 + lane];
        float4 yb = ((const float4*)bHi)[ch * 32 + lane];
        float r0 = fmaxf(x.x + yb.x + rl * A.x + rh * C.x, 0.f);
        float r1 = fmaxf(x.y + yb.y + rl * A.y + rh * C.y, 0.f);
        float r2 = fmaxf(x.z + yb.z + rl * A.z + rh * C.z, 0.f);
        float r3 = fmaxf(x.w + yb.w + rl * A.w + rh * C.w, 0.f);
        bf16 h0 = __float2bfloat16(r0), hh1 = __float2bfloat16(r1);
        bf16 h2v = __float2bfloat16(r2), h3 = __float2bfloat16(r3);
        __nv_bfloat162 p0 = __halves2bfloat162(h0, hh1);
        __nv_bfloat162 p1 = __halves2bfloat162(h2v, h3);
        uint2 st;
        st.x = *(unsigned*)&p0; st.y = *(unsigned*)&p1;
        size_t off = (size_t)d * HID_F + ch * 128 + lane * 4;
        *(uint2*)(o1 + off) = st;
        bf16 l0 = __float2bfloat16(r0 - __bfloat162float(h0));
        bf16 l1 = __float2bfloat16(r1 - __bfloat162float(hh1));
        bf16 l2 = __float2bfloat16(r2 - __bfloat162float(h2v));
        bf16 l3 = __float2bfloat16(r3 - __bfloat162float(h3));
        p0 = __halves2bfloat162(l0, l1);
        p1 = __halves2bfloat162(l2, l3);
        st.x = *(unsigned*)&p0; st.y = *(unsigned*)&p1;
        *(uint2*)(o2 + off) = st;
    }
}

// --------- fused gather layer2 + z split ---------
__global__ void __launch_bounds__(256) k_gag2(
    const float* __restrict__ y,
    const int* __restrict__ csrs, const float* __restrict__ csrw,
    const int* __restrict__ base, const int* __restrict__ cnt,
    const float* __restrict__ rin, const float* __restrict__ b2,
    float* __restrict__ zd, float* __restrict__ zp,
    bf16* __restrict__ za1, bf16* __restrict__ za2) {
    int gw = (blockIdx.x * blockDim.x + threadIdx.x) >> 5;
    if (gw >= NN) return;
    int lane = threadIdx.x & 31;
    int d = gw;
    int by = blockIdx.y;
    int ci = by >> 1, t = by & 1;
    int uLo = ci * 4 + t, uHi = uLo + 2;
    int c = (ci == 0) ? 0 : (ci == 1 ? 2 : 3);
    const float* yLo = y + (size_t)uLo * NN * OUT_F;
    const float* yHi = y + (size_t)uHi * NN * OUT_F;
    const float* bLo = b2 + (c * 4 + t) * OUT_F;
    const float* bHi = b2 + (c * 4 + t + 2) * OUT_F;

    float4 a0 = make_float4(0, 0, 0, 0), c0 = a0;
    {
        int b = base[uLo * NN + d], n = cnt[uLo * NN + d];
        const int* cs = csrs + (size_t)uLo * EE;
        const float* cw = csrw + (size_t)uLo * EE;
        for (int i = 0; i < n; ++i)
            fma4(a0, cw[b + i], ((const float4*)(yLo + (size_t)cs[b + i] * OUT_F))[lane]);
    }
    {
        int b = base[uHi * NN + d], n = cnt[uHi * NN + d];
        const int* cs = csrs + (size_t)uHi * EE;
        const float* cw = csrw + (size_t)uHi * EE;
        for (int i = 0; i < n; ++i)
            fma4(c0, cw[b + i], ((const float4*)(yHi + (size_t)cs[b + i] * OUT_F))[lane]);
    }
    float rl = rin[uLo * NN + d], rh = rin[uHi * NN + d];
    float4 x = ((const float4*)bLo)[lane], yb = ((const float4*)bHi)[lane];
    float4 res;
    res.x = fmaxf(x.x + yb.x + rl * a0.x + rh * c0.x, 0.f);
    res.y = fmaxf(x.y + yb.y + rl * a0.y + rh * c0.y, 0.f);
    res.z = fmaxf(x.z + yb.z + rl * a0.z + rh * c0.z, 0.f);
    res.w = fmaxf(x.w + yb.w + rl * a0.w + rh * c0.w, 0.f);
    float* zt = t ? zp : zd;
    *(float4*)(zt + (size_t)d * (3 * OUT_F) + ci * OUT_F + lane * 4) = res;

    size_t row = (size_t)t * NN * 3 + (size_t)d * 3 + ci;
    bf16 h0 = __float2bfloat16(res.x), h1 = __float2bfloat16(res.y);
    bf16 h2 = __float2bfloat16(res.z), h3 = __float2bfloat16(res.w);
    __nv_bfloat162 p0 = __halves2bfloat162(h0, h1);
    __nv_bfloat162 p1 = __halves2bfloat162(h2, h3);
    uint2 st;
    st.x = *(unsigned*)&p0; st.y = *(unsigned*)&p1;
    *(uint2*)(za1 + row * OUT_F + lane * 4) = st;
    bf16 l0 = __float2bfloat16(res.x - __bfloat162float(h0));
    bf16 l1 = __float2bfloat16(res.y - __bfloat162float(h1));
    bf16 l2 = __float2bfloat16(res.z - __bfloat162float(h2));
    bf16 l3 = __float2bfloat16(res.w - __bfloat162float(h3));
    p0 = __halves2bfloat162(l0, l1);
    p1 = __halves2bfloat162(l2, l3);
    st.x = *(unsigned*)&p0; st.y = *(unsigned*)&p1;
    *(uint2*)(za2 + row * OUT_F + lane * 4) = st;
}

// ------------- attention tail -------------
__global__ void k_wred(const float* __restrict__ T, const float* __restrict__ bp,
                       const float* __restrict__ q, float* __restrict__ wsum) {
    __shared__ float sb[6];
    if (threadIdx.x < 6) sb[threadIdx.x] = 0.f;
    __syncthreads();
    int gw = (blockIdx.x * blockDim.x + threadIdx.x) >> 5;
    int lane = threadIdx.x & 31;
    bool valid = gw < 2 * NN * 3;
    float s = 0.f;
    int t = 0, k = 0;
    if (valid) {
        t = gw / (NN * 3);
        int r = gw - t * NN * 3;
        k = r % 3;
        const float* tp = T + (size_t)gw * OUT_F;
        int j0 = lane * 4;
        float4 tv = *(const float4*)(tp + j0);
        float4 bv = *(const float4*)(bp + j0);
        float4 qv = *(const float4*)(q + j0);
        s = tanhf(tv.x + bv.x) * qv.x + tanhf(tv.y + bv.y) * qv.y
          + tanhf(tv.z + bv.z) * qv.z + tanhf(tv.w + bv.w) * qv.w;
    }
#pragma unroll
    for (int o = 16; o; o >>= 1) s += __shfl_down_sync(0xffffffffu, s, o);
    if (valid && lane == 0) atomicAdd(&sb[t * 3 + k], s);
    __syncthreads();
    if (threadIdx.x < 6 && sb[threadIdx.x] != 0.f) atomicAdd(&wsum[threadIdx.x], sb[threadIdx.x]);
}

__global__ void k_beta(const float* __restrict__ wsum, float* __restrict__ beta,
                       float* __restrict__ outBeta) {
    if (threadIdx.x != 0 || blockIdx.x != 0) return;
    for (int t = 0; t < 2; ++t) {
        float w0 = wsum[t * 3 + 0] / (float)NN;
        float w1 = wsum[t * 3 + 1] / (float)NN;
        float w2 = wsum[t * 3 + 2] / (float)NN;
        float m = fmaxf(w0, fmaxf(w1, w2));
        float e0 = expf(w0 - m), e1 = expf(w1 - m), e2 = expf(w2 - m);
        float inv = 1.f / (e0 + e1 + e2);
        beta[t * 3 + 0] = e0 * inv; outBeta[t * 3 + 0] = e0 * inv;
        beta[t * 3 + 1] = e1 * inv; outBeta[t * 3 + 1] = e1 * inv;
        beta[t * 3 + 2] = e2 * inv; outBeta[t * 3 + 2] = e2 * inv;
    }
}

__global__ void k_combine(const float* __restrict__ zd, const float* __restrict__ zp,
                          const float* __restrict__ beta, float* __restrict__ out) {
    int i = blockIdx.x * blockDim.x + threadIdx.x;
    if (i >= 2 * NN * OUT_F) return;
    int t = i / (NN * OUT_F);
    int r = i - t * NN * OUT_F;
    int n = r / OUT_F, f = r - n * OUT_F;
    const float* z = (t ? zp : zd) + (size_t)n * (3 * OUT_F) + f;
    const float* b = beta + t * 3;
    out[i] = b[0] * z[0] + b[1] * z[OUT_F] + b[2] * z[2 * OUT_F];
}

// ---------------- host orchestration ----------------
extern "C" void kernel_launch(void* const* d_in, const int* in_sizes, int n_in,
                              void* d_out, int out_size) {
    const float* xd  = (const float*)d_in[0];
    const float* xp  = (const float*)d_in[1];
    const int*   src = (const int*)  d_in[2];
    const int*   dst = (const int*)  d_in[3];
    const float* W1  = (const float*)d_in[4];
    const float* b1  = (const float*)d_in[5];
    const float* W2  = (const float*)d_in[6];
    const float* b2  = (const float*)d_in[7];
    const float* Wpm = (const float*)d_in[8];
    const float* bp  = (const float*)d_in[9];
    const float* q   = (const float*)d_in[10];
    float* out = (float*)d_out;

    float *y, *zd, *zp, *rout, *rin, *wsum, *beta, *csrw;
    int *cnts, *cnt, *base, *cur, *csrs;
    bf16 *x1, *x2, *h1, *h2, *za1, *za2;
    bf16 *wt1a, *wt1b, *wt2a, *wt2b, *wpa, *wpb;
    cudaGetSymbolAddress((void**)&y,    g_y);
    cudaGetSymbolAddress((void**)&zd,   g_zd);
    cudaGetSymbolAddress((void**)&zp,   g_zp);
    cudaGetSymbolAddress((void**)&rout, g_rout);
    cudaGetSymbolAddress((void**)&rin,  g_rin);
    cudaGetSymbolAddress((void**)&wsum, g_wsum);
    cudaGetSymbolAddress((void**)&beta, g_beta);
    cudaGetSymbolAddress((void**)&cnts, g_cnts);
    cudaGetSymbolAddress((void**)&cnt,  g_cnt);
    cudaGetSymbolAddress((void**)&base, g_base);
    cudaGetSymbolAddress((void**)&cur,  g_cur);
    cudaGetSymbolAddress((void**)&csrs, g_csrs);
    cudaGetSymbolAddress((void**)&csrw, g_csrw);
    cudaGetSymbolAddress((void**)&x1,   g_x1);
    cudaGetSymbolAddress((void**)&x2,   g_x2);
    cudaGetSymbolAddress((void**)&h1,   g_h1);
    cudaGetSymbolAddress((void**)&h2,   g_h2);
    cudaGetSymbolAddress((void**)&za1,  g_za1);
    cudaGetSymbolAddress((void**)&za2,  g_za2);
    cudaGetSymbolAddress((void**)&wt1a, g_wt1a);
    cudaGetSymbolAddress((void**)&wt1b, g_wt1b);
    cudaGetSymbolAddress((void**)&wt2a, g_wt2a);
    cudaGetSymbolAddress((void**)&wt2b, g_wt2b);
    cudaGetSymbolAddress((void**)&wpa,  g_wpa);
    cudaGetSymbolAddress((void**)&wpb,  g_wpb);

    const int SMEM = 3 * 32768;   // 98304
    cudaFuncSetAttribute(k_mma<IN_F, HID_F, 0>,
                         cudaFuncAttributeMaxDynamicSharedMemorySize, SMEM);
    cudaFuncSetAttribute(k_mma<HID_F, OUT_F, 1>,
                         cudaFuncAttributeMaxDynamicSharedMemorySize, SMEM);
    cudaFuncSetAttribute(k_mma<OUT_F, OUT_F, 0>,
                         cudaFuncAttributeMaxDynamicSharedMemorySize, SMEM);

    const int T = 256;
    const int mtiles = (NN + 127) / 128;            // 235
    const int gblocks = (NN * 32 + T - 1) / T;      // 3750

    // 1-3: splits + W1 transform (k_mma is launch #4 for ncu -s 5 -c 1)
    k_split<<<(NN * IN_F / 4 + T - 1) / T, T>>>(xd, x1, x2, NN * IN_F / 4);
    k_split<<<(NN * IN_F / 4 + T - 1) / T, T>>>(xp, x1 + (size_t)NN * IN_F,
                                                x2 + (size_t)NN * IN_F, NN * IN_F / 4);
    k_wts<<<dim3(HID_F / 32, IN_F / 32, 12), dim3(32, 8)>>>(W1, wt1a, wt1b, IN_F, HID_F);

    // 4: ALL 12 layer-1 GEMMs in one launch
    k_mma<IN_F, HID_F, 0><<<dim3(12 * (HID_F / 128), mtiles), 256, SMEM>>>(
        x1, x2, wt1a, wt1b, y, NN);

    // CSR + remaining weight transforms
    k_zeroi2<<<(12 * NN + T - 1) / T, T>>>(cnts, cnt, 12 * NN);
    k_hist2<<<(12 * EE + T - 1) / T, T>>>(src, dst, cnts, cnt);
    k_prep<<<(12 * NN + T - 1) / T, T>>>(cnts, cnt, rout, rin);
    k_scan<<<12, 1024>>>(cnt, base, cur);
    k_fill<<<(12 * EE + T - 1) / T, T>>>(src, dst, rout, cur, csrs, csrw);
    k_wts<<<dim3(OUT_F / 32, HID_F / 32, 12), dim3(32, 8)>>>(W2, wt2a, wt2b, HID_F, OUT_F);
    k_wts1<<<dim3(OUT_F / 32, OUT_F / 32), dim3(32, 8)>>>(Wpm, wpa, wpb, OUT_F, OUT_F);

    // gather layer 1
    k_gag1<<<dim3(gblocks, 6), T>>>(y, csrs, csrw, base, cnt, rin, b1, h1, h2);

    // ALL 12 layer-2 GEMMs
    k_mma<HID_F, OUT_F, 1><<<dim3(12, mtiles), 256, SMEM>>>(h1, h2, wt2a, wt2b, y, NN);

    // gather layer 2 (+ z bf16 split)
    k_gag2<<<dim3(gblocks, 6), T>>>(y, csrs, csrw, base, cnt, rin, b2, zd, zp, za1, za2);

    // attention GEMM
    const int rowsA = 2 * NN * 3;
    k_mma<OUT_F, OUT_F, 0><<<dim3(1, (rowsA + 127) / 128), 256, SMEM>>>(
        za1, za2, wpa, wpb, y, rowsA);

    k_zero<<<1, 32>>>(wsum, 8);
    k_wred<<<(rowsA * 32 + 255) / 256, 256>>>(y, bp, q, wsum);
    k_beta<<<1, 1>>>(wsum, beta, out + (size_t)2 * NN * OUT_F);
    k_combine<<<(2 * NN * OUT_F + T - 1) / T, T>>>(zd, zp, beta, out);
}

// round 9
// speedup vs baseline: 1.0773x; 1.0699x over previous
#include <cuda_runtime.h>
#include <cuda_bf16.h>
#include <cstdint>

#define NN 30000
#define EE 250000
#define IN_F 512
#define HID_F 256
#define OUT_F 128

typedef unsigned long long u64;
typedef __nv_bfloat16 bf16;

// ---------------- scratch (static device globals; no allocs) ----------------
__device__ float g_y[(size_t)12 * NN * HID_F];
__device__ float g_zd[(size_t)NN * 3 * OUT_F];
__device__ float g_zp[(size_t)NN * 3 * OUT_F];
__device__ float g_rout[12 * NN];
__device__ float g_rin[12 * NN];
__device__ float g_wsum[8];
__device__ float g_beta[8];
__device__ int   g_cnts[12 * NN];
__device__ int   g_cnt[12 * NN];
__device__ int   g_base[12 * NN];
__device__ int   g_cur[12 * NN];
__device__ int   g_csrs[(size_t)12 * EE];
__device__ float g_csrw[(size_t)12 * EE];
__device__ __align__(16) bf16 g_x1[(size_t)2 * NN * IN_F];
__device__ __align__(16) bf16 g_x2[(size_t)2 * NN * IN_F];
__device__ __align__(16) bf16 g_h1[(size_t)6 * NN * HID_F];
__device__ __align__(16) bf16 g_h2[(size_t)6 * NN * HID_F];
__device__ __align__(16) bf16 g_za1[(size_t)2 * NN * 3 * OUT_F];
__device__ __align__(16) bf16 g_wt1a[(size_t)12 * HID_F * IN_F];
__device__ __align__(16) bf16 g_wt1b[(size_t)12 * HID_F * IN_F];
__device__ __align__(16) bf16 g_wt2a[(size_t)12 * OUT_F * HID_F];
__device__ __align__(16) bf16 g_wt2b[(size_t)12 * OUT_F * HID_F];
__device__ __align__(16) bf16 g_wpa[(size_t)OUT_F * OUT_F];
__device__ __align__(16) bf16 g_wpb[(size_t)OUT_F * OUT_F];

__device__ __forceinline__ void fma4(float4& a, float w, const float4 v) {
    a.x += w * v.x; a.y += w * v.y; a.z += w * v.z; a.w += w * v.w;
}
__device__ __forceinline__ int u2cr(int u) {
    int ci = u >> 2;
    int c = (ci == 0) ? 0 : (ci == 1 ? 2 : 3);
    return c * 4 + (u & 3);
}

// ---------------- side-stream handles (created at static init, pre-checkpoint) ---
struct SideStream {
    cudaStream_t s = nullptr;
    cudaEvent_t fork = nullptr, join = nullptr;
    SideStream() {
        cudaStreamCreateWithFlags(&s, cudaStreamNonBlocking);
        cudaEventCreateWithFlags(&fork, cudaEventDisableTiming);
        cudaEventCreateWithFlags(&join, cudaEventDisableTiming);
    }
};
static SideStream g_ss;

// ---------------- utility kernels ----------------
__global__ void k_zero(float* __restrict__ p, int n) {
    int i = blockIdx.x * blockDim.x + threadIdx.x;
    if (i < n) p[i] = 0.f;
}
__global__ void k_zeroi2(int* __restrict__ a, int* __restrict__ b, int n) {
    int i = blockIdx.x * blockDim.x + threadIdx.x;
    if (i < n) { a[i] = 0; b[i] = 0; }
}

__global__ void k_hist2(const int* __restrict__ src, const int* __restrict__ dst,
                        int* __restrict__ cnts, int* __restrict__ cntd) {
    int i = blockIdx.x * blockDim.x + threadIdx.x;
    if (i >= 12 * EE) return;
    int u = i / EE, e = i - u * EE;
    int cr = u2cr(u);
    atomicAdd(&cnts[u * NN + src[(size_t)cr * EE + e]], 1);
    atomicAdd(&cntd[u * NN + dst[(size_t)cr * EE + e]], 1);
}

__global__ void k_prep(const int* __restrict__ cnts, const int* __restrict__ cntd,
                       float* __restrict__ rout, float* __restrict__ rin) {
    int i = blockIdx.x * blockDim.x + threadIdx.x;
    if (i >= 12 * NN) return;
    rout[i] = rsqrtf((float)max(cnts[i], 1));
    rin[i]  = rsqrtf((float)max(cntd[i], 1));
}

// deterministic exclusive scan per u (12 blocks, 1024 threads)
__global__ void k_scan(const int* __restrict__ cnt, int* __restrict__ base,
                       int* __restrict__ cur) {
    __shared__ int ws[32];
    __shared__ int carry;
    int u = blockIdx.x;
    const int* c = cnt + u * NN;
    int* b = base + u * NN;
    int* q = cur + u * NN;
    int lane = threadIdx.x & 31, w = threadIdx.x >> 5;
    if (threadIdx.x == 0) carry = 0;
    __syncthreads();
    for (int off = 0; off < NN; off += 1024) {
        int i = off + threadIdx.x;
        int v = (i < NN) ? c[i] : 0;
        int s = v;
#pragma unroll
        for (int o = 1; o < 32; o <<= 1) {
            int t = __shfl_up_sync(0xffffffffu, s, o);
            if (lane >= o) s += t;
        }
        if (lane == 31) ws[w] = s;
        __syncthreads();
        if (w == 0) {
            int t2 = ws[lane];
#pragma unroll
            for (int o = 1; o < 32; o <<= 1) {
                int t = __shfl_up_sync(0xffffffffu, t2, o);
                if (lane >= o) t2 += t;
            }
            ws[lane] = t2;
        }
        __syncthreads();
        int excl = s - v + (w > 0 ? ws[w - 1] : 0) + carry;
        if (i < NN) { b[i] = excl; q[i] = excl; }
        __syncthreads();
        if (threadIdx.x == 1023) carry = excl + v;
        __syncthreads();
    }
}

__global__ void k_fill(const int* __restrict__ src, const int* __restrict__ dst,
                       const float* __restrict__ rout, int* __restrict__ cur,
                       int* __restrict__ csrs, float* __restrict__ csrw) {
    int i = blockIdx.x * blockDim.x + threadIdx.x;
    if (i >= 12 * EE) return;
    int u = i / EE, e = i - u * EE;
    int cr = u2cr(u);
    int s = src[(size_t)cr * EE + e];
    int d = dst[(size_t)cr * EE + e];
    int pos = atomicAdd(&cur[u * NN + d], 1);
    csrs[(size_t)u * EE + pos] = s;
    csrw[(size_t)u * EE + pos] = rout[u * NN + s];
}

// split fp32 -> bf16 hi/lo
__global__ void k_split(const float* __restrict__ x, bf16* __restrict__ hi,
                        bf16* __restrict__ lo, int n4) {
    int i = blockIdx.x * blockDim.x + threadIdx.x;
    if (i >= n4) return;
    float4 v = ((const float4*)x)[i];
    bf16 h0 = __float2bfloat16(v.x), h1 = __float2bfloat16(v.y);
    bf16 h2 = __float2bfloat16(v.z), h3 = __float2bfloat16(v.w);
    ((__nv_bfloat162*)hi)[2 * i]     = __halves2bfloat162(h0, h1);
    ((__nv_bfloat162*)hi)[2 * i + 1] = __halves2bfloat162(h2, h3);
    bf16 l0 = __float2bfloat16(v.x - __bfloat162float(h0));
    bf16 l1 = __float2bfloat16(v.y - __bfloat162float(h1));
    bf16 l2 = __float2bfloat16(v.z - __bfloat162float(h2));
    bf16 l3 = __float2bfloat16(v.w - __bfloat162float(h3));
    ((__nv_bfloat162*)lo)[2 * i]     = __halves2bfloat162(l0, l1);
    ((__nv_bfloat162*)lo)[2 * i + 1] = __halves2bfloat162(l2, l3);
}

// transpose+split weights
__global__ void k_wts(const float* __restrict__ W, bf16* __restrict__ t1,
                      bf16* __restrict__ t2, int K, int N) {
    __shared__ float tile[32][33];
    int z = blockIdx.z;
    int cz = z >> 2;
    int c = (cz == 0) ? 0 : (cz == 1 ? 2 : 3);
    const float* Wm = W + (size_t)(c * 4 + (z & 3)) * K * N;
    bf16* o1 = t1 + (size_t)z * K * N;
    bf16* o2 = t2 + (size_t)z * K * N;
    int k0 = blockIdx.y * 32, n0 = blockIdx.x * 32;
    for (int r = threadIdx.y; r < 32; r += 8)
        tile[r][threadIdx.x] = Wm[(size_t)(k0 + r) * N + n0 + threadIdx.x];
    __syncthreads();
    for (int r = threadIdx.y; r < 32; r += 8) {
        float v = tile[threadIdx.x][r];
        bf16 h = __float2bfloat16(v);
        size_t o = (size_t)(n0 + r) * K + k0 + threadIdx.x;
        o1[o] = h;
        o2[o] = __float2bfloat16(v - __bfloat162float(h));
    }
}

__global__ void k_wts1(const float* __restrict__ W, bf16* __restrict__ t1,
                       bf16* __restrict__ t2, int K, int N) {
    __shared__ float tile[32][33];
    int k0 = blockIdx.y * 32, n0 = blockIdx.x * 32;
    for (int r = threadIdx.y; r < 32; r += 8)
        tile[r][threadIdx.x] = W[(size_t)(k0 + r) * N + n0 + threadIdx.x];
    __syncthreads();
    for (int r = threadIdx.y; r < 32; r += 8) {
        float v = tile[threadIdx.x][r];
        bf16 h = __float2bfloat16(v);
        size_t o = (size_t)(n0 + r) * K + k0 + threadIdx.x;
        t1[o] = h;
        t2[o] = __float2bfloat16(v - __bfloat162float(h));
    }
}

// ---------------- mma.sync bf16 GEMM, 128x128 tile (R6 winner), CHAINS param ---
__device__ __forceinline__ void mma16816(float* c, const uint32_t* a, const uint32_t* b) {
    asm volatile("mma.sync.aligned.m16n8k16.row.col.f32.bf16.bf16.f32 "
                 "{%0,%1,%2,%3}, {%4,%5,%6,%7}, {%8,%9}, {%0,%1,%2,%3};"
                 : "+f"(c[0]), "+f"(c[1]), "+f"(c[2]), "+f"(c[3])
                 : "r"(a[0]), "r"(a[1]), "r"(a[2]), "r"(a[3]), "r"(b[0]), "r"(b[1]));
}

template <int KK, int NOUT, int CH, int CHAINS>
__global__ void __launch_bounds__(256, 2) k_mma(
    const bf16* __restrict__ A1b, const bf16* __restrict__ A2b,
    const bf16* __restrict__ Bt1, const bf16* __restrict__ Bt2,
    float* __restrict__ Y, int M) {
    __shared__ uint32_t AS[2][2048];   // 128 x 32 bf16
    __shared__ uint32_t BS[2][2048];   // 128 x 32 bf16

    const int tid = threadIdx.x;
    const int lane = tid & 31;
    const int wid = tid >> 5;
    const int warpM = wid & 3;
    const int warpN = wid >> 2;        // 0..1
    constexpr int NT = NOUT / 128;
    const int u = blockIdx.x / NT;
    const int bn = (blockIdx.x % NT) * 128;
    const int bm = blockIdx.y * 128;

    const int aoff = (CH ? (u >> 2) * 2 : 0) + ((u & 3) >> 1);
    const bf16* A1 = A1b + (size_t)aoff * M * KK;
    const bf16* A2 = A2b + (size_t)aoff * M * KK;
    const bf16* B1 = Bt1 + (size_t)u * KK * NOUT;
    const bf16* B2 = Bt2 + (size_t)u * KK * NOUT;
    float* Yp = Y + (size_t)u * M * NOUT;

    const bf16* APass[3] = {A1, A1, A2};
    const bf16* BPass[3] = {B1, B2, B1};

    constexpr int CPP = KK / 32;
    constexpr int NP = (CHAINS == 3) ? 3 : 1;
    constexpr int NC = NP * CPP;

    float c[2][8][4];
#pragma unroll
    for (int i = 0; i < 2; ++i)
#pragma unroll
        for (int j = 0; j < 8; ++j)
#pragma unroll
            for (int l = 0; l < 4; ++l) c[i][j][l] = 0.f;

    uint4 va[2], vb[2];
    {
        const bf16* Ag = APass[0];
        const bf16* Bg = BPass[0];
#pragma unroll
        for (int i = 0; i < 2; ++i) {
            int u2 = tid + i * 256;
            int m = u2 >> 2, seg = u2 & 3;
            int gm = bm + m;
            va[i] = make_uint4(0, 0, 0, 0);
            if (gm < M)
                va[i] = *(const uint4*)(Ag + (size_t)gm * KK + (seg >> 1) * 16 + (seg & 1) * 8);
            int n = u2 >> 2;
            vb[i] = *(const uint4*)(Bg + (size_t)(bn + n) * KK + (seg >> 1) * 16 + (seg & 1) * 8);
        }
    }

#pragma unroll 1
    for (int g = 0; g < NC; ++g) {
        const int buf = g & 1;
#pragma unroll
        for (int i = 0; i < 2; ++i) {
            int u2 = tid + i * 256;
            int m = u2 >> 2, seg = u2 & 3;
            int kb = seg >> 1, h = seg & 1;
            int r = ((m >> 3) & 1) + 2 * h;
            int Lb = (((m & 7) * 4) + seg * 8) & 31;
            int W = ((kb * 8 + (m >> 4)) * 4 + r) * 32 + Lb;
            *(uint4*)&AS[buf][W] = va[i];
            int n = m;
            int Wb = ((kb * 16 + (n >> 3)) * 2 + h) * 32 + Lb;
            *(uint4*)&BS[buf][Wb] = vb[i];
        }
        __syncthreads();

        if (g + 1 < NC) {
            int pass = (g + 1) / CPP, kc = (g + 1) % CPP;
            const bf16* Ag = APass[pass];
            const bf16* Bg = BPass[pass];
            int koff = kc * 32;
#pragma unroll
            for (int i = 0; i < 2; ++i) {
                int u2 = tid + i * 256;
                int m = u2 >> 2, seg = u2 & 3;
                int gm = bm + m;
                va[i] = make_uint4(0, 0, 0, 0);
                if (gm < M)
                    va[i] = *(const uint4*)(Ag + (size_t)gm * KK + koff +
                                            (seg >> 1) * 16 + (seg & 1) * 8);
                vb[i] = *(const uint4*)(Bg + (size_t)(bn + m) * KK + koff +
                                        (seg >> 1) * 16 + (seg & 1) * 8);
            }
        }

#pragma unroll
        for (int kb = 0; kb < 2; ++kb) {
            uint32_t a[2][4], b[8][2];
#pragma unroll
            for (int mbl = 0; mbl < 2; ++mbl) {
                int mb = warpM * 2 + mbl;
#pragma unroll
                for (int r = 0; r < 4; ++r) {
                    int Lr = (lane + (kb * 2 + (r >> 1)) * 8) & 31;
                    a[mbl][r] = AS[buf][((kb * 8 + mb) * 4 + r) * 32 + Lr];
                }
            }
#pragma unroll
            for (int nbl = 0; nbl < 8; ++nbl) {
                int nb = warpN * 8 + nbl;
#pragma unroll
                for (int h = 0; h < 2; ++h) {
                    int Lr = (lane + (kb * 2 + h) * 8) & 31;
                    b[nbl][h] = BS[buf][((kb * 16 + nb) * 2 + h) * 32 + Lr];
                }
            }
#pragma unroll
            for (int mbl = 0; mbl < 2; ++mbl)
#pragma unroll
                for (int nbl = 0; nbl < 8; ++nbl)
                    mma16816(c[mbl][nbl], a[mbl], b[nbl]);
        }
        __syncthreads();
    }

#pragma unroll
    for (int mbl = 0; mbl < 2; ++mbl) {
        int mrow = bm + warpM * 32 + mbl * 16 + (lane >> 2);
#pragma unroll
        for (int nbl = 0; nbl < 8; ++nbl) {
            int ncol = bn + warpN * 64 + nbl * 8 + (lane & 3) * 2;
            float* base = Yp + (size_t)mrow * NOUT + ncol;
            if (mrow < M)
                *(float2*)base = make_float2(c[mbl][nbl][0], c[mbl][nbl][1]);
            if (mrow + 8 < M)
                *(float2*)(base + (size_t)8 * NOUT) = make_float2(c[mbl][nbl][2], c[mbl][nbl][3]);
        }
    }
}

// --------- fused gather layer1 ---------
__global__ void __launch_bounds__(256) k_gag1(
    const float* __restrict__ y,
    const int* __restrict__ csrs, const float* __restrict__ csrw,
    const int* __restrict__ base, const int* __restrict__ cnt,
    const float* __restrict__ rin, const float* __restrict__ b1,
    bf16* __restrict__ h1, bf16* __restrict__ h2) {
    int gw = (blockIdx.x * blockDim.x + threadIdx.x) >> 5;
    if (gw >= NN) return;
    int lane = threadIdx.x & 31;
    int d = gw;
    int by = blockIdx.y;
    int ci = by >> 1, t = by & 1;
    int uLo = ci * 4 + t, uHi = uLo + 2;
    int c = (ci == 0) ? 0 : (ci == 1 ? 2 : 3);
    const float* yLo = y + (size_t)uLo * NN * HID_F;
    const float* yHi = y + (size_t)uHi * NN * HID_F;
    const float* bLo = b1 + (c * 4 + t) * HID_F;
    const float* bHi = b1 + (c * 4 + t + 2) * HID_F;

    float4 a0 = make_float4(0, 0, 0, 0), a1 = a0, c0 = a0, c1 = a0;
    {
        int b = base[uLo * NN + d], n = cnt[uLo * NN + d];
        const int* cs = csrs + (size_t)uLo * EE;
        const float* cw = csrw + (size_t)uLo * EE;
        for (int i = 0; i < n; ++i) {
            int s = cs[b + i];
            float w = cw[b + i];
            const float4* r = (const float4*)(yLo + (size_t)s * HID_F);
            fma4(a0, w, r[lane]);
            fma4(a1, w, r[32 + lane]);
        }
    }
    {
        int b = base[uHi * NN + d], n = cnt[uHi * NN + d];
        const int* cs = csrs + (size_t)uHi * EE;
        const float* cw = csrw + (size_t)uHi * EE;
        for (int i = 0; i < n; ++i) {
            int s = cs[b + i];
            float w = cw[b + i];
            const float4* r = (const float4*)(yHi + (size_t)s * HID_F);
            fma4(c0, w, r[lane]);
            fma4(c1, w, r[32 + lane]);
        }
    }
    float rl = rin[uLo * NN + d], rh = rin[uHi * NN + d];
    bf16* o1 = h1 + (size_t)by * NN * HID_F;
    bf16* o2 = h2 + (size_t)by * NN * HID_F;
#pragma unroll
    for (int ch = 0; ch < 2; ++ch) {
        float4 A = ch ? a1 : a0, C = ch ? c1 : c0;
        float4 x = ((const float4*)bLo)[ch * 32 + lane];
        float4 yb = ((const float4*)bHi)[ch * 32 + lane];
        float r0 = fmaxf(x.x + yb.x + rl * A.x + rh * C.x, 0.f);
        float r1 = fmaxf(x.y + yb.y + rl * A.y + rh * C.y, 0.f);
        float r2 = fmaxf(x.z + yb.z + rl * A.z + rh * C.z, 0.f);
        float r3 = fmaxf(x.w + yb.w + rl * A.w + rh * C.w, 0.f);
        bf16 h0 = __float2bfloat16(r0), hh1 = __float2bfloat16(r1);
        bf16 h2v = __float2bfloat16(r2), h3 = __float2bfloat16(r3);
        __nv_bfloat162 p0 = __halves2bfloat162(h0, hh1);
        __nv_bfloat162 p1 = __halves2bfloat162(h2v, h3);
        uint2 st;
        st.x = *(unsigned*)&p0; st.y = *(unsigned*)&p1;
        size_t off = (size_t)d * HID_F + ch * 128 + lane * 4;
        *(uint2*)(o1 + off) = st;
        bf16 l0 = __float2bfloat16(r0 - __bfloat162float(h0));
        bf16 l1 = __float2bfloat16(r1 - __bfloat162float(hh1));
        bf16 l2 = __float2bfloat16(r2 - __bfloat162float(h2v));
        bf16 l3 = __float2bfloat16(r3 - __bfloat162float(h3));
        p0 = __halves2bfloat162(l0, l1);
        p1 = __halves2bfloat162(l2, l3);
        st.x = *(unsigned*)&p0; st.y = *(unsigned*)&p1;
        *(uint2*)(o2 + off) = st;
    }
}

// --------- fused gather layer2 + z hi-split (za1 only) ---------
__global__ void __launch_bounds__(256) k_gag2(
    const float* __restrict__ y,
    const int* __restrict__ csrs, const float* __restrict__ csrw,
    const int* __restrict__ base, const int* __restrict__ cnt,
    const float* __restrict__ rin, const float* __restrict__ b2,
    float* __restrict__ zd, float* __restrict__ zp,
    bf16* __restrict__ za1) {
    int gw = (blockIdx.x * blockDim.x + threadIdx.x) >> 5;
    if (gw >= NN) return;
    int lane = threadIdx.x & 31;
    int d = gw;
    int by = blockIdx.y;
    int ci = by >> 1, t = by & 1;
    int uLo = ci * 4 + t, uHi = uLo + 2;
    int c = (ci == 0) ? 0 : (ci == 1 ? 2 : 3);
    const float* yLo = y + (size_t)uLo * NN * OUT_F;
    const float* yHi = y + (size_t)uHi * NN * OUT_F;
    const float* bLo = b2 + (c * 4 + t) * OUT_F;
    const float* bHi = b2 + (c * 4 + t + 2) * OUT_F;

    float4 a0 = make_float4(0, 0, 0, 0), c0 = a0;
    {
        int b = base[uLo * NN + d], n = cnt[uLo * NN + d];
        const int* cs = csrs + (size_t)uLo * EE;
        const float* cw = csrw + (size_t)uLo * EE;
        for (int i = 0; i < n; ++i)
            fma4(a0, cw[b + i], ((const float4*)(yLo + (size_t)cs[b + i] * OUT_F))[lane]);
    }
    {
        int b = base[uHi * NN + d], n = cnt[uHi * NN + d];
        const int* cs = csrs + (size_t)uHi * EE;
        const float* cw = csrw + (size_t)uHi * EE;
        for (int i = 0; i < n; ++i)
            fma4(c0, cw[b + i], ((const float4*)(yHi + (size_t)cs[b + i] * OUT_F))[lane]);
    }
    float rl = rin[uLo * NN + d], rh = rin[uHi * NN + d];
    float4 x = ((const float4*)bLo)[lane], yb = ((const float4*)bHi)[lane];
    float4 res;
    res.x = fmaxf(x.x + yb.x + rl * a0.x + rh * c0.x, 0.f);
    res.y = fmaxf(x.y + yb.y + rl * a0.y + rh * c0.y, 0.f);
    res.z = fmaxf(x.z + yb.z + rl * a0.z + rh * c0.z, 0.f);
    res.w = fmaxf(x.w + yb.w + rl * a0.w + rh * c0.w, 0.f);
    float* zt = t ? zp : zd;
    *(float4*)(zt + (size_t)d * (3 * OUT_F) + ci * OUT_F + lane * 4) = res;

    size_t row = (size_t)t * NN * 3 + (size_t)d * 3 + ci;
    bf16 h0 = __float2bfloat16(res.x), h1 = __float2bfloat16(res.y);
    bf16 h2 = __float2bfloat16(res.z), h3 = __float2bfloat16(res.w);
    __nv_bfloat162 p0 = __halves2bfloat162(h0, h1);
    __nv_bfloat162 p1 = __halves2bfloat162(h2, h3);
    uint2 st;
    st.x = *(unsigned*)&p0; st.y = *(unsigned*)&p1;
    *(uint2*)(za1 + row * OUT_F + lane * 4) = st;
}

// ------------- attention tail -------------
__global__ void k_wred(const float* __restrict__ T, const float* __restrict__ bp,
                       const float* __restrict__ q, float* __restrict__ wsum) {
    __shared__ float sb[6];
    if (threadIdx.x < 6) sb[threadIdx.x] = 0.f;
    __syncthreads();
    int gw = (blockIdx.x * blockDim.x + threadIdx.x) >> 5;
    int lane = threadIdx.x & 31;
    bool valid = gw < 2 * NN * 3;
    float s = 0.f;
    int t = 0, k = 0;
    if (valid) {
        t = gw / (NN * 3);
        int r = gw - t * NN * 3;
        k = r % 3;
        const float* tp = T + (size_t)gw * OUT_F;
        int j0 = lane * 4;
        float4 tv = *(const float4*)(tp + j0);
        float4 bv = *(const float4*)(bp + j0);
        float4 qv = *(const float4*)(q + j0);
        s = tanhf(tv.x + bv.x) * qv.x + tanhf(tv.y + bv.y) * qv.y
          + tanhf(tv.z + bv.z) * qv.z + tanhf(tv.w + bv.w) * qv.w;
    }
#pragma unroll
    for (int o = 16; o; o >>= 1) s += __shfl_down_sync(0xffffffffu, s, o);
    if (valid && lane == 0) atomicAdd(&sb[t * 3 + k], s);
    __syncthreads();
    if (threadIdx.x < 6 && sb[threadIdx.x] != 0.f) atomicAdd(&wsum[threadIdx.x], sb[threadIdx.x]);
}

__global__ void k_beta(const float* __restrict__ wsum, float* __restrict__ beta,
                       float* __restrict__ outBeta) {
    if (threadIdx.x != 0 || blockIdx.x != 0) return;
    for (int t = 0; t < 2; ++t) {
        float w0 = wsum[t * 3 + 0] / (float)NN;
        float w1 = wsum[t * 3 + 1] / (float)NN;
        float w2 = wsum[t * 3 + 2] / (float)NN;
        float m = fmaxf(w0, fmaxf(w1, w2));
        float e0 = expf(w0 - m), e1 = expf(w1 - m), e2 = expf(w2 - m);
        float inv = 1.f / (e0 + e1 + e2);
        beta[t * 3 + 0] = e0 * inv; outBeta[t * 3 + 0] = e0 * inv;
        beta[t * 3 + 1] = e1 * inv; outBeta[t * 3 + 1] = e1 * inv;
        beta[t * 3 + 2] = e2 * inv; outBeta[t * 3 + 2] = e2 * inv;
    }
}

__global__ void k_combine(const float* __restrict__ zd, const float* __restrict__ zp,
                          const float* __restrict__ beta, float* __restrict__ out) {
    int i = blockIdx.x * blockDim.x + threadIdx.x;
    if (i >= 2 * NN * OUT_F) return;
    int t = i / (NN * OUT_F);
    int r = i - t * NN * OUT_F;
    int n = r / OUT_F, f = r - n * OUT_F;
    const float* z = (t ? zp : zd) + (size_t)n * (3 * OUT_F) + f;
    const float* b = beta + t * 3;
    out[i] = b[0] * z[0] + b[1] * z[OUT_F] + b[2] * z[2 * OUT_F];
}

// ---------------- host orchestration ----------------
extern "C" void kernel_launch(void* const* d_in, const int* in_sizes, int n_in,
                              void* d_out, int out_size) {
    const float* xd  = (const float*)d_in[0];
    const float* xp  = (const float*)d_in[1];
    const int*   src = (const int*)  d_in[2];
    const int*   dst = (const int*)  d_in[3];
    const float* W1  = (const float*)d_in[4];
    const float* b1  = (const float*)d_in[5];
    const float* W2  = (const float*)d_in[6];
    const float* b2  = (const float*)d_in[7];
    const float* Wpm = (const float*)d_in[8];
    const float* bp  = (const float*)d_in[9];
    const float* q   = (const float*)d_in[10];
    float* out = (float*)d_out;

    float *y, *zd, *zp, *rout, *rin, *wsum, *beta, *csrw;
    int *cnts, *cnt, *base, *cur, *csrs;
    bf16 *x1, *x2, *h1, *h2, *za1;
    bf16 *wt1a, *wt1b, *wt2a, *wt2b, *wpa, *wpb;
    cudaGetSymbolAddress((void**)&y,    g_y);
    cudaGetSymbolAddress((void**)&zd,   g_zd);
    cudaGetSymbolAddress((void**)&zp,   g_zp);
    cudaGetSymbolAddress((void**)&rout, g_rout);
    cudaGetSymbolAddress((void**)&rin,  g_rin);
    cudaGetSymbolAddress((void**)&wsum, g_wsum);
    cudaGetSymbolAddress((void**)&beta, g_beta);
    cudaGetSymbolAddress((void**)&cnts, g_cnts);
    cudaGetSymbolAddress((void**)&cnt,  g_cnt);
    cudaGetSymbolAddress((void**)&base, g_base);
    cudaGetSymbolAddress((void**)&cur,  g_cur);
    cudaGetSymbolAddress((void**)&csrs, g_csrs);
    cudaGetSymbolAddress((void**)&csrw, g_csrw);
    cudaGetSymbolAddress((void**)&x1,   g_x1);
    cudaGetSymbolAddress((void**)&x2,   g_x2);
    cudaGetSymbolAddress((void**)&h1,   g_h1);
    cudaGetSymbolAddress((void**)&h2,   g_h2);
    cudaGetSymbolAddress((void**)&za1,  g_za1);
    cudaGetSymbolAddress((void**)&wt1a, g_wt1a);
    cudaGetSymbolAddress((void**)&wt1b, g_wt1b);
    cudaGetSymbolAddress((void**)&wt2a, g_wt2a);
    cudaGetSymbolAddress((void**)&wt2b, g_wt2b);
    cudaGetSymbolAddress((void**)&wpa,  g_wpa);
    cudaGetSymbolAddress((void**)&wpb,  g_wpb);

    const int T = 256;
    const int mtiles = (NN + 127) / 128;            // 235
    const int gblocks = (NN * 32 + T - 1) / T;      // 3750
    cudaStream_t sd = g_ss.s;

    // ---- fork side stream: CSR build + W2/Wp transforms + wsum zero ----
    cudaEventRecord(g_ss.fork, 0);
    cudaStreamWaitEvent(sd, g_ss.fork, 0);
    k_zeroi2<<<(12 * NN + T - 1) / T, T, 0, sd>>>(cnts, cnt, 12 * NN);
    k_hist2<<<(12 * EE + T - 1) / T, T, 0, sd>>>(src, dst, cnts, cnt);
    k_prep<<<(12 * NN + T - 1) / T, T, 0, sd>>>(cnts, cnt, rout, rin);
    k_scan<<<12, 1024, 0, sd>>>(cnt, base, cur);
    k_fill<<<(12 * EE + T - 1) / T, T, 0, sd>>>(src, dst, rout, cur, csrs, csrw);
    k_wts<<<dim3(OUT_F / 32, HID_F / 32, 12), dim3(32, 8), 0, sd>>>(W2, wt2a, wt2b, HID_F, OUT_F);
    k_wts1<<<dim3(OUT_F / 32, OUT_F / 32), dim3(32, 8), 0, sd>>>(Wpm, wpa, wpb, OUT_F, OUT_F);
    k_zero<<<1, 32, 0, sd>>>(wsum, 8);
    cudaEventRecord(g_ss.join, sd);

    // ---- main stream: splits + W1 transform + layer-1 GEMM (overlaps side) ----
    k_split<<<(NN * IN_F / 4 + T - 1) / T, T>>>(xd, x1, x2, NN * IN_F / 4);
    k_split<<<(NN * IN_F / 4 + T - 1) / T, T>>>(xp, x1 + (size_t)NN * IN_F,
                                                x2 + (size_t)NN * IN_F, NN * IN_F / 4);
    k_wts<<<dim3(HID_F / 32, IN_F / 32, 12), dim3(32, 8)>>>(W1, wt1a, wt1b, IN_F, HID_F);

    k_mma<IN_F, HID_F, 0, 3><<<dim3(12 * (HID_F / 128), mtiles), 256>>>(
        x1, x2, wt1a, wt1b, y, NN);

    // join: gather needs CSR
    cudaStreamWaitEvent(0, g_ss.join, 0);

    // gather layer 1
    k_gag1<<<dim3(gblocks, 6), T>>>(y, csrs, csrw, base, cnt, rin, b1, h1, h2);

    // ALL 12 layer-2 GEMMs
    k_mma<HID_F, OUT_F, 1, 3><<<dim3(12, mtiles), 256>>>(h1, h2, wt2a, wt2b, y, NN);

    // gather layer 2 (+ z hi split)
    k_gag2<<<dim3(gblocks, 6), T>>>(y, csrs, csrw, base, cnt, rin, b2, zd, zp, za1);

    // attention GEMM: single-chain bf16 (precision averaged over 30000 rows)
    const int rowsA = 2 * NN * 3;
    k_mma<OUT_F, OUT_F, 0, 1><<<dim3(1, (rowsA + 127) / 128), 256>>>(
        za1, za1, wpa, wpa, y, rowsA);

    k_wred<<<(rowsA * 32 + 255) / 256, 256>>>(y, bp, q, wsum);
    k_beta<<<1, 1>>>(wsum, beta, out + (size_t)2 * NN * OUT_F);
    k_combine<<<(2 * NN * OUT_F + T - 1) / T, T>>>(zd, zp, beta, out);
}

// round 10
// speedup vs baseline: 1.0845x; 1.0067x over previous
#include <cuda_runtime.h>
#include <cuda_bf16.h>
#include <cstdint>

#define NN 30000
#define EE 250000
#define IN_F 512
#define HID_F 256
#define OUT_F 128

typedef unsigned long long u64;
typedef __nv_bfloat16 bf16;

// ---------------- scratch (static device globals; no allocs) ----------------
__device__ float g_y[(size_t)12 * NN * HID_F];
__device__ float g_zd[(size_t)NN * 3 * OUT_F];
__device__ float g_zp[(size_t)NN * 3 * OUT_F];
__device__ float g_rout[12 * NN];
__device__ float g_rin[12 * NN];
__device__ float g_wsum[8];
__device__ float g_beta[8];
__device__ int   g_cnts[12 * NN];
__device__ int   g_cnt[12 * NN];
__device__ int   g_base[12 * NN];
__device__ int   g_cur[12 * NN];
__device__ int   g_csrs[(size_t)12 * EE];
__device__ float g_csrw[(size_t)12 * EE];
__device__ __align__(16) bf16 g_x1[(size_t)2 * NN * IN_F];
__device__ __align__(16) bf16 g_x2[(size_t)2 * NN * IN_F];
__device__ __align__(16) bf16 g_h1[(size_t)6 * NN * HID_F];
__device__ __align__(16) bf16 g_h2[(size_t)6 * NN * HID_F];
__device__ __align__(16) bf16 g_za1[(size_t)2 * NN * 3 * OUT_F];
__device__ __align__(16) bf16 g_wt1a[(size_t)12 * HID_F * IN_F];
__device__ __align__(16) bf16 g_wt1b[(size_t)12 * HID_F * IN_F];
__device__ __align__(16) bf16 g_wt2a[(size_t)12 * OUT_F * HID_F];
__device__ __align__(16) bf16 g_wt2b[(size_t)12 * OUT_F * HID_F];
__device__ __align__(16) bf16 g_wpa[(size_t)OUT_F * OUT_F];
__device__ __align__(16) bf16 g_wpb[(size_t)OUT_F * OUT_F];

__device__ __forceinline__ void fma4(float4& a, float w, const float4 v) {
    a.x += w * v.x; a.y += w * v.y; a.z += w * v.z; a.w += w * v.w;
}
__device__ __forceinline__ int u2cr(int u) {
    int ci = u >> 2;
    int c = (ci == 0) ? 0 : (ci == 1 ? 2 : 3);
    return c * 4 + (u & 3);
}

// ---------------- side-stream handles (created at static init, pre-checkpoint) ---
struct SideStream {
    cudaStream_t s = nullptr;
    cudaEvent_t fork = nullptr, join = nullptr;
    SideStream() {
        cudaStreamCreateWithFlags(&s, cudaStreamNonBlocking);
        cudaEventCreateWithFlags(&fork, cudaEventDisableTiming);
        cudaEventCreateWithFlags(&join, cudaEventDisableTiming);
    }
};
static SideStream g_ss;

// ---------------- utility kernels ----------------
__global__ void k_zero(float* __restrict__ p, int n) {
    int i = blockIdx.x * blockDim.x + threadIdx.x;
    if (i < n) p[i] = 0.f;
}
__global__ void k_zeroi2(int* __restrict__ a, int* __restrict__ b, int n) {
    int i = blockIdx.x * blockDim.x + threadIdx.x;
    if (i < n) { a[i] = 0; b[i] = 0; }
}

__global__ void k_hist2(const int* __restrict__ src, const int* __restrict__ dst,
                        int* __restrict__ cnts, int* __restrict__ cntd) {
    int i = blockIdx.x * blockDim.x + threadIdx.x;
    if (i >= 12 * EE) return;
    int u = i / EE, e = i - u * EE;
    int cr = u2cr(u);
    atomicAdd(&cnts[u * NN + src[(size_t)cr * EE + e]], 1);
    atomicAdd(&cntd[u * NN + dst[(size_t)cr * EE + e]], 1);
}

__global__ void k_prep(const int* __restrict__ cnts, const int* __restrict__ cntd,
                       float* __restrict__ rout, float* __restrict__ rin) {
    int i = blockIdx.x * blockDim.x + threadIdx.x;
    if (i >= 12 * NN) return;
    rout[i] = rsqrtf((float)max(cnts[i], 1));
    rin[i]  = rsqrtf((float)max(cntd[i], 1));
}

// deterministic exclusive scan per u (12 blocks, 1024 threads)
__global__ void k_scan(const int* __restrict__ cnt, int* __restrict__ base,
                       int* __restrict__ cur) {
    __shared__ int ws[32];
    __shared__ int carry;
    int u = blockIdx.x;
    const int* c = cnt + u * NN;
    int* b = base + u * NN;
    int* q = cur + u * NN;
    int lane = threadIdx.x & 31, w = threadIdx.x >> 5;
    if (threadIdx.x == 0) carry = 0;
    __syncthreads();
    for (int off = 0; off < NN; off += 1024) {
        int i = off + threadIdx.x;
        int v = (i < NN) ? c[i] : 0;
        int s = v;
#pragma unroll
        for (int o = 1; o < 32; o <<= 1) {
            int t = __shfl_up_sync(0xffffffffu, s, o);
            if (lane >= o) s += t;
        }
        if (lane == 31) ws[w] = s;
        __syncthreads();
        if (w == 0) {
            int t2 = ws[lane];
#pragma unroll
            for (int o = 1; o < 32; o <<= 1) {
                int t = __shfl_up_sync(0xffffffffu, t2, o);
                if (lane >= o) t2 += t;
            }
            ws[lane] = t2;
        }
        __syncthreads();
        int excl = s - v + (w > 0 ? ws[w - 1] : 0) + carry;
        if (i < NN) { b[i] = excl; q[i] = excl; }
        __syncthreads();
        if (threadIdx.x == 1023) carry = excl + v;
        __syncthreads();
    }
}

__global__ void k_fill(const int* __restrict__ src, const int* __restrict__ dst,
                       const float* __restrict__ rout, int* __restrict__ cur,
                       int* __restrict__ csrs, float* __restrict__ csrw) {
    int i = blockIdx.x * blockDim.x + threadIdx.x;
    if (i >= 12 * EE) return;
    int u = i / EE, e = i - u * EE;
    int cr = u2cr(u);
    int s = src[(size_t)cr * EE + e];
    int d = dst[(size_t)cr * EE + e];
    int pos = atomicAdd(&cur[u * NN + d], 1);
    csrs[(size_t)u * EE + pos] = s;
    csrw[(size_t)u * EE + pos] = rout[u * NN + s];
}

// split fp32 -> bf16 hi/lo
__global__ void k_split(const float* __restrict__ x, bf16* __restrict__ hi,
                        bf16* __restrict__ lo, int n4) {
    int i = blockIdx.x * blockDim.x + threadIdx.x;
    if (i >= n4) return;
    float4 v = ((const float4*)x)[i];
    bf16 h0 = __float2bfloat16(v.x), h1 = __float2bfloat16(v.y);
    bf16 h2 = __float2bfloat16(v.z), h3 = __float2bfloat16(v.w);
    ((__nv_bfloat162*)hi)[2 * i]     = __halves2bfloat162(h0, h1);
    ((__nv_bfloat162*)hi)[2 * i + 1] = __halves2bfloat162(h2, h3);
    bf16 l0 = __float2bfloat16(v.x - __bfloat162float(h0));
    bf16 l1 = __float2bfloat16(v.y - __bfloat162float(h1));
    bf16 l2 = __float2bfloat16(v.z - __bfloat162float(h2));
    bf16 l3 = __float2bfloat16(v.w - __bfloat162float(h3));
    ((__nv_bfloat162*)lo)[2 * i]     = __halves2bfloat162(l0, l1);
    ((__nv_bfloat162*)lo)[2 * i + 1] = __halves2bfloat162(l2, l3);
}

// transpose+split weights
__global__ void k_wts(const float* __restrict__ W, bf16* __restrict__ t1,
                      bf16* __restrict__ t2, int K, int N) {
    __shared__ float tile[32][33];
    int z = blockIdx.z;
    int cz = z >> 2;
    int c = (cz == 0) ? 0 : (cz == 1 ? 2 : 3);
    const float* Wm = W + (size_t)(c * 4 + (z & 3)) * K * N;
    bf16* o1 = t1 + (size_t)z * K * N;
    bf16* o2 = t2 + (size_t)z * K * N;
    int k0 = blockIdx.y * 32, n0 = blockIdx.x * 32;
    for (int r = threadIdx.y; r < 32; r += 8)
        tile[r][threadIdx.x] = Wm[(size_t)(k0 + r) * N + n0 + threadIdx.x];
    __syncthreads();
    for (int r = threadIdx.y; r < 32; r += 8) {
        float v = tile[threadIdx.x][r];
        bf16 h = __float2bfloat16(v);
        size_t o = (size_t)(n0 + r) * K + k0 + threadIdx.x;
        o1[o] = h;
        o2[o] = __float2bfloat16(v - __bfloat162float(h));
    }
}

__global__ void k_wts1(const float* __restrict__ W, bf16* __restrict__ t1,
                       bf16* __restrict__ t2, int K, int N) {
    __shared__ float tile[32][33];
    int k0 = blockIdx.y * 32, n0 = blockIdx.x * 32;
    for (int r = threadIdx.y; r < 32; r += 8)
        tile[r][threadIdx.x] = W[(size_t)(k0 + r) * N + n0 + threadIdx.x];
    __syncthreads();
    for (int r = threadIdx.y; r < 32; r += 8) {
        float v = tile[threadIdx.x][r];
        bf16 h = __float2bfloat16(v);
        size_t o = (size_t)(n0 + r) * K + k0 + threadIdx.x;
        t1[o] = h;
        t2[o] = __float2bfloat16(v - __bfloat162float(h));
    }
}

// ---------------- mma.sync bf16 GEMM, 128x128 tile (R6 winner) ----------------
// CHAINS: 3 = A1B1+A1B2+A2B1, 2 = A1B1+A1B2, 1 = A1B1.
// ATT: 1 = fused attention epilogue (wsum += tanh(c+bp).q), no Y store.
__device__ __forceinline__ void mma16816(float* c, const uint32_t* a, const uint32_t* b) {
    asm volatile("mma.sync.aligned.m16n8k16.row.col.f32.bf16.bf16.f32 "
                 "{%0,%1,%2,%3}, {%4,%5,%6,%7}, {%8,%9}, {%0,%1,%2,%3};"
                 : "+f"(c[0]), "+f"(c[1]), "+f"(c[2]), "+f"(c[3])
                 : "r"(a[0]), "r"(a[1]), "r"(a[2]), "r"(a[3]), "r"(b[0]), "r"(b[1]));
}

template <int KK, int NOUT, int CH, int CHAINS, int ATT>
__global__ void __launch_bounds__(256, 2) k_mma(
    const bf16* __restrict__ A1b, const bf16* __restrict__ A2b,
    const bf16* __restrict__ Bt1, const bf16* __restrict__ Bt2,
    float* __restrict__ Y, int M,
    const float* __restrict__ bp, const float* __restrict__ q,
    float* __restrict__ wsum) {
    __shared__ uint32_t AS[2][2048];   // 128 x 32 bf16
    __shared__ uint32_t BS[2][2048];   // 128 x 32 bf16
    __shared__ float sb[6];

    const int tid = threadIdx.x;
    const int lane = tid & 31;
    const int wid = tid >> 5;
    const int warpM = wid & 3;
    const int warpN = wid >> 2;        // 0..1
    constexpr int NT = NOUT / 128;
    const int u = blockIdx.x / NT;
    const int bn = (blockIdx.x % NT) * 128;
    const int bm = blockIdx.y * 128;

    if (ATT && tid < 6) sb[tid] = 0.f;

    const int aoff = (CH ? (u >> 2) * 2 : 0) + ((u & 3) >> 1);
    const bf16* A1 = A1b + (size_t)aoff * M * KK;
    const bf16* A2 = A2b + (size_t)aoff * M * KK;
    const bf16* B1 = Bt1 + (size_t)u * KK * NOUT;
    const bf16* B2 = Bt2 + (size_t)u * KK * NOUT;
    float* Yp = Y + (size_t)u * M * NOUT;

    // chain order: A1B1, A1B2, A2B1 (first CHAINS used)
    const bf16* APass[3] = {A1, A1, A2};
    const bf16* BPass[3] = {B1, B2, B1};

    constexpr int CPP = KK / 32;
    constexpr int NC = CHAINS * CPP;

    float c[2][8][4];
#pragma unroll
    for (int i = 0; i < 2; ++i)
#pragma unroll
        for (int j = 0; j < 8; ++j)
#pragma unroll
            for (int l = 0; l < 4; ++l) c[i][j][l] = 0.f;

    uint4 va[2], vb[2];
    {
        const bf16* Ag = APass[0];
        const bf16* Bg = BPass[0];
#pragma unroll
        for (int i = 0; i < 2; ++i) {
            int u2 = tid + i * 256;
            int m = u2 >> 2, seg = u2 & 3;
            int gm = bm + m;
            va[i] = make_uint4(0, 0, 0, 0);
            if (gm < M)
                va[i] = *(const uint4*)(Ag + (size_t)gm * KK + (seg >> 1) * 16 + (seg & 1) * 8);
            int n = u2 >> 2;
            vb[i] = *(const uint4*)(Bg + (size_t)(bn + n) * KK + (seg >> 1) * 16 + (seg & 1) * 8);
        }
    }

#pragma unroll 1
    for (int g = 0; g < NC; ++g) {
        const int buf = g & 1;
#pragma unroll
        for (int i = 0; i < 2; ++i) {
            int u2 = tid + i * 256;
            int m = u2 >> 2, seg = u2 & 3;
            int kb = seg >> 1, h = seg & 1;
            int r = ((m >> 3) & 1) + 2 * h;
            int Lb = (((m & 7) * 4) + seg * 8) & 31;
            int W = ((kb * 8 + (m >> 4)) * 4 + r) * 32 + Lb;
            *(uint4*)&AS[buf][W] = va[i];
            int n = m;
            int Wb = ((kb * 16 + (n >> 3)) * 2 + h) * 32 + Lb;
            *(uint4*)&BS[buf][Wb] = vb[i];
        }
        __syncthreads();

        if (g + 1 < NC) {
            int pass = (g + 1) / CPP, kc = (g + 1) % CPP;
            const bf16* Ag = APass[pass];
            const bf16* Bg = BPass[pass];
            int koff = kc * 32;
#pragma unroll
            for (int i = 0; i < 2; ++i) {
                int u2 = tid + i * 256;
                int m = u2 >> 2, seg = u2 & 3;
                int gm = bm + m;
                va[i] = make_uint4(0, 0, 0, 0);
                if (gm < M)
                    va[i] = *(const uint4*)(Ag + (size_t)gm * KK + koff +
                                            (seg >> 1) * 16 + (seg & 1) * 8);
                vb[i] = *(const uint4*)(Bg + (size_t)(bn + m) * KK + koff +
                                        (seg >> 1) * 16 + (seg & 1) * 8);
            }
        }

#pragma unroll
        for (int kb = 0; kb < 2; ++kb) {
            uint32_t a[2][4], b[8][2];
#pragma unroll
            for (int mbl = 0; mbl < 2; ++mbl) {
                int mb = warpM * 2 + mbl;
#pragma unroll
                for (int r = 0; r < 4; ++r) {
                    int Lr = (lane + (kb * 2 + (r >> 1)) * 8) & 31;
                    a[mbl][r] = AS[buf][((kb * 8 + mb) * 4 + r) * 32 + Lr];
                }
            }
#pragma unroll
            for (int nbl = 0; nbl < 8; ++nbl) {
                int nb = warpN * 8 + nbl;
#pragma unroll
                for (int h = 0; h < 2; ++h) {
                    int Lr = (lane + (kb * 2 + h) * 8) & 31;
                    b[nbl][h] = BS[buf][((kb * 16 + nb) * 2 + h) * 32 + Lr];
                }
            }
#pragma unroll
            for (int mbl = 0; mbl < 2; ++mbl)
#pragma unroll
                for (int nbl = 0; nbl < 8; ++nbl)
                    mma16816(c[mbl][nbl], a[mbl], b[nbl]);
        }
        __syncthreads();
    }

    if (ATT) {
        // fused attention reduction: wsum[t*3+k] += tanh(c + bp).q per row
        float s[2][2] = {{0.f, 0.f}, {0.f, 0.f}};
#pragma unroll
        for (int mbl = 0; mbl < 2; ++mbl)
#pragma unroll
            for (int nbl = 0; nbl < 8; ++nbl) {
                int ncol = warpN * 64 + nbl * 8 + (lane & 3) * 2;
                float bp0 = __ldg(bp + ncol), bp1 = __ldg(bp + ncol + 1);
                float q0 = __ldg(q + ncol), q1 = __ldg(q + ncol + 1);
                s[mbl][0] += tanhf(c[mbl][nbl][0] + bp0) * q0
                           + tanhf(c[mbl][nbl][1] + bp1) * q1;
                s[mbl][1] += tanhf(c[mbl][nbl][2] + bp0) * q0
                           + tanhf(c[mbl][nbl][3] + bp1) * q1;
            }
#pragma unroll
        for (int mbl = 0; mbl < 2; ++mbl)
#pragma unroll
            for (int h2 = 0; h2 < 2; ++h2) {
                float v = s[mbl][h2];
                v += __shfl_xor_sync(0xffffffffu, v, 1);
                v += __shfl_xor_sync(0xffffffffu, v, 2);
                if ((lane & 3) == 0) {
                    int grow = bm + warpM * 32 + mbl * 16 + h2 * 8 + (lane >> 2);
                    if (grow < M) {
                        int t = (grow >= NN * 3) ? 1 : 0;
                        int k = grow % 3;
                        atomicAdd(&sb[t * 3 + k], v);
                    }
                }
            }
        __syncthreads();
        if (tid < 6) atomicAdd(&wsum[tid], sb[tid]);
    } else {
#pragma unroll
        for (int mbl = 0; mbl < 2; ++mbl) {
            int mrow = bm + warpM * 32 + mbl * 16 + (lane >> 2);
#pragma unroll
            for (int nbl = 0; nbl < 8; ++nbl) {
                int ncol = bn + warpN * 64 + nbl * 8 + (lane & 3) * 2;
                float* base = Yp + (size_t)mrow * NOUT + ncol;
                if (mrow < M)
                    *(float2*)base = make_float2(c[mbl][nbl][0], c[mbl][nbl][1]);
                if (mrow + 8 < M)
                    *(float2*)(base + (size_t)8 * NOUT) =
                        make_float2(c[mbl][nbl][2], c[mbl][nbl][3]);
            }
        }
    }
}

// --------- fused gather layer1 ---------
__global__ void __launch_bounds__(256) k_gag1(
    const float* __restrict__ y,
    const int* __restrict__ csrs, const float* __restrict__ csrw,
    const int* __restrict__ base, const int* __restrict__ cnt,
    const float* __restrict__ rin, const float* __restrict__ b1,
    bf16* __restrict__ h1, bf16* __restrict__ h2) {
    int gw = (blockIdx.x * blockDim.x + threadIdx.x) >> 5;
    if (gw >= NN) return;
    int lane = threadIdx.x & 31;
    int d = gw;
    int by = blockIdx.y;
    int ci = by >> 1, t = by & 1;
    int uLo = ci * 4 + t, uHi = uLo + 2;
    int c = (ci == 0) ? 0 : (ci == 1 ? 2 : 3);
    const float* yLo = y + (size_t)uLo * NN * HID_F;
    const float* yHi = y + (size_t)uHi * NN * HID_F;
    const float* bLo = b1 + (c * 4 + t) * HID_F;
    const float* bHi = b1 + (c * 4 + t + 2) * HID_F;

    float4 a0 = make_float4(0, 0, 0, 0), a1 = a0, c0 = a0, c1 = a0;
    {
        int b = base[uLo * NN + d], n = cnt[uLo * NN + d];
        const int* cs = csrs + (size_t)uLo * EE;
        const float* cw = csrw + (size_t)uLo * EE;
        for (int i = 0; i < n; ++i) {
            int s = cs[b + i];
            float w = cw[b + i];
            const float4* r = (const float4*)(yLo + (size_t)s * HID_F);
            fma4(a0, w, r[lane]);
            fma4(a1, w, r[32 + lane]);
        }
    }
    {
        int b = base[uHi * NN + d], n = cnt[uHi * NN + d];
        const int* cs = csrs + (size_t)uHi * EE;
        const float* cw = csrw + (size_t)uHi * EE;
        for (int i = 0; i < n; ++i) {
            int s = cs[b + i];
            float w = cw[b + i];
            const float4* r = (const float4*)(yHi + (size_t)s * HID_F);
            fma4(c0, w, r[lane]);
            fma4(c1, w, r[32 + lane]);
        }
    }
    float rl = rin[uLo * NN + d], rh = rin[uHi * NN + d];
    bf16* o1 = h1 + (size_t)by * NN * HID_F;
    bf16* o2 = h2 + (size_t)by * NN * HID_F;
#pragma unroll
    for (int ch = 0; ch < 2; ++ch) {
        float4 A = ch ? a1 : a0, C = ch ? c1 : c0;
        float4 x = ((const float4*)bLo)[ch * 32 + lane];
        float4 yb = ((const float4*)bHi)[ch * 32 + lane];
        float r0 = fmaxf(x.x + yb.x + rl * A.x + rh * C.x, 0.f);
        float r1 = fmaxf(x.y + yb.y + rl * A.y + rh * C.y, 0.f);
        float r2 = fmaxf(x.z + yb.z + rl * A.z + rh * C.z, 0.f);
        float r3 = fmaxf(x.w + yb.w + rl * A.w + rh * C.w, 0.f);
        bf16 h0 = __float2bfloat16(r0), hh1 = __float2bfloat16(r1);
        bf16 h2v = __float2bfloat16(r2), h3 = __float2bfloat16(r3);
        __nv_bfloat162 p0 = __halves2bfloat162(h0, hh1);
        __nv_bfloat162 p1 = __halves2bfloat162(h2v, h3);
        uint2 st;
        st.x = *(unsigned*)&p0; st.y = *(unsigned*)&p1;
        size_t off = (size_t)d * HID_F + ch * 128 + lane * 4;
        *(uint2*)(o1 + off) = st;
        bf16 l0 = __float2bfloat16(r0 - __bfloat162float(h0));
        bf16 l1 = __float2bfloat16(r1 - __bfloat162float(hh1));
        bf16 l2 = __float2bfloat16(r2 - __bfloat162float(h2v));
        bf16 l3 = __float2bfloat16(r3 - __bfloat162float(h3));
        p0 = __halves2bfloat162(l0, l1);
        p1 = __halves2bfloat162(l2, l3);
        st.x = *(unsigned*)&p0; st.y = *(unsigned*)&p1;
        *(uint2*)(o2 + off) = st;
    }
}

// --------- fused gather layer2 + z hi-split (za1 only) ---------
__global__ void __launch_bounds__(256) k_gag2(
    const float* __restrict__ y,
    const int* __restrict__ csrs, const float* __restrict__ csrw,
    const int* __restrict__ base, const int* __restrict__ cnt,
    const float* __restrict__ rin, const float* __restrict__ b2,
    float* __restrict__ zd, float* __restrict__ zp,
    bf16* __restrict__ za1) {
    int gw = (blockIdx.x * blockDim.x + threadIdx.x) >> 5;
    if (gw >= NN) return;
    int lane = threadIdx.x & 31;
    int d = gw;
    int by = blockIdx.y;
    int ci = by >> 1, t = by & 1;
    int uLo = ci * 4 + t, uHi = uLo + 2;
    int c = (ci == 0) ? 0 : (ci == 1 ? 2 : 3);
    const float* yLo = y + (size_t)uLo * NN * OUT_F;
    const float* yHi = y + (size_t)uHi * NN * OUT_F;
    const float* bLo = b2 + (c * 4 + t) * OUT_F;
    const float* bHi = b2 + (c * 4 + t + 2) * OUT_F;

    float4 a0 = make_float4(0, 0, 0, 0), c0 = a0;
    {
        int b = base[uLo * NN + d], n = cnt[uLo * NN + d];
        const int* cs = csrs + (size_t)uLo * EE;
        const float* cw = csrw + (size_t)uLo * EE;
        for (int i = 0; i < n; ++i)
            fma4(a0, cw[b + i], ((const float4*)(yLo + (size_t)cs[b + i] * OUT_F))[lane]);
    }
    {
        int b = base[uHi * NN + d], n = cnt[uHi * NN + d];
        const int* cs = csrs + (size_t)uHi * EE;
        const float* cw = csrw + (size_t)uHi * EE;
        for (int i = 0; i < n; ++i)
            fma4(c0, cw[b + i], ((const float4*)(yHi + (size_t)cs[b + i] * OUT_F))[lane]);
    }
    float rl = rin[uLo * NN + d], rh = rin[uHi * NN + d];
    float4 x = ((const float4*)bLo)[lane], yb = ((const float4*)bHi)[lane];
    float4 res;
    res.x = fmaxf(x.x + yb.x + rl * a0.x + rh * c0.x, 0.f);
    res.y = fmaxf(x.y + yb.y + rl * a0.y + rh * c0.y, 0.f);
    res.z = fmaxf(x.z + yb.z + rl * a0.z + rh * c0.z, 0.f);
    res.w = fmaxf(x.w + yb.w + rl * a0.w + rh * c0.w, 0.f);
    float* zt = t ? zp : zd;
    *(float4*)(zt + (size_t)d * (3 * OUT_F) + ci * OUT_F + lane * 4) = res;

    size_t row = (size_t)t * NN * 3 + (size_t)d * 3 + ci;
    bf16 h0 = __float2bfloat16(res.x), h1 = __float2bfloat16(res.y);
    bf16 h2 = __float2bfloat16(res.z), h3 = __float2bfloat16(res.w);
    __nv_bfloat162 p0 = __halves2bfloat162(h0, h1);
    __nv_bfloat162 p1 = __halves2bfloat162(h2, h3);
    uint2 st;
    st.x = *(unsigned*)&p0; st.y = *(unsigned*)&p1;
    *(uint2*)(za1 + row * OUT_F + lane * 4) = st;
}

// ------------- attention tail -------------
__global__ void k_beta(const float* __restrict__ wsum, float* __restrict__ beta,
                       float* __restrict__ outBeta) {
    if (threadIdx.x != 0 || blockIdx.x != 0) return;
    for (int t = 0; t < 2; ++t) {
        float w0 = wsum[t * 3 + 0] / (float)NN;
        float w1 = wsum[t * 3 + 1] / (float)NN;
        float w2 = wsum[t * 3 + 2] / (float)NN;
        float m = fmaxf(w0, fmaxf(w1, w2));
        float e0 = expf(w0 - m), e1 = expf(w1 - m), e2 = expf(w2 - m);
        float inv = 1.f / (e0 + e1 + e2);
        beta[t * 3 + 0] = e0 * inv; outBeta[t * 3 + 0] = e0 * inv;
        beta[t * 3 + 1] = e1 * inv; outBeta[t * 3 + 1] = e1 * inv;
        beta[t * 3 + 2] = e2 * inv; outBeta[t * 3 + 2] = e2 * inv;
    }
}

__global__ void k_combine(const float* __restrict__ zd, const float* __restrict__ zp,
                          const float* __restrict__ beta, float* __restrict__ out) {
    int i = blockIdx.x * blockDim.x + threadIdx.x;
    if (i >= 2 * NN * OUT_F) return;
    int t = i / (NN * OUT_F);
    int r = i - t * NN * OUT_F;
    int n = r / OUT_F, f = r - n * OUT_F;
    const float* z = (t ? zp : zd) + (size_t)n * (3 * OUT_F) + f;
    const float* b = beta + t * 3;
    out[i] = b[0] * z[0] + b[1] * z[OUT_F] + b[2] * z[2 * OUT_F];
}

// ---------------- host orchestration ----------------
extern "C" void kernel_launch(void* const* d_in, const int* in_sizes, int n_in,
                              void* d_out, int out_size) {
    const float* xd  = (const float*)d_in[0];
    const float* xp  = (const float*)d_in[1];
    const int*   src = (const int*)  d_in[2];
    const int*   dst = (const int*)  d_in[3];
    const float* W1  = (const float*)d_in[4];
    const float* b1  = (const float*)d_in[5];
    const float* W2  = (const float*)d_in[6];
    const float* b2  = (const float*)d_in[7];
    const float* Wpm = (const float*)d_in[8];
    const float* bp  = (const float*)d_in[9];
    const float* q   = (const float*)d_in[10];
    float* out = (float*)d_out;

    float *y, *zd, *zp, *rout, *rin, *wsum, *beta, *csrw;
    int *cnts, *cnt, *base, *cur, *csrs;
    bf16 *x1, *x2, *h1, *h2, *za1;
    bf16 *wt1a, *wt1b, *wt2a, *wt2b, *wpa, *wpb;
    cudaGetSymbolAddress((void**)&y,    g_y);
    cudaGetSymbolAddress((void**)&zd,   g_zd);
    cudaGetSymbolAddress((void**)&zp,   g_zp);
    cudaGetSymbolAddress((void**)&rout, g_rout);
    cudaGetSymbolAddress((void**)&rin,  g_rin);
    cudaGetSymbolAddress((void**)&wsum, g_wsum);
    cudaGetSymbolAddress((void**)&beta, g_beta);
    cudaGetSymbolAddress((void**)&cnts, g_cnts);
    cudaGetSymbolAddress((void**)&cnt,  g_cnt);
    cudaGetSymbolAddress((void**)&base, g_base);
    cudaGetSymbolAddress((void**)&cur,  g_cur);
    cudaGetSymbolAddress((void**)&csrs, g_csrs);
    cudaGetSymbolAddress((void**)&csrw, g_csrw);
    cudaGetSymbolAddress((void**)&x1,   g_x1);
    cudaGetSymbolAddress((void**)&x2,   g_x2);
    cudaGetSymbolAddress((void**)&h1,   g_h1);
    cudaGetSymbolAddress((void**)&h2,   g_h2);
    cudaGetSymbolAddress((void**)&za1,  g_za1);
    cudaGetSymbolAddress((void**)&wt1a, g_wt1a);
    cudaGetSymbolAddress((void**)&wt1b, g_wt1b);
    cudaGetSymbolAddress((void**)&wt2a, g_wt2a);
    cudaGetSymbolAddress((void**)&wt2b, g_wt2b);
    cudaGetSymbolAddress((void**)&wpa,  g_wpa);
    cudaGetSymbolAddress((void**)&wpb,  g_wpb);

    const int T = 256;
    const int mtiles = (NN + 127) / 128;            // 235
    const int gblocks = (NN * 32 + T - 1) / T;      // 3750
    cudaStream_t sd = g_ss.s;

    // ---- fork side stream: CSR build + W2/Wp transforms + wsum zero ----
    cudaEventRecord(g_ss.fork, 0);
    cudaStreamWaitEvent(sd, g_ss.fork, 0);
    k_zeroi2<<<(12 * NN + T - 1) / T, T, 0, sd>>>(cnts, cnt, 12 * NN);
    k_hist2<<<(12 * EE + T - 1) / T, T, 0, sd>>>(src, dst, cnts, cnt);
    k_prep<<<(12 * NN + T - 1) / T, T, 0, sd>>>(cnts, cnt, rout, rin);
    k_scan<<<12, 1024, 0, sd>>>(cnt, base, cur);
    k_fill<<<(12 * EE + T - 1) / T, T, 0, sd>>>(src, dst, rout, cur, csrs, csrw);
    k_wts<<<dim3(OUT_F / 32, HID_F / 32, 12), dim3(32, 8), 0, sd>>>(W2, wt2a, wt2b, HID_F, OUT_F);
    k_wts1<<<dim3(OUT_F / 32, OUT_F / 32), dim3(32, 8), 0, sd>>>(Wpm, wpa, wpb, OUT_F, OUT_F);
    k_zero<<<1, 32, 0, sd>>>(wsum, 8);
    cudaEventRecord(g_ss.join, sd);

    // ---- main stream: splits + W1 transform + layer-1 GEMM (overlaps side) ----
    k_split<<<(NN * IN_F / 4 + T - 1) / T, T>>>(xd, x1, x2, NN * IN_F / 4);
    k_split<<<(NN * IN_F / 4 + T - 1) / T, T>>>(xp, x1 + (size_t)NN * IN_F,
                                                x2 + (size_t)NN * IN_F, NN * IN_F / 4);
    k_wts<<<dim3(HID_F / 32, IN_F / 32, 12), dim3(32, 8)>>>(W1, wt1a, wt1b, IN_F, HID_F);

    k_mma<IN_F, HID_F, 0, 3, 0><<<dim3(12 * (HID_F / 128), mtiles), 256>>>(
        x1, x2, wt1a, wt1b, y, NN, nullptr, nullptr, nullptr);

    // join: gather needs CSR
    cudaStreamWaitEvent(0, g_ss.join, 0);

    // gather layer 1
    k_gag1<<<dim3(gblocks, 6), T>>>(y, csrs, csrw, base, cnt, rin, b1, h1, h2);

    // ALL 12 layer-2 GEMMs
    k_mma<HID_F, OUT_F, 1, 3, 0><<<dim3(12, mtiles), 256>>>(
        h1, h2, wt2a, wt2b, y, NN, nullptr, nullptr, nullptr);

    // gather layer 2 (+ z hi split)
    k_gag2<<<dim3(gblocks, 6), T>>>(y, csrs, csrw, base, cnt, rin, b2, zd, zp, za1);

    // attention GEMM: 2-chain (exact Wp via hi+lo) + fused tanh/q reduction
    const int rowsA = 2 * NN * 3;
    k_mma<OUT_F, OUT_F, 0, 2, 1><<<dim3(1, (rowsA + 127) / 128), 256>>>(
        za1, za1, wpa, wpb, nullptr, rowsA, bp, q, wsum);

    k_beta<<<1, 1>>>(wsum, beta, out + (size_t)2 * NN * OUT_F);
    k_combine<<<(2 * NN * OUT_F + T - 1) / T, T>>>(zd, zp, beta, out);
}

// round 11
// speedup vs baseline: 1.0914x; 1.0064x over previous
#include <cuda_runtime.h>
#include <cuda_bf16.h>
#include <cstdint>

#define NN 30000
#define EE 250000
#define IN_F 512
#define HID_F 256
#define OUT_F 128

typedef unsigned long long u64;
typedef __nv_bfloat16 bf16;

// ---------------- scratch (static device globals; no allocs) ----------------
__device__ float g_y[(size_t)12 * NN * HID_F];    // layer-1 GEMM outputs
__device__ float g_y2[(size_t)12 * NN * OUT_F];   // layer-2 GEMM outputs (separate: overlap safety)
__device__ float g_zd[(size_t)NN * 3 * OUT_F];
__device__ float g_zp[(size_t)NN * 3 * OUT_F];
__device__ float g_rout[12 * NN];
__device__ float g_rin[12 * NN];
__device__ float g_wsum[8];
__device__ float g_beta[8];
__device__ int   g_cnts[12 * NN];
__device__ int   g_cnt[12 * NN];
__device__ int   g_base[12 * NN];
__device__ int   g_cur[12 * NN];
__device__ int   g_csrs[(size_t)12 * EE];
__device__ float g_csrw[(size_t)12 * EE];
__device__ __align__(16) bf16 g_x1[(size_t)2 * NN * IN_F];
__device__ __align__(16) bf16 g_x2[(size_t)2 * NN * IN_F];
__device__ __align__(16) bf16 g_h1[(size_t)6 * NN * HID_F];
__device__ __align__(16) bf16 g_h2[(size_t)6 * NN * HID_F];
__device__ __align__(16) bf16 g_za1[(size_t)2 * NN * 3 * OUT_F];
__device__ __align__(16) bf16 g_wt1a[(size_t)12 * HID_F * IN_F];
__device__ __align__(16) bf16 g_wt1b[(size_t)12 * HID_F * IN_F];
__device__ __align__(16) bf16 g_wt2a[(size_t)12 * OUT_F * HID_F];
__device__ __align__(16) bf16 g_wt2b[(size_t)12 * OUT_F * HID_F];
__device__ __align__(16) bf16 g_wpa[(size_t)OUT_F * OUT_F];
__device__ __align__(16) bf16 g_wpb[(size_t)OUT_F * OUT_F];

__device__ __forceinline__ void fma4(float4& a, float w, const float4 v) {
    a.x += w * v.x; a.y += w * v.y; a.z += w * v.z; a.w += w * v.w;
}
__device__ __forceinline__ int u2cr(int u) {
    int ci = u >> 2;
    int c = (ci == 0) ? 0 : (ci == 1 ? 2 : 3);
    return c * 4 + (u & 3);
}

// ---------------- stream handles (created at static init, pre-checkpoint) ----
struct Streams {
    cudaStream_t side = nullptr;
    cudaStream_t sc[3] = {nullptr, nullptr, nullptr};
    cudaEvent_t fork = nullptr, join = nullptr;
    cudaEvent_t e1[3] = {nullptr, nullptr, nullptr};
    cudaEvent_t ec[3] = {nullptr, nullptr, nullptr};
    Streams() {
        cudaStreamCreateWithFlags(&side, cudaStreamNonBlocking);
        cudaEventCreateWithFlags(&fork, cudaEventDisableTiming);
        cudaEventCreateWithFlags(&join, cudaEventDisableTiming);
        for (int c = 0; c < 3; ++c) {
            cudaStreamCreateWithFlags(&sc[c], cudaStreamNonBlocking);
            cudaEventCreateWithFlags(&e1[c], cudaEventDisableTiming);
            cudaEventCreateWithFlags(&ec[c], cudaEventDisableTiming);
        }
    }
};
static Streams g_ss;

// ---------------- utility kernels ----------------
__global__ void k_zero(float* __restrict__ p, int n) {
    int i = blockIdx.x * blockDim.x + threadIdx.x;
    if (i < n) p[i] = 0.f;
}
__global__ void k_zeroi2(int* __restrict__ a, int* __restrict__ b, int n) {
    int i = blockIdx.x * blockDim.x + threadIdx.x;
    if (i < n) { a[i] = 0; b[i] = 0; }
}

__global__ void k_hist2(const int* __restrict__ src, const int* __restrict__ dst,
                        int* __restrict__ cnts, int* __restrict__ cntd) {
    int i = blockIdx.x * blockDim.x + threadIdx.x;
    if (i >= 12 * EE) return;
    int u = i / EE, e = i - u * EE;
    int cr = u2cr(u);
    atomicAdd(&cnts[u * NN + src[(size_t)cr * EE + e]], 1);
    atomicAdd(&cntd[u * NN + dst[(size_t)cr * EE + e]], 1);
}

__global__ void k_prep(const int* __restrict__ cnts, const int* __restrict__ cntd,
                       float* __restrict__ rout, float* __restrict__ rin) {
    int i = blockIdx.x * blockDim.x + threadIdx.x;
    if (i >= 12 * NN) return;
    rout[i] = rsqrtf((float)max(cnts[i], 1));
    rin[i]  = rsqrtf((float)max(cntd[i], 1));
}

// deterministic exclusive scan per u (12 blocks, 1024 threads)
__global__ void k_scan(const int* __restrict__ cnt, int* __restrict__ base,
                       int* __restrict__ cur) {
    __shared__ int ws[32];
    __shared__ int carry;
    int u = blockIdx.x;
    const int* c = cnt + u * NN;
    int* b = base + u * NN;
    int* q = cur + u * NN;
    int lane = threadIdx.x & 31, w = threadIdx.x >> 5;
    if (threadIdx.x == 0) carry = 0;
    __syncthreads();
    for (int off = 0; off < NN; off += 1024) {
        int i = off + threadIdx.x;
        int v = (i < NN) ? c[i] : 0;
        int s = v;
#pragma unroll
        for (int o = 1; o < 32; o <<= 1) {
            int t = __shfl_up_sync(0xffffffffu, s, o);
            if (lane >= o) s += t;
        }
        if (lane == 31) ws[w] = s;
        __syncthreads();
        if (w == 0) {
            int t2 = ws[lane];
#pragma unroll
            for (int o = 1; o < 32; o <<= 1) {
                int t = __shfl_up_sync(0xffffffffu, t2, o);
                if (lane >= o) t2 += t;
            }
            ws[lane] = t2;
        }
        __syncthreads();
        int excl = s - v + (w > 0 ? ws[w - 1] : 0) + carry;
        if (i < NN) { b[i] = excl; q[i] = excl; }
        __syncthreads();
        if (threadIdx.x == 1023) carry = excl + v;
        __syncthreads();
    }
}

__global__ void k_fill(const int* __restrict__ src, const int* __restrict__ dst,
                       const float* __restrict__ rout, int* __restrict__ cur,
                       int* __restrict__ csrs, float* __restrict__ csrw) {
    int i = blockIdx.x * blockDim.x + threadIdx.x;
    if (i >= 12 * EE) return;
    int u = i / EE, e = i - u * EE;
    int cr = u2cr(u);
    int s = src[(size_t)cr * EE + e];
    int d = dst[(size_t)cr * EE + e];
    int pos = atomicAdd(&cur[u * NN + d], 1);
    csrs[(size_t)u * EE + pos] = s;
    csrw[(size_t)u * EE + pos] = rout[u * NN + s];
}

// split fp32 -> bf16 hi/lo
__global__ void k_split(const float* __restrict__ x, bf16* __restrict__ hi,
                        bf16* __restrict__ lo, int n4) {
    int i = blockIdx.x * blockDim.x + threadIdx.x;
    if (i >= n4) return;
    float4 v = ((const float4*)x)[i];
    bf16 h0 = __float2bfloat16(v.x), h1 = __float2bfloat16(v.y);
    bf16 h2 = __float2bfloat16(v.z), h3 = __float2bfloat16(v.w);
    ((__nv_bfloat162*)hi)[2 * i]     = __halves2bfloat162(h0, h1);
    ((__nv_bfloat162*)hi)[2 * i + 1] = __halves2bfloat162(h2, h3);
    bf16 l0 = __float2bfloat16(v.x - __bfloat162float(h0));
    bf16 l1 = __float2bfloat16(v.y - __bfloat162float(h1));
    bf16 l2 = __float2bfloat16(v.z - __bfloat162float(h2));
    bf16 l3 = __float2bfloat16(v.w - __bfloat162float(h3));
    ((__nv_bfloat162*)lo)[2 * i]     = __halves2bfloat162(l0, l1);
    ((__nv_bfloat162*)lo)[2 * i + 1] = __halves2bfloat162(l2, l3);
}

// transpose+split weights
__global__ void k_wts(const float* __restrict__ W, bf16* __restrict__ t1,
                      bf16* __restrict__ t2, int K, int N) {
    __shared__ float tile[32][33];
    int z = blockIdx.z;
    int cz = z >> 2;
    int c = (cz == 0) ? 0 : (cz == 1 ? 2 : 3);
    const float* Wm = W + (size_t)(c * 4 + (z & 3)) * K * N;
    bf16* o1 = t1 + (size_t)z * K * N;
    bf16* o2 = t2 + (size_t)z * K * N;
    int k0 = blockIdx.y * 32, n0 = blockIdx.x * 32;
    for (int r = threadIdx.y; r < 32; r += 8)
        tile[r][threadIdx.x] = Wm[(size_t)(k0 + r) * N + n0 + threadIdx.x];
    __syncthreads();
    for (int r = threadIdx.y; r < 32; r += 8) {
        float v = tile[threadIdx.x][r];
        bf16 h = __float2bfloat16(v);
        size_t o = (size_t)(n0 + r) * K + k0 + threadIdx.x;
        o1[o] = h;
        o2[o] = __float2bfloat16(v - __bfloat162float(h));
    }
}

__global__ void k_wts1(const float* __restrict__ W, bf16* __restrict__ t1,
                       bf16* __restrict__ t2, int K, int N) {
    __shared__ float tile[32][33];
    int k0 = blockIdx.y * 32, n0 = blockIdx.x * 32;
    for (int r = threadIdx.y; r < 32; r += 8)
        tile[r][threadIdx.x] = W[(size_t)(k0 + r) * N + n0 + threadIdx.x];
    __syncthreads();
    for (int r = threadIdx.y; r < 32; r += 8) {
        float v = tile[threadIdx.x][r];
        bf16 h = __float2bfloat16(v);
        size_t o = (size_t)(n0 + r) * K + k0 + threadIdx.x;
        t1[o] = h;
        t2[o] = __float2bfloat16(v - __bfloat162float(h));
    }
}

// ---------------- mma.sync bf16 GEMM, 128x128 tile (R6 winner) ----------------
// CHAINS: 3 = A1B1+A1B2+A2B1, 2 = A1B1+A1B2. ATT: fused attention epilogue.
// u0: relation-index offset (channel pipelining).
__device__ __forceinline__ void mma16816(float* c, const uint32_t* a, const uint32_t* b) {
    asm volatile("mma.sync.aligned.m16n8k16.row.col.f32.bf16.bf16.f32 "
                 "{%0,%1,%2,%3}, {%4,%5,%6,%7}, {%8,%9}, {%0,%1,%2,%3};"
                 : "+f"(c[0]), "+f"(c[1]), "+f"(c[2]), "+f"(c[3])
                 : "r"(a[0]), "r"(a[1]), "r"(a[2]), "r"(a[3]), "r"(b[0]), "r"(b[1]));
}

template <int KK, int NOUT, int CH, int CHAINS, int ATT>
__global__ void __launch_bounds__(256, 2) k_mma(
    const bf16* __restrict__ A1b, const bf16* __restrict__ A2b,
    const bf16* __restrict__ Bt1, const bf16* __restrict__ Bt2,
    float* __restrict__ Y, int M, int u0,
    const float* __restrict__ bp, const float* __restrict__ q,
    float* __restrict__ wsum) {
    __shared__ uint32_t AS[2][2048];   // 128 x 32 bf16
    __shared__ uint32_t BS[2][2048];   // 128 x 32 bf16
    __shared__ float sb[6];

    const int tid = threadIdx.x;
    const int lane = tid & 31;
    const int wid = tid >> 5;
    const int warpM = wid & 3;
    const int warpN = wid >> 2;        // 0..1
    constexpr int NT = NOUT / 128;
    const int u = u0 + blockIdx.x / NT;
    const int bn = (blockIdx.x % NT) * 128;
    const int bm = blockIdx.y * 128;

    if (ATT && tid < 6) sb[tid] = 0.f;

    const int aoff = (CH ? (u >> 2) * 2 : 0) + ((u & 3) >> 1);
    const bf16* A1 = A1b + (size_t)aoff * M * KK;
    const bf16* A2 = A2b + (size_t)aoff * M * KK;
    const bf16* B1 = Bt1 + (size_t)u * KK * NOUT;
    const bf16* B2 = Bt2 + (size_t)u * KK * NOUT;
    float* Yp = Y + (size_t)u * M * NOUT;

    const bf16* APass[3] = {A1, A1, A2};
    const bf16* BPass[3] = {B1, B2, B1};

    constexpr int CPP = KK / 32;
    constexpr int NC = CHAINS * CPP;

    float c[2][8][4];
#pragma unroll
    for (int i = 0; i < 2; ++i)
#pragma unroll
        for (int j = 0; j < 8; ++j)
#pragma unroll
            for (int l = 0; l < 4; ++l) c[i][j][l] = 0.f;

    uint4 va[2], vb[2];
    {
        const bf16* Ag = APass[0];
        const bf16* Bg = BPass[0];
#pragma unroll
        for (int i = 0; i < 2; ++i) {
            int u2 = tid + i * 256;
            int m = u2 >> 2, seg = u2 & 3;
            int gm = bm + m;
            va[i] = make_uint4(0, 0, 0, 0);
            if (gm < M)
                va[i] = *(const uint4*)(Ag + (size_t)gm * KK + (seg >> 1) * 16 + (seg & 1) * 8);
            int n = u2 >> 2;
            vb[i] = *(const uint4*)(Bg + (size_t)(bn + n) * KK + (seg >> 1) * 16 + (seg & 1) * 8);
        }
    }

#pragma unroll 1
    for (int g = 0; g < NC; ++g) {
        const int buf = g & 1;
#pragma unroll
        for (int i = 0; i < 2; ++i) {
            int u2 = tid + i * 256;
            int m = u2 >> 2, seg = u2 & 3;
            int kb = seg >> 1, h = seg & 1;
            int r = ((m >> 3) & 1) + 2 * h;
            int Lb = (((m & 7) * 4) + seg * 8) & 31;
            int W = ((kb * 8 + (m >> 4)) * 4 + r) * 32 + Lb;
            *(uint4*)&AS[buf][W] = va[i];
            int n = m;
            int Wb = ((kb * 16 + (n >> 3)) * 2 + h) * 32 + Lb;
            *(uint4*)&BS[buf][Wb] = vb[i];
        }
        __syncthreads();

        if (g + 1 < NC) {
            int pass = (g + 1) / CPP, kc = (g + 1) % CPP;
            const bf16* Ag = APass[pass];
            const bf16* Bg = BPass[pass];
            int koff = kc * 32;
#pragma unroll
            for (int i = 0; i < 2; ++i) {
                int u2 = tid + i * 256;
                int m = u2 >> 2, seg = u2 & 3;
                int gm = bm + m;
                va[i] = make_uint4(0, 0, 0, 0);
                if (gm < M)
                    va[i] = *(const uint4*)(Ag + (size_t)gm * KK + koff +
                                            (seg >> 1) * 16 + (seg & 1) * 8);
                vb[i] = *(const uint4*)(Bg + (size_t)(bn + m) * KK + koff +
                                        (seg >> 1) * 16 + (seg & 1) * 8);
            }
        }

#pragma unroll
        for (int kb = 0; kb < 2; ++kb) {
            uint32_t a[2][4], b[8][2];
#pragma unroll
            for (int mbl = 0; mbl < 2; ++mbl) {
                int mb = warpM * 2 + mbl;
#pragma unroll
                for (int r = 0; r < 4; ++r) {
                    int Lr = (lane + (kb * 2 + (r >> 1)) * 8) & 31;
                    a[mbl][r] = AS[buf][((kb * 8 + mb) * 4 + r) * 32 + Lr];
                }
            }
#pragma unroll
            for (int nbl = 0; nbl < 8; ++nbl) {
                int nb = warpN * 8 + nbl;
#pragma unroll
                for (int h = 0; h < 2; ++h) {
                    int Lr = (lane + (kb * 2 + h) * 8) & 31;
                    b[nbl][h] = BS[buf][((kb * 16 + nb) * 2 + h) * 32 + Lr];
                }
            }
#pragma unroll
            for (int mbl = 0; mbl < 2; ++mbl)
#pragma unroll
                for (int nbl = 0; nbl < 8; ++nbl)
                    mma16816(c[mbl][nbl], a[mbl], b[nbl]);
        }
        __syncthreads();
    }

    if (ATT) {
        float s[2][2] = {{0.f, 0.f}, {0.f, 0.f}};
#pragma unroll
        for (int mbl = 0; mbl < 2; ++mbl)
#pragma unroll
            for (int nbl = 0; nbl < 8; ++nbl) {
                int ncol = warpN * 64 + nbl * 8 + (lane & 3) * 2;
                float bp0 = __ldg(bp + ncol), bp1 = __ldg(bp + ncol + 1);
                float q0 = __ldg(q + ncol), q1 = __ldg(q + ncol + 1);
                s[mbl][0] += tanhf(c[mbl][nbl][0] + bp0) * q0
                           + tanhf(c[mbl][nbl][1] + bp1) * q1;
                s[mbl][1] += tanhf(c[mbl][nbl][2] + bp0) * q0
                           + tanhf(c[mbl][nbl][3] + bp1) * q1;
            }
#pragma unroll
        for (int mbl = 0; mbl < 2; ++mbl)
#pragma unroll
            for (int h2 = 0; h2 < 2; ++h2) {
                float v = s[mbl][h2];
                v += __shfl_xor_sync(0xffffffffu, v, 1);
                v += __shfl_xor_sync(0xffffffffu, v, 2);
                if ((lane & 3) == 0) {
                    int grow = bm + warpM * 32 + mbl * 16 + h2 * 8 + (lane >> 2);
                    if (grow < M) {
                        int t = (grow >= NN * 3) ? 1 : 0;
                        int k = grow % 3;
                        atomicAdd(&sb[t * 3 + k], v);
                    }
                }
            }
        __syncthreads();
        if (tid < 6) atomicAdd(&wsum[tid], sb[tid]);
    } else {
#pragma unroll
        for (int mbl = 0; mbl < 2; ++mbl) {
            int mrow = bm + warpM * 32 + mbl * 16 + (lane >> 2);
#pragma unroll
            for (int nbl = 0; nbl < 8; ++nbl) {
                int ncol = bn + warpN * 64 + nbl * 8 + (lane & 3) * 2;
                float* base = Yp + (size_t)mrow * NOUT + ncol;
                if (mrow < M)
                    *(float2*)base = make_float2(c[mbl][nbl][0], c[mbl][nbl][1]);
                if (mrow + 8 < M)
                    *(float2*)(base + (size_t)8 * NOUT) =
                        make_float2(c[mbl][nbl][2], c[mbl][nbl][3]);
            }
        }
    }
}

// --------- fused gather layer1 (one channel; blockIdx.y = type) ---------
__global__ void __launch_bounds__(256) k_gag1(
    const float* __restrict__ y,
    const int* __restrict__ csrs, const float* __restrict__ csrw,
    const int* __restrict__ base, const int* __restrict__ cnt,
    const float* __restrict__ rin, const float* __restrict__ b1,
    bf16* __restrict__ h1, bf16* __restrict__ h2, int ci) {
    int gw = (blockIdx.x * blockDim.x + threadIdx.x) >> 5;
    if (gw >= NN) return;
    int lane = threadIdx.x & 31;
    int d = gw;
    int t = blockIdx.y;
    int by = ci * 2 + t;
    int uLo = ci * 4 + t, uHi = uLo + 2;
    int c = (ci == 0) ? 0 : (ci == 1 ? 2 : 3);
    const float* yLo = y + (size_t)uLo * NN * HID_F;
    const float* yHi = y + (size_t)uHi * NN * HID_F;
    const float* bLo = b1 + (c * 4 + t) * HID_F;
    const float* bHi = b1 + (c * 4 + t + 2) * HID_F;

    float4 a0 = make_float4(0, 0, 0, 0), a1 = a0, c0 = a0, c1 = a0;
    {
        int b = base[uLo * NN + d], n = cnt[uLo * NN + d];
        const int* cs = csrs + (size_t)uLo * EE;
        const float* cw = csrw + (size_t)uLo * EE;
        for (int i = 0; i < n; ++i) {
            int s = cs[b + i];
            float w = cw[b + i];
            const float4* r = (const float4*)(yLo + (size_t)s * HID_F);
            fma4(a0, w, r[lane]);
            fma4(a1, w, r[32 + lane]);
        }
    }
    {
        int b = base[uHi * NN + d], n = cnt[uHi * NN + d];
        const int* cs = csrs + (size_t)uHi * EE;
        const float* cw = csrw + (size_t)uHi * EE;
        for (int i = 0; i < n; ++i) {
            int s = cs[b + i];
            float w = cw[b + i];
            const float4* r = (const float4*)(yHi + (size_t)s * HID_F);
            fma4(c0, w, r[lane]);
            fma4(c1, w, r[32 + lane]);
        }
    }
    float rl = rin[uLo * NN + d], rh = rin[uHi * NN + d];
    bf16* o1 = h1 + (size_t)by * NN * HID_F;
    bf16* o2 = h2 + (size_t)by * NN * HID_F;
#pragma unroll
    for (int ch = 0; ch < 2; ++ch) {
        float4 A = ch ? a1 : a0, C = ch ? c1 : c0;
        float4 x = ((const float4*)bLo)[ch * 32 + lane];
        float4 yb = ((const float4*)bHi)[ch * 32 + lane];
        float r0 = fmaxf(x.x + yb.x + rl * A.x + rh * C.x, 0.f);
        float r1 = fmaxf(x.y + yb.y + rl * A.y + rh * C.y, 0.f);
        float r2 = fmaxf(x.z + yb.z + rl * A.z + rh * C.z, 0.f);
        float r3 = fmaxf(x.w + yb.w + rl * A.w + rh * C.w, 0.f);
        bf16 h0 = __float2bfloat16(r0), hh1 = __float2bfloat16(r1);
        bf16 h2v = __float2bfloat16(r2), h3 = __float2bfloat16(r3);
        __nv_bfloat162 p0 = __halves2bfloat162(h0, hh1);
        __nv_bfloat162 p1 = __halves2bfloat162(h2v, h3);
        uint2 st;
        st.x = *(unsigned*)&p0; st.y = *(unsigned*)&p1;
        size_t off = (size_t)d * HID_F + ch * 128 + lane * 4;
        *(uint2*)(o1 + off) = st;
        bf16 l0 = __float2bfloat16(r0 - __bfloat162float(h0));
        bf16 l1 = __float2bfloat16(r1 - __bfloat162float(hh1));
        bf16 l2 = __float2bfloat16(r2 - __bfloat162float(h2v));
        bf16 l3 = __float2bfloat16(r3 - __bfloat162float(h3));
        p0 = __halves2bfloat162(l0, l1);
        p1 = __halves2bfloat162(l2, l3);
        st.x = *(unsigned*)&p0; st.y = *(unsigned*)&p1;
        *(uint2*)(o2 + off) = st;
    }
}

// --------- fused gather layer2 + z hi-split (one channel) ---------
__global__ void __launch_bounds__(256) k_gag2(
    const float* __restrict__ y2,
    const int* __restrict__ csrs, const float* __restrict__ csrw,
    const int* __restrict__ base, const int* __restrict__ cnt,
    const float* __restrict__ rin, const float* __restrict__ b2,
    float* __restrict__ zd, float* __restrict__ zp,
    bf16* __restrict__ za1, int ci) {
    int gw = (blockIdx.x * blockDim.x + threadIdx.x) >> 5;
    if (gw >= NN) return;
    int lane = threadIdx.x & 31;
    int d = gw;
    int t = blockIdx.y;
    int uLo = ci * 4 + t, uHi = uLo + 2;
    int c = (ci == 0) ? 0 : (ci == 1 ? 2 : 3);
    const float* yLo = y2 + (size_t)uLo * NN * OUT_F;
    const float* yHi = y2 + (size_t)uHi * NN * OUT_F;
    const float* bLo = b2 + (c * 4 + t) * OUT_F;
    const float* bHi = b2 + (c * 4 + t + 2) * OUT_F;

    float4 a0 = make_float4(0, 0, 0, 0), c0 = a0;
    {
        int b = base[uLo * NN + d], n = cnt[uLo * NN + d];
        const int* cs = csrs + (size_t)uLo * EE;
        const float* cw = csrw + (size_t)uLo * EE;
        for (int i = 0; i < n; ++i)
            fma4(a0, cw[b + i], ((const float4*)(yLo + (size_t)cs[b + i] * OUT_F))[lane]);
    }
    {
        int b = base[uHi * NN + d], n = cnt[uHi * NN + d];
        const int* cs = csrs + (size_t)uHi * EE;
        const float* cw = csrw + (size_t)uHi * EE;
        for (int i = 0; i < n; ++i)
            fma4(c0, cw[b + i], ((const float4*)(yHi + (size_t)cs[b + i] * OUT_F))[lane]);
    }
    float rl = rin[uLo * NN + d], rh = rin[uHi * NN + d];
    float4 x = ((const float4*)bLo)[lane], yb = ((const float4*)bHi)[lane];
    float4 res;
    res.x = fmaxf(x.x + yb.x + rl * a0.x + rh * c0.x, 0.f);
    res.y = fmaxf(x.y + yb.y + rl * a0.y + rh * c0.y, 0.f);
    res.z = fmaxf(x.z + yb.z + rl * a0.z + rh * c0.z, 0.f);
    res.w = fmaxf(x.w + yb.w + rl * a0.w + rh * c0.w, 0.f);
    float* zt = t ? zp : zd;
    *(float4*)(zt + (size_t)d * (3 * OUT_F) + ci * OUT_F + lane * 4) = res;

    size_t row = (size_t)t * NN * 3 + (size_t)d * 3 + ci;
    bf16 h0 = __float2bfloat16(res.x), h1 = __float2bfloat16(res.y);
    bf16 h2 = __float2bfloat16(res.z), h3 = __float2bfloat16(res.w);
    __nv_bfloat162 p0 = __halves2bfloat162(h0, h1);
    __nv_bfloat162 p1 = __halves2bfloat162(h2, h3);
    uint2 st;
    st.x = *(unsigned*)&p0; st.y = *(unsigned*)&p1;
    *(uint2*)(za1 + row * OUT_F + lane * 4) = st;
}

// ------------- attention tail -------------
__global__ void k_beta(const float* __restrict__ wsum, float* __restrict__ beta,
                       float* __restrict__ outBeta) {
    if (threadIdx.x != 0 || blockIdx.x != 0) return;
    for (int t = 0; t < 2; ++t) {
        float w0 = wsum[t * 3 + 0] / (float)NN;
        float w1 = wsum[t * 3 + 1] / (float)NN;
        float w2 = wsum[t * 3 + 2] / (float)NN;
        float m = fmaxf(w0, fmaxf(w1, w2));
        float e0 = expf(w0 - m), e1 = expf(w1 - m), e2 = expf(w2 - m);
        float inv = 1.f / (e0 + e1 + e2);
        beta[t * 3 + 0] = e0 * inv; outBeta[t * 3 + 0] = e0 * inv;
        beta[t * 3 + 1] = e1 * inv; outBeta[t * 3 + 1] = e1 * inv;
        beta[t * 3 + 2] = e2 * inv; outBeta[t * 3 + 2] = e2 * inv;
    }
}

__global__ void k_combine(const float* __restrict__ zd, const float* __restrict__ zp,
                          const float* __restrict__ beta, float* __restrict__ out) {
    int i = blockIdx.x * blockDim.x + threadIdx.x;
    if (i >= 2 * NN * OUT_F) return;
    int t = i / (NN * OUT_F);
    int r = i - t * NN * OUT_F;
    int n = r / OUT_F, f = r - n * OUT_F;
    const float* z = (t ? zp : zd) + (size_t)n * (3 * OUT_F) + f;
    const float* b = beta + t * 3;
    out[i] = b[0] * z[0] + b[1] * z[OUT_F] + b[2] * z[2 * OUT_F];
}

// ---------------- host orchestration ----------------
extern "C" void kernel_launch(void* const* d_in, const int* in_sizes, int n_in,
                              void* d_out, int out_size) {
    const float* xd  = (const float*)d_in[0];
    const float* xp  = (const float*)d_in[1];
    const int*   src = (const int*)  d_in[2];
    const int*   dst = (const int*)  d_in[3];
    const float* W1  = (const float*)d_in[4];
    const float* b1  = (const float*)d_in[5];
    const float* W2  = (const float*)d_in[6];
    const float* b2  = (const float*)d_in[7];
    const float* Wpm = (const float*)d_in[8];
    const float* bp  = (const float*)d_in[9];
    const float* q   = (const float*)d_in[10];
    float* out = (float*)d_out;

    float *y, *y2, *zd, *zp, *rout, *rin, *wsum, *beta, *csrw;
    int *cnts, *cnt, *base, *cur, *csrs;
    bf16 *x1, *x2, *h1, *h2, *za1;
    bf16 *wt1a, *wt1b, *wt2a, *wt2b, *wpa, *wpb;
    cudaGetSymbolAddress((void**)&y,    g_y);
    cudaGetSymbolAddress((void**)&y2,   g_y2);
    cudaGetSymbolAddress((void**)&zd,   g_zd);
    cudaGetSymbolAddress((void**)&zp,   g_zp);
    cudaGetSymbolAddress((void**)&rout, g_rout);
    cudaGetSymbolAddress((void**)&rin,  g_rin);
    cudaGetSymbolAddress((void**)&wsum, g_wsum);
    cudaGetSymbolAddress((void**)&beta, g_beta);
    cudaGetSymbolAddress((void**)&cnts, g_cnts);
    cudaGetSymbolAddress((void**)&cnt,  g_cnt);
    cudaGetSymbolAddress((void**)&base, g_base);
    cudaGetSymbolAddress((void**)&cur,  g_cur);
    cudaGetSymbolAddress((void**)&csrs, g_csrs);
    cudaGetSymbolAddress((void**)&csrw, g_csrw);
    cudaGetSymbolAddress((void**)&x1,   g_x1);
    cudaGetSymbolAddress((void**)&x2,   g_x2);
    cudaGetSymbolAddress((void**)&h1,   g_h1);
    cudaGetSymbolAddress((void**)&h2,   g_h2);
    cudaGetSymbolAddress((void**)&za1,  g_za1);
    cudaGetSymbolAddress((void**)&wt1a, g_wt1a);
    cudaGetSymbolAddress((void**)&wt1b, g_wt1b);
    cudaGetSymbolAddress((void**)&wt2a, g_wt2a);
    cudaGetSymbolAddress((void**)&wt2b, g_wt2b);
    cudaGetSymbolAddress((void**)&wpa,  g_wpa);
    cudaGetSymbolAddress((void**)&wpb,  g_wpb);

    const int T = 256;
    const int mtiles = (NN + 127) / 128;            // 235
    const int gblocks = (NN * 32 + T - 1) / T;      // 3750
    cudaStream_t sd = g_ss.side;

    // ---- fork side stream: CSR build + W2/Wp transforms + wsum zero ----
    cudaEventRecord(g_ss.fork, 0);
    cudaStreamWaitEvent(sd, g_ss.fork, 0);
    k_zeroi2<<<(12 * NN + T - 1) / T, T, 0, sd>>>(cnts, cnt, 12 * NN);
    k_hist2<<<(12 * EE + T - 1) / T, T, 0, sd>>>(src, dst, cnts, cnt);
    k_prep<<<(12 * NN + T - 1) / T, T, 0, sd>>>(cnts, cnt, rout, rin);
    k_scan<<<12, 1024, 0, sd>>>(cnt, base, cur);
    k_fill<<<(12 * EE + T - 1) / T, T, 0, sd>>>(src, dst, rout, cur, csrs, csrw);
    k_wts<<<dim3(OUT_F / 32, HID_F / 32, 12), dim3(32, 8), 0, sd>>>(W2, wt2a, wt2b, HID_F, OUT_F);
    k_wts1<<<dim3(OUT_F / 32, OUT_F / 32), dim3(32, 8), 0, sd>>>(Wpm, wpa, wpb, OUT_F, OUT_F);
    k_zero<<<1, 32, 0, sd>>>(wsum, 8);
    cudaEventRecord(g_ss.join, sd);

    // ---- main stream: splits + W1 transform, then 3 channel GEMM1 launches ----
    k_split<<<(NN * IN_F / 4 + T - 1) / T, T>>>(xd, x1, x2, NN * IN_F / 4);
    k_split<<<(NN * IN_F / 4 + T - 1) / T, T>>>(xp, x1 + (size_t)NN * IN_F,
                                                x2 + (size_t)NN * IN_F, NN * IN_F / 4);
    k_wts<<<dim3(HID_F / 32, IN_F / 32, 12), dim3(32, 8)>>>(W1, wt1a, wt1b, IN_F, HID_F);

    for (int c = 0; c < 3; ++c) {
        k_mma<IN_F, HID_F, 0, 3, 0><<<dim3(4 * (HID_F / 128), mtiles), 256>>>(
            x1, x2, wt1a, wt1b, y, NN, c * 4, nullptr, nullptr, nullptr);
        cudaEventRecord(g_ss.e1[c], 0);
    }

    // ---- per-channel pipelines: gag1 -> GEMM2 -> gag2 on dedicated streams ----
    for (int c = 0; c < 3; ++c) {
        cudaStream_t s = g_ss.sc[c];
        cudaStreamWaitEvent(s, g_ss.e1[c], 0);
        cudaStreamWaitEvent(s, g_ss.join, 0);
        k_gag1<<<dim3(gblocks, 2), T, 0, s>>>(y, csrs, csrw, base, cnt, rin, b1,
                                              h1, h2, c);
        k_mma<HID_F, OUT_F, 1, 3, 0><<<dim3(4, mtiles), 256, 0, s>>>(
            h1, h2, wt2a, wt2b, y2, NN, c * 4, nullptr, nullptr, nullptr);
        k_gag2<<<dim3(gblocks, 2), T, 0, s>>>(y2, csrs, csrw, base, cnt, rin, b2,
                                              zd, zp, za1, c);
        cudaEventRecord(g_ss.ec[c], s);
    }

    // ---- join all channels, then attention + combine on main ----
    for (int c = 0; c < 3; ++c) cudaStreamWaitEvent(0, g_ss.ec[c], 0);

    const int rowsA = 2 * NN * 3;
    k_mma<OUT_F, OUT_F, 0, 2, 1><<<dim3(1, (rowsA + 127) / 128), 256>>>(
        za1, za1, wpa, wpb, nullptr, rowsA, 0, bp, q, wsum);

    k_beta<<<1, 1>>>(wsum, beta, out + (size_t)2 * NN * OUT_F);
    k_combine<<<(2 * NN * OUT_F + T - 1) / T, T>>>(zd, zp, beta, out);
}

// round 12
// speedup vs baseline: 1.1072x; 1.0145x over previous
#include <cuda_runtime.h>
#include <cuda_bf16.h>
#include <cstdint>

#define NN 30000
#define EE 250000
#define IN_F 512
#define HID_F 256
#define OUT_F 128

typedef unsigned long long u64;
typedef __nv_bfloat16 bf16;

// ---------------- scratch (static device globals; no allocs) ----------------
__device__ float g_y[(size_t)12 * NN * HID_F];    // layer-1 GEMM outputs
__device__ float g_y2[(size_t)12 * NN * OUT_F];   // layer-2 GEMM outputs
__device__ float g_zd[(size_t)NN * 3 * OUT_F];
__device__ float g_zp[(size_t)NN * 3 * OUT_F];
__device__ float g_rout[12 * NN];
__device__ float g_rin[12 * NN];
__device__ float g_wsum[8];
__device__ float g_beta[8];
__device__ int   g_cnts[12 * NN];
__device__ int   g_cnt[12 * NN];
__device__ int   g_base[12 * NN];
__device__ int   g_cur[12 * NN];
__device__ int   g_csrs[(size_t)12 * EE];
__device__ float g_csrw[(size_t)12 * EE];
__device__ __align__(16) bf16 g_x1[(size_t)2 * NN * IN_F];
__device__ __align__(16) bf16 g_x2[(size_t)2 * NN * IN_F];
__device__ __align__(16) bf16 g_h1[(size_t)6 * NN * HID_F];
__device__ __align__(16) bf16 g_h2[(size_t)6 * NN * HID_F];
__device__ __align__(16) bf16 g_za1[(size_t)2 * NN * 3 * OUT_F];  // [ci][t][d] rows
__device__ __align__(16) bf16 g_wt1a[(size_t)12 * HID_F * IN_F];
__device__ __align__(16) bf16 g_wt1b[(size_t)12 * HID_F * IN_F];
__device__ __align__(16) bf16 g_wt2a[(size_t)12 * OUT_F * HID_F];
__device__ __align__(16) bf16 g_wt2b[(size_t)12 * OUT_F * HID_F];
__device__ __align__(16) bf16 g_wpa[(size_t)OUT_F * OUT_F];
__device__ __align__(16) bf16 g_wpb[(size_t)OUT_F * OUT_F];

__device__ __forceinline__ void fma4(float4& a, float w, const float4 v) {
    a.x += w * v.x; a.y += w * v.y; a.z += w * v.z; a.w += w * v.w;
}
__device__ __forceinline__ int u2cr(int u) {
    int ci = u >> 2;
    int c = (ci == 0) ? 0 : (ci == 1 ? 2 : 3);
    return c * 4 + (u & 3);
}

// ---------------- stream handles (created at static init, pre-checkpoint) ----
struct Streams {
    cudaStream_t side = nullptr;
    cudaStream_t sc[3] = {nullptr, nullptr, nullptr};
    cudaEvent_t fork = nullptr, join = nullptr, w1e = nullptr;
    cudaEvent_t e1[3] = {nullptr, nullptr, nullptr};
    cudaEvent_t ec[3] = {nullptr, nullptr, nullptr};
    Streams() {
        cudaStreamCreateWithFlags(&side, cudaStreamNonBlocking);
        cudaEventCreateWithFlags(&fork, cudaEventDisableTiming);
        cudaEventCreateWithFlags(&join, cudaEventDisableTiming);
        cudaEventCreateWithFlags(&w1e, cudaEventDisableTiming);
        for (int c = 0; c < 3; ++c) {
            cudaStreamCreateWithFlags(&sc[c], cudaStreamNonBlocking);
            cudaEventCreateWithFlags(&e1[c], cudaEventDisableTiming);
            cudaEventCreateWithFlags(&ec[c], cudaEventDisableTiming);
        }
    }
};
static Streams g_ss;

// ---------------- utility kernels ----------------
__global__ void k_zero(float* __restrict__ p, int n) {
    int i = blockIdx.x * blockDim.x + threadIdx.x;
    if (i < n) p[i] = 0.f;
}
__global__ void k_zeroi2(int* __restrict__ a, int* __restrict__ b, int n) {
    int i = blockIdx.x * blockDim.x + threadIdx.x;
    if (i < n) { a[i] = 0; b[i] = 0; }
}

__global__ void k_hist2(const int* __restrict__ src, const int* __restrict__ dst,
                        int* __restrict__ cnts, int* __restrict__ cntd) {
    int i = blockIdx.x * blockDim.x + threadIdx.x;
    if (i >= 12 * EE) return;
    int u = i / EE, e = i - u * EE;
    int cr = u2cr(u);
    atomicAdd(&cnts[u * NN + src[(size_t)cr * EE + e]], 1);
    atomicAdd(&cntd[u * NN + dst[(size_t)cr * EE + e]], 1);
}

__global__ void k_prep(const int* __restrict__ cnts, const int* __restrict__ cntd,
                       float* __restrict__ rout, float* __restrict__ rin) {
    int i = blockIdx.x * blockDim.x + threadIdx.x;
    if (i >= 12 * NN) return;
    rout[i] = rsqrtf((float)max(cnts[i], 1));
    rin[i]  = rsqrtf((float)max(cntd[i], 1));
}

// deterministic exclusive scan per u (12 blocks, 1024 threads)
__global__ void k_scan(const int* __restrict__ cnt, int* __restrict__ base,
                       int* __restrict__ cur) {
    __shared__ int ws[32];
    __shared__ int carry;
    int u = blockIdx.x;
    const int* c = cnt + u * NN;
    int* b = base + u * NN;
    int* q = cur + u * NN;
    int lane = threadIdx.x & 31, w = threadIdx.x >> 5;
    if (threadIdx.x == 0) carry = 0;
    __syncthreads();
    for (int off = 0; off < NN; off += 1024) {
        int i = off + threadIdx.x;
        int v = (i < NN) ? c[i] : 0;
        int s = v;
#pragma unroll
        for (int o = 1; o < 32; o <<= 1) {
            int t = __shfl_up_sync(0xffffffffu, s, o);
            if (lane >= o) s += t;
        }
        if (lane == 31) ws[w] = s;
        __syncthreads();
        if (w == 0) {
            int t2 = ws[lane];
#pragma unroll
            for (int o = 1; o < 32; o <<= 1) {
                int t = __shfl_up_sync(0xffffffffu, t2, o);
                if (lane >= o) t2 += t;
            }
            ws[lane] = t2;
        }
        __syncthreads();
        int excl = s - v + (w > 0 ? ws[w - 1] : 0) + carry;
        if (i < NN) { b[i] = excl; q[i] = excl; }
        __syncthreads();
        if (threadIdx.x == 1023) carry = excl + v;
        __syncthreads();
    }
}

__global__ void k_fill(const int* __restrict__ src, const int* __restrict__ dst,
                       const float* __restrict__ rout, int* __restrict__ cur,
                       int* __restrict__ csrs, float* __restrict__ csrw) {
    int i = blockIdx.x * blockDim.x + threadIdx.x;
    if (i >= 12 * EE) return;
    int u = i / EE, e = i - u * EE;
    int cr = u2cr(u);
    int s = src[(size_t)cr * EE + e];
    int d = dst[(size_t)cr * EE + e];
    int pos = atomicAdd(&cur[u * NN + d], 1);
    csrs[(size_t)u * EE + pos] = s;
    csrw[(size_t)u * EE + pos] = rout[u * NN + s];
}

// split fp32 -> bf16 hi/lo
__global__ void k_split(const float* __restrict__ x, bf16* __restrict__ hi,
                        bf16* __restrict__ lo, int n4) {
    int i = blockIdx.x * blockDim.x + threadIdx.x;
    if (i >= n4) return;
    float4 v = ((const float4*)x)[i];
    bf16 h0 = __float2bfloat16(v.x), h1 = __float2bfloat16(v.y);
    bf16 h2 = __float2bfloat16(v.z), h3 = __float2bfloat16(v.w);
    ((__nv_bfloat162*)hi)[2 * i]     = __halves2bfloat162(h0, h1);
    ((__nv_bfloat162*)hi)[2 * i + 1] = __halves2bfloat162(h2, h3);
    bf16 l0 = __float2bfloat16(v.x - __bfloat162float(h0));
    bf16 l1 = __float2bfloat16(v.y - __bfloat162float(h1));
    bf16 l2 = __float2bfloat16(v.z - __bfloat162float(h2));
    bf16 l3 = __float2bfloat16(v.w - __bfloat162float(h3));
    ((__nv_bfloat162*)lo)[2 * i]     = __halves2bfloat162(l0, l1);
    ((__nv_bfloat162*)lo)[2 * i + 1] = __halves2bfloat162(l2, l3);
}

// transpose+split weights
__global__ void k_wts(const float* __restrict__ W, bf16* __restrict__ t1,
                      bf16* __restrict__ t2, int K, int N) {
    __shared__ float tile[32][33];
    int z = blockIdx.z;
    int cz = z >> 2;
    int c = (cz == 0) ? 0 : (cz == 1 ? 2 : 3);
    const float* Wm = W + (size_t)(c * 4 + (z & 3)) * K * N;
    bf16* o1 = t1 + (size_t)z * K * N;
    bf16* o2 = t2 + (size_t)z * K * N;
    int k0 = blockIdx.y * 32, n0 = blockIdx.x * 32;
    for (int r = threadIdx.y; r < 32; r += 8)
        tile[r][threadIdx.x] = Wm[(size_t)(k0 + r) * N + n0 + threadIdx.x];
    __syncthreads();
    for (int r = threadIdx.y; r < 32; r += 8) {
        float v = tile[threadIdx.x][r];
        bf16 h = __float2bfloat16(v);
        size_t o = (size_t)(n0 + r) * K + k0 + threadIdx.x;
        o1[o] = h;
        o2[o] = __float2bfloat16(v - __bfloat162float(h));
    }
}

__global__ void k_wts1(const float* __restrict__ W, bf16* __restrict__ t1,
                       bf16* __restrict__ t2, int K, int N) {
    __shared__ float tile[32][33];
    int k0 = blockIdx.y * 32, n0 = blockIdx.x * 32;
    for (int r = threadIdx.y; r < 32; r += 8)
        tile[r][threadIdx.x] = W[(size_t)(k0 + r) * N + n0 + threadIdx.x];
    __syncthreads();
    for (int r = threadIdx.y; r < 32; r += 8) {
        float v = tile[threadIdx.x][r];
        bf16 h = __float2bfloat16(v);
        size_t o = (size_t)(n0 + r) * K + k0 + threadIdx.x;
        t1[o] = h;
        t2[o] = __float2bfloat16(v - __bfloat162float(h));
    }
}

// ---------------- mma.sync bf16 GEMM, 128x128 tile (R6 winner) ----------------
// CHAINS: 3 = A1B1+A1B2+A2B1, 2 = A1B1+A1B2. ATT: fused attention epilogue.
__device__ __forceinline__ void mma16816(float* c, const uint32_t* a, const uint32_t* b) {
    asm volatile("mma.sync.aligned.m16n8k16.row.col.f32.bf16.bf16.f32 "
                 "{%0,%1,%2,%3}, {%4,%5,%6,%7}, {%8,%9}, {%0,%1,%2,%3};"
                 : "+f"(c[0]), "+f"(c[1]), "+f"(c[2]), "+f"(c[3])
                 : "r"(a[0]), "r"(a[1]), "r"(a[2]), "r"(a[3]), "r"(b[0]), "r"(b[1]));
}

template <int KK, int NOUT, int CH, int CHAINS, int ATT>
__global__ void __launch_bounds__(256, 2) k_mma(
    const bf16* __restrict__ A1b, const bf16* __restrict__ A2b,
    const bf16* __restrict__ Bt1, const bf16* __restrict__ Bt2,
    float* __restrict__ Y, int M, int u0, int attk,
    const float* __restrict__ bp, const float* __restrict__ q,
    float* __restrict__ wsum) {
    __shared__ uint32_t AS[2][2048];
    __shared__ uint32_t BS[2][2048];
    __shared__ float sb[6];

    const int tid = threadIdx.x;
    const int lane = tid & 31;
    const int wid = tid >> 5;
    const int warpM = wid & 3;
    const int warpN = wid >> 2;
    constexpr int NT = NOUT / 128;
    const int u = u0 + blockIdx.x / NT;
    const int bn = (blockIdx.x % NT) * 128;
    const int bm = blockIdx.y * 128;

    if (ATT && tid < 6) sb[tid] = 0.f;

    const int aoff = (CH ? (u >> 2) * 2 : 0) + ((u & 3) >> 1);
    const bf16* A1 = A1b + (size_t)aoff * M * KK;
    const bf16* A2 = A2b + (size_t)aoff * M * KK;
    const bf16* B1 = Bt1 + (size_t)u * KK * NOUT;
    const bf16* B2 = Bt2 + (size_t)u * KK * NOUT;
    float* Yp = Y + (size_t)u * M * NOUT;

    const bf16* APass[3] = {A1, A1, A2};
    const bf16* BPass[3] = {B1, B2, B1};

    constexpr int CPP = KK / 32;
    constexpr int NC = CHAINS * CPP;

    float c[2][8][4];
#pragma unroll
    for (int i = 0; i < 2; ++i)
#pragma unroll
        for (int j = 0; j < 8; ++j)
#pragma unroll
            for (int l = 0; l < 4; ++l) c[i][j][l] = 0.f;

    uint4 va[2], vb[2];
    {
        const bf16* Ag = APass[0];
        const bf16* Bg = BPass[0];
#pragma unroll
        for (int i = 0; i < 2; ++i) {
            int u2 = tid + i * 256;
            int m = u2 >> 2, seg = u2 & 3;
            int gm = bm + m;
            va[i] = make_uint4(0, 0, 0, 0);
            if (gm < M)
                va[i] = *(const uint4*)(Ag + (size_t)gm * KK + (seg >> 1) * 16 + (seg & 1) * 8);
            int n = u2 >> 2;
            vb[i] = *(const uint4*)(Bg + (size_t)(bn + n) * KK + (seg >> 1) * 16 + (seg & 1) * 8);
        }
    }

#pragma unroll 1
    for (int g = 0; g < NC; ++g) {
        const int buf = g & 1;
#pragma unroll
        for (int i = 0; i < 2; ++i) {
            int u2 = tid + i * 256;
            int m = u2 >> 2, seg = u2 & 3;
            int kb = seg >> 1, h = seg & 1;
            int r = ((m >> 3) & 1) + 2 * h;
            int Lb = (((m & 7) * 4) + seg * 8) & 31;
            int W = ((kb * 8 + (m >> 4)) * 4 + r) * 32 + Lb;
            *(uint4*)&AS[buf][W] = va[i];
            int n = m;
            int Wb = ((kb * 16 + (n >> 3)) * 2 + h) * 32 + Lb;
            *(uint4*)&BS[buf][Wb] = vb[i];
        }
        __syncthreads();

        if (g + 1 < NC) {
            int pass = (g + 1) / CPP, kc = (g + 1) % CPP;
            const bf16* Ag = APass[pass];
            const bf16* Bg = BPass[pass];
            int koff = kc * 32;
#pragma unroll
            for (int i = 0; i < 2; ++i) {
                int u2 = tid + i * 256;
                int m = u2 >> 2, seg = u2 & 3;
                int gm = bm + m;
                va[i] = make_uint4(0, 0, 0, 0);
                if (gm < M)
                    va[i] = *(const uint4*)(Ag + (size_t)gm * KK + koff +
                                            (seg >> 1) * 16 + (seg & 1) * 8);
                vb[i] = *(const uint4*)(Bg + (size_t)(bn + m) * KK + koff +
                                        (seg >> 1) * 16 + (seg & 1) * 8);
            }
        }

#pragma unroll
        for (int kb = 0; kb < 2; ++kb) {
            uint32_t a[2][4], b[8][2];
#pragma unroll
            for (int mbl = 0; mbl < 2; ++mbl) {
                int mb = warpM * 2 + mbl;
#pragma unroll
                for (int r = 0; r < 4; ++r) {
                    int Lr = (lane + (kb * 2 + (r >> 1)) * 8) & 31;
                    a[mbl][r] = AS[buf][((kb * 8 + mb) * 4 + r) * 32 + Lr];
                }
            }
#pragma unroll
            for (int nbl = 0; nbl < 8; ++nbl) {
                int nb = warpN * 8 + nbl;
#pragma unroll
                for (int h = 0; h < 2; ++h) {
                    int Lr = (lane + (kb * 2 + h) * 8) & 31;
                    b[nbl][h] = BS[buf][((kb * 16 + nb) * 2 + h) * 32 + Lr];
                }
            }
#pragma unroll
            for (int mbl = 0; mbl < 2; ++mbl)
#pragma unroll
                for (int nbl = 0; nbl < 8; ++nbl)
                    mma16816(c[mbl][nbl], a[mbl], b[nbl]);
        }
        __syncthreads();
    }

    if (ATT) {
        // rows are one channel: [0,NN) = drug, [NN,2NN) = protein; k = attk
        float s[2][2] = {{0.f, 0.f}, {0.f, 0.f}};
#pragma unroll
        for (int mbl = 0; mbl < 2; ++mbl)
#pragma unroll
            for (int nbl = 0; nbl < 8; ++nbl) {
                int ncol = warpN * 64 + nbl * 8 + (lane & 3) * 2;
                float bp0 = __ldg(bp + ncol), bp1 = __ldg(bp + ncol + 1);
                float q0 = __ldg(q + ncol), q1 = __ldg(q + ncol + 1);
                s[mbl][0] += tanhf(c[mbl][nbl][0] + bp0) * q0
                           + tanhf(c[mbl][nbl][1] + bp1) * q1;
                s[mbl][1] += tanhf(c[mbl][nbl][2] + bp0) * q0
                           + tanhf(c[mbl][nbl][3] + bp1) * q1;
            }
#pragma unroll
        for (int mbl = 0; mbl < 2; ++mbl)
#pragma unroll
            for (int h2 = 0; h2 < 2; ++h2) {
                float v = s[mbl][h2];
                v += __shfl_xor_sync(0xffffffffu, v, 1);
                v += __shfl_xor_sync(0xffffffffu, v, 2);
                if ((lane & 3) == 0) {
                    int grow = bm + warpM * 32 + mbl * 16 + h2 * 8 + (lane >> 2);
                    if (grow < M) {
                        int t = (grow >= NN) ? 1 : 0;
                        atomicAdd(&sb[t * 3 + attk], v);
                    }
                }
            }
        __syncthreads();
        if (tid < 6 && sb[tid] != 0.f) atomicAdd(&wsum[tid], sb[tid]);
    } else {
#pragma unroll
        for (int mbl = 0; mbl < 2; ++mbl) {
            int mrow = bm + warpM * 32 + mbl * 16 + (lane >> 2);
#pragma unroll
            for (int nbl = 0; nbl < 8; ++nbl) {
                int ncol = bn + warpN * 64 + nbl * 8 + (lane & 3) * 2;
                float* base = Yp + (size_t)mrow * NOUT + ncol;
                if (mrow < M)
                    *(float2*)base = make_float2(c[mbl][nbl][0], c[mbl][nbl][1]);
                if (mrow + 8 < M)
                    *(float2*)(base + (size_t)8 * NOUT) =
                        make_float2(c[mbl][nbl][2], c[mbl][nbl][3]);
            }
        }
    }
}

// --------- fused gather layer1 (one channel; blockIdx.y = type), 2x unroll ---------
__global__ void __launch_bounds__(256) k_gag1(
    const float* __restrict__ y,
    const int* __restrict__ csrs, const float* __restrict__ csrw,
    const int* __restrict__ base, const int* __restrict__ cnt,
    const float* __restrict__ rin, const float* __restrict__ b1,
    bf16* __restrict__ h1, bf16* __restrict__ h2, int ci) {
    int gw = (blockIdx.x * blockDim.x + threadIdx.x) >> 5;
    if (gw >= NN) return;
    int lane = threadIdx.x & 31;
    int d = gw;
    int t = blockIdx.y;
    int by = ci * 2 + t;
    int uLo = ci * 4 + t, uHi = uLo + 2;
    int c = (ci == 0) ? 0 : (ci == 1 ? 2 : 3);
    const float* yLo = y + (size_t)uLo * NN * HID_F;
    const float* yHi = y + (size_t)uHi * NN * HID_F;
    const float* bLo = b1 + (c * 4 + t) * HID_F;
    const float* bHi = b1 + (c * 4 + t + 2) * HID_F;

    float4 a0 = make_float4(0, 0, 0, 0), a1 = a0, e0 = a0, e1 = a0;
    float4 c0 = a0, c1 = a0, f0 = a0, f1 = a0;
    {
        int b = base[uLo * NN + d], n = cnt[uLo * NN + d];
        const int* cs = csrs + (size_t)uLo * EE;
        const float* cw = csrw + (size_t)uLo * EE;
        int i = 0;
        for (; i + 2 <= n; i += 2) {
            int s0 = cs[b + i], s1 = cs[b + i + 1];
            float w0 = cw[b + i], w1 = cw[b + i + 1];
            const float4* r0 = (const float4*)(yLo + (size_t)s0 * HID_F);
            const float4* r1 = (const float4*)(yLo + (size_t)s1 * HID_F);
            fma4(a0, w0, r0[lane]);
            fma4(a1, w0, r0[32 + lane]);
            fma4(e0, w1, r1[lane]);
            fma4(e1, w1, r1[32 + lane]);
        }
        if (i < n) {
            int s0 = cs[b + i];
            float w0 = cw[b + i];
            const float4* r0 = (const float4*)(yLo + (size_t)s0 * HID_F);
            fma4(a0, w0, r0[lane]);
            fma4(a1, w0, r0[32 + lane]);
        }
    }
    {
        int b = base[uHi * NN + d], n = cnt[uHi * NN + d];
        const int* cs = csrs + (size_t)uHi * EE;
        const float* cw = csrw + (size_t)uHi * EE;
        int i = 0;
        for (; i + 2 <= n; i += 2) {
            int s0 = cs[b + i], s1 = cs[b + i + 1];
            float w0 = cw[b + i], w1 = cw[b + i + 1];
            const float4* r0 = (const float4*)(yHi + (size_t)s0 * HID_F);
            const float4* r1 = (const float4*)(yHi + (size_t)s1 * HID_F);
            fma4(c0, w0, r0[lane]);
            fma4(c1, w0, r0[32 + lane]);
            fma4(f0, w1, r1[lane]);
            fma4(f1, w1, r1[32 + lane]);
        }
        if (i < n) {
            int s0 = cs[b + i];
            float w0 = cw[b + i];
            const float4* r0 = (const float4*)(yHi + (size_t)s0 * HID_F);
            fma4(c0, w0, r0[lane]);
            fma4(c1, w0, r0[32 + lane]);
        }
    }
    a0.x += e0.x; a0.y += e0.y; a0.z += e0.z; a0.w += e0.w;
    a1.x += e1.x; a1.y += e1.y; a1.z += e1.z; a1.w += e1.w;
    c0.x += f0.x; c0.y += f0.y; c0.z += f0.z; c0.w += f0.w;
    c1.x += f1.x; c1.y += f1.y; c1.z += f1.z; c1.w += f1.w;

    float rl = rin[uLo * NN + d], rh = rin[uHi * NN + d];
    bf16* o1 = h1 + (size_t)by * NN * HID_F;
    bf16* o2 = h2 + (size_t)by * NN * HID_F;
#pragma unroll
    for (int ch = 0; ch < 2; ++ch) {
        float4 A = ch ? a1 : a0, C = ch ? c1 : c0;
        float4 x = ((const float4*)bLo)[ch * 32 + lane];
        float4 yb = ((const float4*)bHi)[ch * 32 + lane];
        float r0 = fmaxf(x.x + yb.x + rl * A.x + rh * C.x, 0.f);
        float r1 = fmaxf(x.y + yb.y + rl * A.y + rh * C.y, 0.f);
        float r2 = fmaxf(x.z + yb.z + rl * A.z + rh * C.z, 0.f);
        float r3 = fmaxf(x.w + yb.w + rl * A.w + rh * C.w, 0.f);
        bf16 h0 = __float2bfloat16(r0), hh1 = __float2bfloat16(r1);
        bf16 h2v = __float2bfloat16(r2), h3 = __float2bfloat16(r3);
        __nv_bfloat162 p0 = __halves2bfloat162(h0, hh1);
        __nv_bfloat162 p1 = __halves2bfloat162(h2v, h3);
        uint2 st;
        st.x = *(unsigned*)&p0; st.y = *(unsigned*)&p1;
        size_t off = (size_t)d * HID_F + ch * 128 + lane * 4;
        *(uint2*)(o1 + off) = st;
        bf16 l0 = __float2bfloat16(r0 - __bfloat162float(h0));
        bf16 l1 = __float2bfloat16(r1 - __bfloat162float(hh1));
        bf16 l2 = __float2bfloat16(r2 - __bfloat162float(h2v));
        bf16 l3 = __float2bfloat16(r3 - __bfloat162float(h3));
        p0 = __halves2bfloat162(l0, l1);
        p1 = __halves2bfloat162(l2, l3);
        st.x = *(unsigned*)&p0; st.y = *(unsigned*)&p1;
        *(uint2*)(o2 + off) = st;
    }
}

// --------- fused gather layer2 + z hi-split (channel-contiguous za rows) ---------
__global__ void __launch_bounds__(256) k_gag2(
    const float* __restrict__ y2,
    const int* __restrict__ csrs, const float* __restrict__ csrw,
    const int* __restrict__ base, const int* __restrict__ cnt,
    const float* __restrict__ rin, const float* __restrict__ b2,
    float* __restrict__ zd, float* __restrict__ zp,
    bf16* __restrict__ za1, int ci) {
    int gw = (blockIdx.x * blockDim.x + threadIdx.x) >> 5;
    if (gw >= NN) return;
    int lane = threadIdx.x & 31;
    int d = gw;
    int t = blockIdx.y;
    int uLo = ci * 4 + t, uHi = uLo + 2;
    int c = (ci == 0) ? 0 : (ci == 1 ? 2 : 3);
    const float* yLo = y2 + (size_t)uLo * NN * OUT_F;
    const float* yHi = y2 + (size_t)uHi * NN * OUT_F;
    const float* bLo = b2 + (c * 4 + t) * OUT_F;
    const float* bHi = b2 + (c * 4 + t + 2) * OUT_F;

    float4 a0 = make_float4(0, 0, 0, 0), e0 = a0, c0 = a0, f0 = a0;
    {
        int b = base[uLo * NN + d], n = cnt[uLo * NN + d];
        const int* cs = csrs + (size_t)uLo * EE;
        const float* cw = csrw + (size_t)uLo * EE;
        int i = 0;
        for (; i + 2 <= n; i += 2) {
            fma4(a0, cw[b + i], ((const float4*)(yLo + (size_t)cs[b + i] * OUT_F))[lane]);
            fma4(e0, cw[b + i + 1],
                 ((const float4*)(yLo + (size_t)cs[b + i + 1] * OUT_F))[lane]);
        }
        if (i < n)
            fma4(a0, cw[b + i], ((const float4*)(yLo + (size_t)cs[b + i] * OUT_F))[lane]);
    }
    {
        int b = base[uHi * NN + d], n = cnt[uHi * NN + d];
        const int* cs = csrs + (size_t)uHi * EE;
        const float* cw = csrw + (size_t)uHi * EE;
        int i = 0;
        for (; i + 2 <= n; i += 2) {
            fma4(c0, cw[b + i], ((const float4*)(yHi + (size_t)cs[b + i] * OUT_F))[lane]);
            fma4(f0, cw[b + i + 1],
                 ((const float4*)(yHi + (size_t)cs[b + i + 1] * OUT_F))[lane]);
        }
        if (i < n)
            fma4(c0, cw[b + i], ((const float4*)(yHi + (size_t)cs[b + i] * OUT_F))[lane]);
    }
    a0.x += e0.x; a0.y += e0.y; a0.z += e0.z; a0.w += e0.w;
    c0.x += f0.x; c0.y += f0.y; c0.z += f0.z; c0.w += f0.w;

    float rl = rin[uLo * NN + d], rh = rin[uHi * NN + d];
    float4 x = ((const float4*)bLo)[lane], yb = ((const float4*)bHi)[lane];
    float4 res;
    res.x = fmaxf(x.x + yb.x + rl * a0.x + rh * c0.x, 0.f);
    res.y = fmaxf(x.y + yb.y + rl * a0.y + rh * c0.y, 0.f);
    res.z = fmaxf(x.z + yb.z + rl * a0.z + rh * c0.z, 0.f);
    res.w = fmaxf(x.w + yb.w + rl * a0.w + rh * c0.w, 0.f);
    float* zt = t ? zp : zd;
    *(float4*)(zt + (size_t)d * (3 * OUT_F) + ci * OUT_F + lane * 4) = res;

    // channel-contiguous attention rows: row = ci*2NN + t*NN + d
    size_t row = (size_t)ci * 2 * NN + (size_t)t * NN + d;
    bf16 h0 = __float2bfloat16(res.x), h1 = __float2bfloat16(res.y);
    bf16 h2 = __float2bfloat16(res.z), h3 = __float2bfloat16(res.w);
    __nv_bfloat162 p0 = __halves2bfloat162(h0, h1);
    __nv_bfloat162 p1 = __halves2bfloat162(h2, h3);
    uint2 st;
    st.x = *(unsigned*)&p0; st.y = *(unsigned*)&p1;
    *(uint2*)(za1 + row * OUT_F + lane * 4) = st;
}

// ------------- attention tail -------------
__global__ void k_beta(const float* __restrict__ wsum, float* __restrict__ beta,
                       float* __restrict__ outBeta) {
    if (threadIdx.x != 0 || blockIdx.x != 0) return;
    for (int t = 0; t < 2; ++t) {
        float w0 = wsum[t * 3 + 0] / (float)NN;
        float w1 = wsum[t * 3 + 1] / (float)NN;
        float w2 = wsum[t * 3 + 2] / (float)NN;
        float m = fmaxf(w0, fmaxf(w1, w2));
        float e0 = expf(w0 - m), e1 = expf(w1 - m), e2 = expf(w2 - m);
        float inv = 1.f / (e0 + e1 + e2);
        beta[t * 3 + 0] = e0 * inv; outBeta[t * 3 + 0] = e0 * inv;
        beta[t * 3 + 1] = e1 * inv; outBeta[t * 3 + 1] = e1 * inv;
        beta[t * 3 + 2] = e2 * inv; outBeta[t * 3 + 2] = e2 * inv;
    }
}

__global__ void k_combine(const float* __restrict__ zd, const float* __restrict__ zp,
                          const float* __restrict__ beta, float* __restrict__ out) {
    int i = blockIdx.x * blockDim.x + threadIdx.x;
    if (i >= 2 * NN * OUT_F) return;
    int t = i / (NN * OUT_F);
    int r = i - t * NN * OUT_F;
    int n = r / OUT_F, f = r - n * OUT_F;
    const float* z = (t ? zp : zd) + (size_t)n * (3 * OUT_F) + f;
    const float* b = beta + t * 3;
    out[i] = b[0] * z[0] + b[1] * z[OUT_F] + b[2] * z[2 * OUT_F];
}

// ---------------- host orchestration ----------------
extern "C" void kernel_launch(void* const* d_in, const int* in_sizes, int n_in,
                              void* d_out, int out_size) {
    const float* xd  = (const float*)d_in[0];
    const float* xp  = (const float*)d_in[1];
    const int*   src = (const int*)  d_in[2];
    const int*   dst = (const int*)  d_in[3];
    const float* W1  = (const float*)d_in[4];
    const float* b1  = (const float*)d_in[5];
    const float* W2  = (const float*)d_in[6];
    const float* b2  = (const float*)d_in[7];
    const float* Wpm = (const float*)d_in[8];
    const float* bp  = (const float*)d_in[9];
    const float* q   = (const float*)d_in[10];
    float* out = (float*)d_out;

    float *y, *y2, *zd, *zp, *rout, *rin, *wsum, *beta, *csrw;
    int *cnts, *cnt, *base, *cur, *csrs;
    bf16 *x1, *x2, *h1, *h2, *za1;
    bf16 *wt1a, *wt1b, *wt2a, *wt2b, *wpa, *wpb;
    cudaGetSymbolAddress((void**)&y,    g_y);
    cudaGetSymbolAddress((void**)&y2,   g_y2);
    cudaGetSymbolAddress((void**)&zd,   g_zd);
    cudaGetSymbolAddress((void**)&zp,   g_zp);
    cudaGetSymbolAddress((void**)&rout, g_rout);
    cudaGetSymbolAddress((void**)&rin,  g_rin);
    cudaGetSymbolAddress((void**)&wsum, g_wsum);
    cudaGetSymbolAddress((void**)&beta, g_beta);
    cudaGetSymbolAddress((void**)&cnts, g_cnts);
    cudaGetSymbolAddress((void**)&cnt,  g_cnt);
    cudaGetSymbolAddress((void**)&base, g_base);
    cudaGetSymbolAddress((void**)&cur,  g_cur);
    cudaGetSymbolAddress((void**)&csrs, g_csrs);
    cudaGetSymbolAddress((void**)&csrw, g_csrw);
    cudaGetSymbolAddress((void**)&x1,   g_x1);
    cudaGetSymbolAddress((void**)&x2,   g_x2);
    cudaGetSymbolAddress((void**)&h1,   g_h1);
    cudaGetSymbolAddress((void**)&h2,   g_h2);
    cudaGetSymbolAddress((void**)&za1,  g_za1);
    cudaGetSymbolAddress((void**)&wt1a, g_wt1a);
    cudaGetSymbolAddress((void**)&wt1b, g_wt1b);
    cudaGetSymbolAddress((void**)&wt2a, g_wt2a);
    cudaGetSymbolAddress((void**)&wt2b, g_wt2b);
    cudaGetSymbolAddress((void**)&wpa,  g_wpa);
    cudaGetSymbolAddress((void**)&wpb,  g_wpb);

    const int T = 256;
    const int mtiles = (NN + 127) / 128;            // 235
    const int gblocks = (NN * 32 + T - 1) / T;      // 3750
    cudaStream_t sd = g_ss.side;

    // ---- fork side stream: W1 transform first (gates GEMM1), then CSR build ----
    cudaEventRecord(g_ss.fork, 0);
    cudaStreamWaitEvent(sd, g_ss.fork, 0);
    k_wts<<<dim3(HID_F / 32, IN_F / 32, 12), dim3(32, 8), 0, sd>>>(W1, wt1a, wt1b, IN_F, HID_F);
    cudaEventRecord(g_ss.w1e, sd);
    k_zeroi2<<<(12 * NN + T - 1) / T, T, 0, sd>>>(cnts, cnt, 12 * NN);
    k_hist2<<<(12 * EE + T - 1) / T, T, 0, sd>>>(src, dst, cnts, cnt);
    k_prep<<<(12 * NN + T - 1) / T, T, 0, sd>>>(cnts, cnt, rout, rin);
    k_scan<<<12, 1024, 0, sd>>>(cnt, base, cur);
    k_fill<<<(12 * EE + T - 1) / T, T, 0, sd>>>(src, dst, rout, cur, csrs, csrw);
    k_wts<<<dim3(OUT_F / 32, HID_F / 32, 12), dim3(32, 8), 0, sd>>>(W2, wt2a, wt2b, HID_F, OUT_F);
    k_wts1<<<dim3(OUT_F / 32, OUT_F / 32), dim3(32, 8), 0, sd>>>(Wpm, wpa, wpb, OUT_F, OUT_F);
    k_zero<<<1, 32, 0, sd>>>(wsum, 8);
    cudaEventRecord(g_ss.join, sd);

    // ---- main stream: x splits (parallel with W1 transform), then GEMM1 ×3 ----
    k_split<<<(NN * IN_F / 4 + T - 1) / T, T>>>(xd, x1, x2, NN * IN_F / 4);
    k_split<<<(NN * IN_F / 4 + T - 1) / T, T>>>(xp, x1 + (size_t)NN * IN_F,
                                                x2 + (size_t)NN * IN_F, NN * IN_F / 4);
    cudaStreamWaitEvent(0, g_ss.w1e, 0);

    for (int c = 0; c < 3; ++c) {
        k_mma<IN_F, HID_F, 0, 3, 0><<<dim3(4 * (HID_F / 128), mtiles), 256>>>(
            x1, x2, wt1a, wt1b, y, NN, c * 4, 0, nullptr, nullptr, nullptr);
        cudaEventRecord(g_ss.e1[c], 0);
    }

    // ---- per-channel pipelines: gag1 -> GEMM2 -> gag2 -> attention GEMM ----
    for (int c = 0; c < 3; ++c) {
        cudaStream_t s = g_ss.sc[c];
        cudaStreamWaitEvent(s, g_ss.e1[c], 0);
        cudaStreamWaitEvent(s, g_ss.join, 0);
        k_gag1<<<dim3(gblocks, 2), T, 0, s>>>(y, csrs, csrw, base, cnt, rin, b1,
                                              h1, h2, c);
        k_mma<HID_F, OUT_F, 1, 3, 0><<<dim3(4, mtiles), 256, 0, s>>>(
            h1, h2, wt2a, wt2b, y2, NN, c * 4, 0, nullptr, nullptr, nullptr);
        k_gag2<<<dim3(gblocks, 2), T, 0, s>>>(y2, csrs, csrw, base, cnt, rin, b2,
                                              zd, zp, za1, c);
        // per-channel attention GEMM (2-chain exact-Wp) with fused reduction
        k_mma<OUT_F, OUT_F, 0, 2, 1><<<dim3(1, (2 * NN + 127) / 128), 256, 0, s>>>(
            za1 + (size_t)c * 2 * NN * OUT_F, za1 + (size_t)c * 2 * NN * OUT_F,
            wpa, wpb, nullptr, 2 * NN, 0, c, bp, q, wsum);
        cudaEventRecord(g_ss.ec[c], s);
    }

    // ---- join all channels, then beta + combine on main ----
    for (int c = 0; c < 3; ++c) cudaStreamWaitEvent(0, g_ss.ec[c], 0);

    k_beta<<<1, 1>>>(wsum, beta, out + (size_t)2 * NN * OUT_F);
    k_combine<<<(2 * NN * OUT_F + T - 1) / T, T>>>(zd, zp, beta, out);
}